// round 6
// baseline (speedup 1.0000x reference)
#include <cuda_runtime.h>

#define NN 50000
#define EE 500000
#define HD 128
#define NLAY 4
#define NG 64
#define NB 196  // (NN+255)/256 scan blocks

// ---------------- scratch (device globals) ------------------------------------
__device__ __align__(16) float d_h[NN * HD];
__device__ __align__(16) float d_P1[NN * HD];
__device__ __align__(16) float d_P2[NN * HD];
__device__ __align__(16) float d_Yagg[NN * HD];
__device__ __align__(16) float d_T[NN * HD];
__device__ __align__(16) float d_degf[NN];
__device__ __align__(16) float d_W2U[NLAY * HD * HD];
__device__ __align__(16) float d_cvec[NLAY * HD];
__device__ __align__(16) float d_pooled[NG * HD];
__device__ __align__(16) float d_cnt[NG];
// CSR
__device__ __align__(16) int   d_rowptr[NN + 1];
__device__ __align__(16) int   d_cursor[NN];
__device__ __align__(16) int   d_bsum[256];
__device__ __align__(16) int2  d_epack[EE];   // (src, dist bits)

// ---------------- f32x2 packed helpers ---------------------------------------
__device__ __forceinline__ unsigned long long pk2(float lo, float hi) {
    unsigned long long r;
    asm("mov.b64 %0, {%1,%2};" : "=l"(r) : "f"(lo), "f"(hi));
    return r;
}
__device__ __forceinline__ void upk2(unsigned long long v, float& lo, float& hi) {
    asm("mov.b64 {%0,%1}, %2;" : "=f"(lo), "=f"(hi) : "l"(v));
}
__device__ __forceinline__ unsigned long long fma2(unsigned long long a,
                                                   unsigned long long b,
                                                   unsigned long long c) {
    unsigned long long d;
    asm("fma.rn.f32x2 %0, %1, %2, %3;" : "=l"(d) : "l"(a), "l"(b), "l"(c));
    return d;
}

// ---------------- tiny utility kernels ----------------------------------------
__global__ void zero_k(float* __restrict__ p, int n) {
    int i = blockIdx.x * blockDim.x + threadIdx.x;
    if (i < n) p[i] = 0.0f;
}
__global__ void zero_int(int* __restrict__ p, int n) {
    int i = blockIdx.x * blockDim.x + threadIdx.x;
    if (i < n) p[i] = 0;
}

// ---------------- CSR build ----------------------------------------------------
__global__ void count_k(const int* __restrict__ ei, int* __restrict__ deg) {
    int e = blockIdx.x * blockDim.x + threadIdx.x;
    if (e < EE) atomicAdd(&deg[ei[EE + e]], 1);
}

__global__ void scan_part(const int* __restrict__ deg, int* __restrict__ rowptr,
                          int* __restrict__ bsum) {
    __shared__ int s[256];
    int tid = threadIdx.x;
    int i = blockIdx.x * 256 + tid;
    int v = (i < NN) ? deg[i] : 0;
    s[tid] = v;
    __syncthreads();
#pragma unroll
    for (int off = 1; off < 256; off <<= 1) {
        int t = (tid >= off) ? s[tid - off] : 0;
        __syncthreads();
        s[tid] += t;
        __syncthreads();
    }
    if (i < NN) rowptr[i] = s[tid] - v;
    if (tid == 255) bsum[blockIdx.x] = s[255];
}

__global__ void scan_bsum(int* __restrict__ bsum) {
    __shared__ int s[256];
    int tid = threadIdx.x;
    int v = (tid < NB) ? bsum[tid] : 0;
    s[tid] = v;
    __syncthreads();
#pragma unroll
    for (int off = 1; off < 256; off <<= 1) {
        int t = (tid >= off) ? s[tid - off] : 0;
        __syncthreads();
        s[tid] += t;
        __syncthreads();
    }
    if (tid < NB) bsum[tid] = s[tid] - v;
}

__global__ void add_off(int* __restrict__ rowptr, const int* __restrict__ bsum,
                        int* __restrict__ cursor) {
    int i = blockIdx.x * 256 + threadIdx.x;
    if (i < NN) {
        int r = rowptr[i] + bsum[blockIdx.x];
        rowptr[i] = r;
        cursor[i] = r;
    }
    if (i == 0) rowptr[NN] = EE;
}

__global__ void degf_k(const int* __restrict__ rowptr, float* __restrict__ degf) {
    int i = blockIdx.x * blockDim.x + threadIdx.x;
    if (i < NN) degf[i] = (float)(rowptr[i + 1] - rowptr[i]);
}

__global__ void scatter_k(const int* __restrict__ ei,
                          const float* __restrict__ pos,
                          int* __restrict__ cursor,
                          int2* __restrict__ epack) {
    int e = blockIdx.x * blockDim.x + threadIdx.x;
    if (e >= EE) return;
    int s = ei[e];
    int t = ei[EE + e];
    float dx = pos[t * 3 + 0] - pos[s * 3 + 0];
    float dy = pos[t * 3 + 1] - pos[s * 3 + 1];
    float dz = pos[t * 3 + 2] - pos[s * 3 + 2];
    float dd = sqrtf(dx * dx + dy * dy + dz * dz);
    int p = atomicAdd(&cursor[t], 1);
    epack[p] = make_int2(s, __float_as_int(dd));
}

// ---------------- encoder: h = x @ enc_w + enc_b (K=15) -----------------------
__global__ void encoder_k(const float* __restrict__ x,
                          const float* __restrict__ w,
                          const float* __restrict__ b,
                          float* __restrict__ h) {
    __shared__ float ws[15 * HD];
    __shared__ float xs[16 * 15];
    __shared__ float bs[HD];
    int c = threadIdx.x;
    for (int i = c; i < 15 * HD; i += HD) ws[i] = w[i];
    bs[c] = b[c];
    int n0 = blockIdx.x * 16;
    for (int i = c; i < 16 * 15; i += HD) {
        int nn = i / 15, kk = i % 15;
        int g = n0 + nn;
        xs[i] = (g < NN) ? x[g * 15 + kk] : 0.0f;
    }
    __syncthreads();
    for (int r = 0; r < 16; r++) {
        int g = n0 + r;
        if (g >= NN) break;
        float acc = bs[c];
#pragma unroll
        for (int k = 0; k < 15; k++) acc += xs[r * 15 + k] * ws[k * HD + c];
        h[g * HD + c] = acc;
    }
}

// W2U[l] = msg_w2[l] @ U1b[l];  cvec[l] = msg_b2[l] @ U1b[l]
__global__ void build_w2u(const float* __restrict__ msg_w2,
                          const float* __restrict__ msg_b2,
                          const float* __restrict__ upd_w1,
                          float* __restrict__ W2U,
                          float* __restrict__ cvec) {
    int l = blockIdx.y, k = blockIdx.x, c = threadIdx.x;
    const float* u1b = upd_w1 + l * 256 * HD + 128 * HD;
    if (k < HD) {
        const float* wrow = msg_w2 + (l * HD + k) * HD;
        float acc = 0.0f;
        for (int j = 0; j < HD; j++) acc += wrow[j] * u1b[j * HD + c];
        W2U[(l * HD + k) * HD + c] = acc;
    } else {
        const float* brow = msg_b2 + l * HD;
        float acc = 0.0f;
        for (int j = 0; j < HD; j++) acc += brow[j] * u1b[j * HD + c];
        cvec[l * HD + c] = acc;
    }
}

// ---------------- CSR gather aggregation (unroll 4, packed edges) --------------
__global__ void __launch_bounds__(256) aggregate_k(
    const int* __restrict__ rowptr,
    const int2* __restrict__ epack,
    const float* __restrict__ P1,
    const float* __restrict__ P2,
    const float* __restrict__ w1c,
    float* __restrict__ Yagg) {
    int node = blockIdx.x * 8 + (threadIdx.x >> 5);
    int lane = threadIdx.x & 31;
    int c4 = lane * 4;
    const float4 cw = *(const float4*)&w1c[c4];
    const float4 p1 = *(const float4*)&P1[node * HD + c4];
    float a0 = 0.f, a1 = 0.f, a2 = 0.f, a3 = 0.f;
    float b0 = 0.f, b1 = 0.f, b2 = 0.f, b3 = 0.f;
    float c0 = 0.f, c1 = 0.f, c2 = 0.f, c3 = 0.f;
    float d0 = 0.f, d1 = 0.f, d2 = 0.f, d3 = 0.f;
    int beg = rowptr[node], end = rowptr[node + 1];
    int e = beg;
    for (; e + 3 < end; e += 4) {
        int2 q0 = epack[e], q1 = epack[e + 1], q2 = epack[e + 2], q3 = epack[e + 3];
        const float4 v0 = *(const float4*)&P2[q0.x * HD + c4];
        const float4 v1 = *(const float4*)&P2[q1.x * HD + c4];
        const float4 v2 = *(const float4*)&P2[q2.x * HD + c4];
        const float4 v3 = *(const float4*)&P2[q3.x * HD + c4];
        float dd0 = __int_as_float(q0.y), dd1 = __int_as_float(q1.y);
        float dd2 = __int_as_float(q2.y), dd3 = __int_as_float(q3.y);
        a0 += fmaxf(p1.x + v0.x + dd0 * cw.x, 0.0f);
        a1 += fmaxf(p1.y + v0.y + dd0 * cw.y, 0.0f);
        a2 += fmaxf(p1.z + v0.z + dd0 * cw.z, 0.0f);
        a3 += fmaxf(p1.w + v0.w + dd0 * cw.w, 0.0f);
        b0 += fmaxf(p1.x + v1.x + dd1 * cw.x, 0.0f);
        b1 += fmaxf(p1.y + v1.y + dd1 * cw.y, 0.0f);
        b2 += fmaxf(p1.z + v1.z + dd1 * cw.z, 0.0f);
        b3 += fmaxf(p1.w + v1.w + dd1 * cw.w, 0.0f);
        c0 += fmaxf(p1.x + v2.x + dd2 * cw.x, 0.0f);
        c1 += fmaxf(p1.y + v2.y + dd2 * cw.y, 0.0f);
        c2 += fmaxf(p1.z + v2.z + dd2 * cw.z, 0.0f);
        c3 += fmaxf(p1.w + v2.w + dd2 * cw.w, 0.0f);
        d0 += fmaxf(p1.x + v3.x + dd3 * cw.x, 0.0f);
        d1 += fmaxf(p1.y + v3.y + dd3 * cw.y, 0.0f);
        d2 += fmaxf(p1.z + v3.z + dd3 * cw.z, 0.0f);
        d3 += fmaxf(p1.w + v3.w + dd3 * cw.w, 0.0f);
    }
    for (; e < end; e++) {
        int2 q0 = epack[e];
        const float4 v0 = *(const float4*)&P2[q0.x * HD + c4];
        float dd0 = __int_as_float(q0.y);
        a0 += fmaxf(p1.x + v0.x + dd0 * cw.x, 0.0f);
        a1 += fmaxf(p1.y + v0.y + dd0 * cw.y, 0.0f);
        a2 += fmaxf(p1.z + v0.z + dd0 * cw.z, 0.0f);
        a3 += fmaxf(p1.w + v0.w + dd0 * cw.w, 0.0f);
    }
    *(float4*)&Yagg[node * HD + c4] = make_float4(
        (a0 + b0) + (c0 + d0), (a1 + b1) + (c1 + d1),
        (a2 + b2) + (c2 + d2), (a3 + b3) + (c3 + d3));
}

// ---------------- main GEMM: 64 rows x 128 cols, 256 thr, 2 blocks/SM ----------
__device__ __forceinline__ void load_tile_A64(float* As, const float* __restrict__ A,
                                              int rowbase, int tid, int n) {
    const float4* av = (const float4*)A;
    float4* asv = (float4*)As;
#pragma unroll
    for (int i = 0; i < 8; i++) {
        int idx = tid + i * 256;          // 0..2047
        int r = idx >> 5;
        int grow = rowbase + r;
        int cr = (grow < n) ? grow : (n - 1);
        asv[idx] = av[cr * 32 + (idx & 31)];
    }
}

__device__ __forceinline__ void load_tile_B(float* Bs, const float* __restrict__ B,
                                            int tid) {
    const float4* bv = (const float4*)B;
    float4* bs = (float4*)Bs;
#pragma unroll
    for (int i = 0; i < 16; i++) bs[tid + i * 256] = bv[tid + i * 256];
}

__device__ __forceinline__ void gemm_compute(const float* As, const float* Bs,
                                             unsigned long long acc0[8],
                                             unsigned long long acc1[8],
                                             int warp, int lane) {
#pragma unroll 2
    for (int k0 = 0; k0 < HD; k0 += 4) {
        float4 avv[8];
#pragma unroll
        for (int r = 0; r < 8; r++)
            avv[r] = *(const float4*)&As[(warp * 8 + r) * HD + k0];
#pragma unroll
        for (int kk = 0; kk < 4; kk++) {
            const unsigned long long* bp =
                (const unsigned long long*)&Bs[(k0 + kk) * HD + lane * 4];
            unsigned long long b01 = bp[0];
            unsigned long long b23 = bp[1];
#pragma unroll
            for (int r = 0; r < 8; r++) {
                float a = (&avv[r].x)[kk];
                unsigned long long a2 = pk2(a, a);
                acc0[r] = fma2(a2, b01, acc0[r]);
                acc1[r] = fma2(a2, b23, acc1[r]);
            }
        }
    }
}

// fused P1/P2: A resident, two B passes. O1 = A@B0 + bias; O2 = A@B1.
__global__ void __launch_bounds__(256) gemm_p12(
    const float* __restrict__ A,
    const float* __restrict__ B0, const float* __restrict__ B1,
    const float* __restrict__ bias,
    float* __restrict__ O1, float* __restrict__ O2) {
    extern __shared__ float sm[];
    float* Bs = sm;                 // 128 x 128
    float* As = sm + 128 * HD;      // 64 x 128
    int tid = threadIdx.x;
    int rowbase = blockIdx.x * 64;
    int warp = tid >> 5, lane = tid & 31;
    int col = lane * 4;

    load_tile_B(Bs, B0, tid);
    load_tile_A64(As, A, rowbase, tid, NN);
    __syncthreads();

    unsigned long long acc0[8], acc1[8];
#pragma unroll
    for (int r = 0; r < 8; r++) { acc0[r] = 0ULL; acc1[r] = 0ULL; }
    gemm_compute(As, Bs, acc0, acc1, warp, lane);

    int rb = rowbase + warp * 8;
#pragma unroll
    for (int r = 0; r < 8; r++) {
        int grow = rb + r;
        if (grow >= NN) break;
        float o0, o1, o2, o3;
        upk2(acc0[r], o0, o1);
        upk2(acc1[r], o2, o3);
        o0 += bias[col + 0]; o1 += bias[col + 1];
        o2 += bias[col + 2]; o3 += bias[col + 3];
        *(float4*)&O1[grow * HD + col] = make_float4(o0, o1, o2, o3);
    }
    __syncthreads();                 // everyone done with Bs pass 1

    load_tile_B(Bs, B1, tid);
    __syncthreads();
#pragma unroll
    for (int r = 0; r < 8; r++) { acc0[r] = 0ULL; acc1[r] = 0ULL; }
    gemm_compute(As, Bs, acc0, acc1, warp, lane);
#pragma unroll
    for (int r = 0; r < 8; r++) {
        int grow = rb + r;
        if (grow >= NN) break;
        float o0, o1, o2, o3;
        upk2(acc0[r], o0, o1);
        upk2(acc1[r], o2, o3);
        *(float4*)&O2[grow * HD + col] = make_float4(o0, o1, o2, o3);
    }
}

// EPI: 2 = +deg*cvec+bias, relu (TWOA)   3 = +bias, LN, relu, (+res)
template <int EPI, bool TWOA>
__global__ void __launch_bounds__(256) gemm_k(
    const float* __restrict__ A0, const float* __restrict__ A1,
    const float* __restrict__ B0, const float* __restrict__ B1,
    const float* __restrict__ bias,
    const float* __restrict__ degf, const float* __restrict__ cvec,
    const float* __restrict__ lng, const float* __restrict__ lnb,
    int addres, float* __restrict__ Out, int n) {
    extern __shared__ float sm[];
    float* Bs = sm;                 // 128 x 128
    float* As = sm + 128 * HD;      // 64 x 128
    int tid = threadIdx.x;
    int rowbase = blockIdx.x * 64;

    load_tile_B(Bs, B0, tid);
    load_tile_A64(As, A0, rowbase, tid, n);
    __syncthreads();

    unsigned long long acc0[8], acc1[8];
#pragma unroll
    for (int r = 0; r < 8; r++) { acc0[r] = 0ULL; acc1[r] = 0ULL; }

    int warp = tid >> 5, lane = tid & 31;
    gemm_compute(As, Bs, acc0, acc1, warp, lane);
    if (TWOA) {
        __syncthreads();
        load_tile_B(Bs, B1, tid);
        load_tile_A64(As, A1, rowbase, tid, n);
        __syncthreads();
        gemm_compute(As, Bs, acc0, acc1, warp, lane);
    }

    int col = lane * 4;
    int rb = rowbase + warp * 8;
#pragma unroll
    for (int r = 0; r < 8; r++) {
        int grow = rb + r;
        float o0, o1, o2, o3;
        upk2(acc0[r], o0, o1);
        upk2(acc1[r], o2, o3);
        if (EPI == 2) {
            float dg = degf[(grow < n) ? grow : 0];
            o0 = fmaxf(o0 + dg * cvec[col + 0] + bias[col + 0], 0.0f);
            o1 = fmaxf(o1 + dg * cvec[col + 1] + bias[col + 1], 0.0f);
            o2 = fmaxf(o2 + dg * cvec[col + 2] + bias[col + 2], 0.0f);
            o3 = fmaxf(o3 + dg * cvec[col + 3] + bias[col + 3], 0.0f);
        }
        if (EPI == 3) {
            o0 += bias[col + 0]; o1 += bias[col + 1];
            o2 += bias[col + 2]; o3 += bias[col + 3];
            float s = o0 + o1 + o2 + o3;
            float sq = o0 * o0 + o1 * o1 + o2 * o2 + o3 * o3;
#pragma unroll
            for (int off = 16; off; off >>= 1) {
                s += __shfl_xor_sync(0xffffffffu, s, off);
                sq += __shfl_xor_sync(0xffffffffu, sq, off);
            }
            float mu = s * (1.0f / HD);
            float var = sq * (1.0f / HD) - mu * mu;
            float rstd = rsqrtf(var + 1e-5f);
            o0 = fmaxf((o0 - mu) * rstd * lng[col + 0] + lnb[col + 0], 0.0f);
            o1 = fmaxf((o1 - mu) * rstd * lng[col + 1] + lnb[col + 1], 0.0f);
            o2 = fmaxf((o2 - mu) * rstd * lng[col + 2] + lnb[col + 2], 0.0f);
            o3 = fmaxf((o3 - mu) * rstd * lng[col + 3] + lnb[col + 3], 0.0f);
            if (addres && grow < n) {
                const float4 hv = *(const float4*)&Out[grow * HD + col];
                o0 += hv.x; o1 += hv.y; o2 += hv.z; o3 += hv.w;
            }
        }
        if (grow < n) {
            *(float4*)&Out[grow * HD + col] = make_float4(o0, o1, o2, o3);
        }
    }
}

// ---------------- readout ------------------------------------------------------
__global__ void pool_k(const float* __restrict__ h,
                       const int* __restrict__ batch,
                       float* __restrict__ pooled, float* __restrict__ cnt) {
    int nidx = blockIdx.x * 8 + (threadIdx.x >> 5);
    int lane = threadIdx.x & 31;
    if (nidx >= NN) return;
    int g = batch[nidx];
    float4 v = *(const float4*)&h[nidx * HD + lane * 4];
    float* p = &pooled[g * HD + lane * 4];
    atomicAdd(p + 0, v.x);
    atomicAdd(p + 1, v.y);
    atomicAdd(p + 2, v.z);
    atomicAdd(p + 3, v.w);
    if (lane == 0) atomicAdd(&cnt[g], 1.0f);
}

__global__ void readout_k(const float* __restrict__ pooled,
                          const float* __restrict__ cnt,
                          const float* __restrict__ w1, const float* __restrict__ b1,
                          const float* __restrict__ w2, const float* __restrict__ b2,
                          const float* __restrict__ w3, const float* __restrict__ b3,
                          float* __restrict__ out) {
    __shared__ float p[HD];
    __shared__ float o1s[HD];
    __shared__ float o2s[64];
    int g = blockIdx.x, c = threadIdx.x;
    float cc = fmaxf(cnt[g], 1.0f);
    p[c] = pooled[g * HD + c] / cc;
    __syncthreads();
    float acc = b1[c];
    for (int k = 0; k < HD; k++) acc += p[k] * w1[k * HD + c];
    o1s[c] = fmaxf(acc, 0.0f);
    __syncthreads();
    if (c < 64) {
        float a = b2[c];
        for (int k = 0; k < HD; k++) a += o1s[k] * w2[k * 64 + c];
        o2s[c] = fmaxf(a, 0.0f);
    }
    __syncthreads();
    if (c == 0) {
        float a = b3[0];
        for (int k = 0; k < 64; k++) a += o2s[k] * w3[k];
        out[g] = a;
    }
}

// ---------------- launch --------------------------------------------------------
extern "C" void kernel_launch(void* const* d_in, const int* in_sizes, int n_in,
                              void* d_out, int out_size) {
    const float* x       = (const float*)d_in[0];
    const int*   ei      = (const int*)d_in[1];
    const float* pos     = (const float*)d_in[3];
    const int*   batch   = (const int*)d_in[4];
    const float* enc_w   = (const float*)d_in[5];
    const float* enc_b   = (const float*)d_in[6];
    const float* msg_w1  = (const float*)d_in[9];
    const float* msg_b1  = (const float*)d_in[10];
    const float* msg_w2  = (const float*)d_in[11];
    const float* msg_b2  = (const float*)d_in[12];
    const float* upd_w1  = (const float*)d_in[13];
    const float* upd_b1  = (const float*)d_in[14];
    const float* upd_w2  = (const float*)d_in[15];
    const float* upd_b2  = (const float*)d_in[16];
    const float* ln_g    = (const float*)d_in[17];
    const float* ln_b    = (const float*)d_in[18];
    const float* mlp_w1  = (const float*)d_in[19];
    const float* mlp_b1  = (const float*)d_in[20];
    const float* mlp_w2  = (const float*)d_in[21];
    const float* mlp_b2  = (const float*)d_in[22];
    const float* mlp_w3  = (const float*)d_in[23];
    const float* mlp_b3  = (const float*)d_in[24];
    float*       out     = (float*)d_out;

    float *h, *P1, *P2, *Yagg, *T, *degf, *W2U, *cvec, *pooled, *cnt;
    int *rowptr, *cursor, *bsum;
    int2 *epack;
    cudaGetSymbolAddress((void**)&h, d_h);
    cudaGetSymbolAddress((void**)&P1, d_P1);
    cudaGetSymbolAddress((void**)&P2, d_P2);
    cudaGetSymbolAddress((void**)&Yagg, d_Yagg);
    cudaGetSymbolAddress((void**)&T, d_T);
    cudaGetSymbolAddress((void**)&degf, d_degf);
    cudaGetSymbolAddress((void**)&W2U, d_W2U);
    cudaGetSymbolAddress((void**)&cvec, d_cvec);
    cudaGetSymbolAddress((void**)&pooled, d_pooled);
    cudaGetSymbolAddress((void**)&cnt, d_cnt);
    cudaGetSymbolAddress((void**)&rowptr, d_rowptr);
    cudaGetSymbolAddress((void**)&cursor, d_cursor);
    cudaGetSymbolAddress((void**)&bsum, d_bsum);
    cudaGetSymbolAddress((void**)&epack, d_epack);

    const int SMEM = (128 * HD + 64 * HD) * 4;   // 96 KB
    cudaFuncSetAttribute(gemm_p12, cudaFuncAttributeMaxDynamicSharedMemorySize, SMEM);
    cudaFuncSetAttribute(gemm_k<2, true>,  cudaFuncAttributeMaxDynamicSharedMemorySize, SMEM);
    cudaFuncSetAttribute(gemm_k<3, false>, cudaFuncAttributeMaxDynamicSharedMemorySize, SMEM);

    const int GB = (NN + 63) / 64;   // 782 blocks

    // ---- prep (ordered so the 6th launch is gemm_p12 for ncu -s 5) ----
    encoder_k<<<(NN + 15) / 16, 128>>>(x, enc_w, enc_b, h);               // 1
    zero_int<<<(NN + 255) / 256, 256>>>(cursor, NN);                      // 2
    count_k<<<(EE + 255) / 256, 256>>>(ei, cursor);                       // 3
    scan_part<<<NB, 256>>>(cursor, rowptr, bsum);                         // 4
    scan_bsum<<<1, 256>>>(bsum);                                          // 5
    // layer 0 P1/P2 (independent of CSR build)                           // 6
    gemm_p12<<<GB, 256, SMEM>>>(h, msg_w1, msg_w1 + 128 * HD, msg_b1, P1, P2);
    add_off<<<NB, 256>>>(rowptr, bsum, cursor);                           // 7
    degf_k<<<(NN + 255) / 256, 256>>>(rowptr, degf);                      // 8
    scatter_k<<<(EE + 255) / 256, 256>>>(ei, pos, cursor, epack);         // 9
    build_w2u<<<dim3(129, 4), 128>>>(msg_w2, msg_b2, upd_w1, W2U, cvec);  // 10
    zero_k<<<(NG * HD + 255) / 256, 256>>>(pooled, NG * HD);              // 11
    zero_k<<<1, 64>>>(cnt, NG);                                           // 12

    for (int l = 0; l < NLAY; l++) {
        const float* w1l = msg_w1 + l * 257 * HD;
        if (l > 0) {
            // P1 = h@W1a + b1 ; P2 = h@W1b  (layer 0 hoisted above)
            gemm_p12<<<GB, 256, SMEM>>>(h, w1l, w1l + 128 * HD,
                                        msg_b1 + l * HD, P1, P2);
        }
        // CSR gather: Yagg[i] = sum_e relu(P1[i]+P2[src]+dist*w1c)
        aggregate_k<<<NN / 8, 256>>>(rowptr, epack, P1, P2,
                                     w1l + 256 * HD, Yagg);
        // T = relu(h@U1a + Yagg@W2U + deg*cvec + bu1)
        gemm_k<2, true><<<GB, 256, SMEM>>>(h, Yagg, upd_w1 + l * 256 * HD,
                                           W2U + l * HD * HD, upd_b1 + l * HD,
                                           degf, cvec + l * HD,
                                           nullptr, nullptr, 0, T, NN);
        // h = (l? h : 0) + relu(LN(T@U2 + bu2))
        gemm_k<3, false><<<GB, 256, SMEM>>>(T, nullptr, upd_w2 + l * HD * HD, nullptr,
                                            upd_b2 + l * HD, nullptr, nullptr,
                                            ln_g + l * HD, ln_b + l * HD,
                                            (l > 0) ? 1 : 0, h, NN);
    }

    pool_k<<<(NN + 7) / 8, 256>>>(h, batch, pooled, cnt);
    readout_k<<<NG, 128>>>(pooled, cnt, mlp_w1, mlp_b1, mlp_w2, mlp_b2,
                           mlp_w3, mlp_b3, out);
}

// round 7
// speedup vs baseline: 1.5448x; 1.5448x over previous
#include <cuda_runtime.h>

#define NN 50000
#define EE 500000
#define HD 128
#define NLAY 4
#define NG 64
#define NB 196  // (NN+255)/256 scan blocks

// ---------------- scratch (device globals) ------------------------------------
__device__ __align__(16) float d_h[NN * HD];
__device__ __align__(16) float d_P1[NN * HD];
__device__ __align__(16) float d_P2[NN * HD];
__device__ __align__(16) float d_Yagg[NN * HD];
__device__ __align__(16) float d_T[NN * HD];
__device__ __align__(16) float d_degf[NN];
__device__ __align__(16) float d_W2U[NLAY * HD * HD];
__device__ __align__(16) float d_cvec[NLAY * HD];
__device__ __align__(16) float d_pooled[NG * HD];
__device__ __align__(16) float d_cnt[NG];
// CSR
__device__ __align__(16) int   d_rowptr[NN + 1];
__device__ __align__(16) int   d_cursor[NN];
__device__ __align__(16) int   d_bsum[256];
__device__ __align__(16) int   d_esrc[EE];
__device__ __align__(16) float d_edist[EE];

// ---------------- f32x2 packed helpers ---------------------------------------
__device__ __forceinline__ unsigned long long pk2(float lo, float hi) {
    unsigned long long r;
    asm("mov.b64 %0, {%1,%2};" : "=l"(r) : "f"(lo), "f"(hi));
    return r;
}
__device__ __forceinline__ void upk2(unsigned long long v, float& lo, float& hi) {
    asm("mov.b64 {%0,%1}, %2;" : "=f"(lo), "=f"(hi) : "l"(v));
}
__device__ __forceinline__ unsigned long long fma2(unsigned long long a,
                                                   unsigned long long b,
                                                   unsigned long long c) {
    unsigned long long d;
    asm("fma.rn.f32x2 %0, %1, %2, %3;" : "=l"(d) : "l"(a), "l"(b), "l"(c));
    return d;
}

// ---------------- tiny utility kernels ----------------------------------------
__global__ void zero_k(float* __restrict__ p, int n) {
    int i = blockIdx.x * blockDim.x + threadIdx.x;
    if (i < n) p[i] = 0.0f;
}
__global__ void zero_int(int* __restrict__ p, int n) {
    int i = blockIdx.x * blockDim.x + threadIdx.x;
    if (i < n) p[i] = 0;
}

// ---------------- CSR build ----------------------------------------------------
__global__ void count_k(const int* __restrict__ ei, int* __restrict__ deg) {
    int e = blockIdx.x * blockDim.x + threadIdx.x;
    if (e < EE) atomicAdd(&deg[ei[EE + e]], 1);
}

__global__ void scan_part(const int* __restrict__ deg, int* __restrict__ rowptr,
                          int* __restrict__ bsum) {
    __shared__ int s[256];
    int tid = threadIdx.x;
    int i = blockIdx.x * 256 + tid;
    int v = (i < NN) ? deg[i] : 0;
    s[tid] = v;
    __syncthreads();
#pragma unroll
    for (int off = 1; off < 256; off <<= 1) {
        int t = (tid >= off) ? s[tid - off] : 0;
        __syncthreads();
        s[tid] += t;
        __syncthreads();
    }
    if (i < NN) rowptr[i] = s[tid] - v;
    if (tid == 255) bsum[blockIdx.x] = s[255];
}

__global__ void scan_bsum(int* __restrict__ bsum) {
    __shared__ int s[256];
    int tid = threadIdx.x;
    int v = (tid < NB) ? bsum[tid] : 0;
    s[tid] = v;
    __syncthreads();
#pragma unroll
    for (int off = 1; off < 256; off <<= 1) {
        int t = (tid >= off) ? s[tid - off] : 0;
        __syncthreads();
        s[tid] += t;
        __syncthreads();
    }
    if (tid < NB) bsum[tid] = s[tid] - v;
}

__global__ void add_off(int* __restrict__ rowptr, const int* __restrict__ bsum,
                        int* __restrict__ cursor) {
    int i = blockIdx.x * 256 + threadIdx.x;
    if (i < NN) {
        int r = rowptr[i] + bsum[blockIdx.x];
        rowptr[i] = r;
        cursor[i] = r;
    }
    if (i == 0) rowptr[NN] = EE;
}

__global__ void degf_k(const int* __restrict__ rowptr, float* __restrict__ degf) {
    int i = blockIdx.x * blockDim.x + threadIdx.x;
    if (i < NN) degf[i] = (float)(rowptr[i + 1] - rowptr[i]);
}

__global__ void scatter_k(const int* __restrict__ ei,
                          const float* __restrict__ pos,
                          int* __restrict__ cursor,
                          int* __restrict__ esrc,
                          float* __restrict__ edist) {
    int e = blockIdx.x * blockDim.x + threadIdx.x;
    if (e >= EE) return;
    int s = ei[e];
    int t = ei[EE + e];
    float dx = pos[t * 3 + 0] - pos[s * 3 + 0];
    float dy = pos[t * 3 + 1] - pos[s * 3 + 1];
    float dz = pos[t * 3 + 2] - pos[s * 3 + 2];
    float dd = sqrtf(dx * dx + dy * dy + dz * dz);
    int p = atomicAdd(&cursor[t], 1);
    esrc[p] = s;
    edist[p] = dd;
}

// ---------------- encoder: h = x @ enc_w + enc_b (K=15) -----------------------
__global__ void encoder_k(const float* __restrict__ x,
                          const float* __restrict__ w,
                          const float* __restrict__ b,
                          float* __restrict__ h) {
    __shared__ float ws[15 * HD];
    __shared__ float xs[16 * 15];
    __shared__ float bs[HD];
    int c = threadIdx.x;
    for (int i = c; i < 15 * HD; i += HD) ws[i] = w[i];
    bs[c] = b[c];
    int n0 = blockIdx.x * 16;
    for (int i = c; i < 16 * 15; i += HD) {
        int nn = i / 15, kk = i % 15;
        int g = n0 + nn;
        xs[i] = (g < NN) ? x[g * 15 + kk] : 0.0f;
    }
    __syncthreads();
    for (int r = 0; r < 16; r++) {
        int g = n0 + r;
        if (g >= NN) break;
        float acc = bs[c];
#pragma unroll
        for (int k = 0; k < 15; k++) acc += xs[r * 15 + k] * ws[k * HD + c];
        h[g * HD + c] = acc;
    }
}

// W2U[l] = msg_w2[l] @ U1b[l];  cvec[l] = msg_b2[l] @ U1b[l]
__global__ void build_w2u(const float* __restrict__ msg_w2,
                          const float* __restrict__ msg_b2,
                          const float* __restrict__ upd_w1,
                          float* __restrict__ W2U,
                          float* __restrict__ cvec) {
    int l = blockIdx.y, k = blockIdx.x, c = threadIdx.x;
    const float* u1b = upd_w1 + l * 256 * HD + 128 * HD;
    if (k < HD) {
        const float* wrow = msg_w2 + (l * HD + k) * HD;
        float acc = 0.0f;
        for (int j = 0; j < HD; j++) acc += wrow[j] * u1b[j * HD + c];
        W2U[(l * HD + k) * HD + c] = acc;
    } else {
        const float* brow = msg_b2 + l * HD;
        float acc = 0.0f;
        for (int j = 0; j < HD; j++) acc += brow[j] * u1b[j * HD + c];
        cvec[l * HD + c] = acc;
    }
}

// ---------------- CSR gather aggregation (unroll 2) ----------------------------
__global__ void __launch_bounds__(256) aggregate_k(
    const int* __restrict__ rowptr,
    const int* __restrict__ esrc,
    const float* __restrict__ edist,
    const float* __restrict__ P1,
    const float* __restrict__ P2,
    const float* __restrict__ w1c,
    float* __restrict__ Yagg) {
    int node = blockIdx.x * 8 + (threadIdx.x >> 5);
    int lane = threadIdx.x & 31;
    int c4 = lane * 4;
    const float4 cw = *(const float4*)&w1c[c4];
    const float4 p1 = *(const float4*)&P1[node * HD + c4];
    float a0 = 0.f, a1 = 0.f, a2 = 0.f, a3 = 0.f;
    float b0 = 0.f, b1 = 0.f, b2 = 0.f, b3 = 0.f;
    int beg = rowptr[node], end = rowptr[node + 1];
    int e = beg;
    for (; e + 1 < end; e += 2) {
        int s0 = esrc[e], s1 = esrc[e + 1];
        float dd0 = edist[e], dd1 = edist[e + 1];
        const float4 v0 = *(const float4*)&P2[s0 * HD + c4];
        const float4 v1 = *(const float4*)&P2[s1 * HD + c4];
        a0 += fmaxf(p1.x + v0.x + dd0 * cw.x, 0.0f);
        a1 += fmaxf(p1.y + v0.y + dd0 * cw.y, 0.0f);
        a2 += fmaxf(p1.z + v0.z + dd0 * cw.z, 0.0f);
        a3 += fmaxf(p1.w + v0.w + dd0 * cw.w, 0.0f);
        b0 += fmaxf(p1.x + v1.x + dd1 * cw.x, 0.0f);
        b1 += fmaxf(p1.y + v1.y + dd1 * cw.y, 0.0f);
        b2 += fmaxf(p1.z + v1.z + dd1 * cw.z, 0.0f);
        b3 += fmaxf(p1.w + v1.w + dd1 * cw.w, 0.0f);
    }
    if (e < end) {
        int s0 = esrc[e];
        float dd0 = edist[e];
        const float4 v0 = *(const float4*)&P2[s0 * HD + c4];
        a0 += fmaxf(p1.x + v0.x + dd0 * cw.x, 0.0f);
        a1 += fmaxf(p1.y + v0.y + dd0 * cw.y, 0.0f);
        a2 += fmaxf(p1.z + v0.z + dd0 * cw.z, 0.0f);
        a3 += fmaxf(p1.w + v0.w + dd0 * cw.w, 0.0f);
    }
    *(float4*)&Yagg[node * HD + c4] =
        make_float4(a0 + b0, a1 + b1, a2 + b2, a3 + b3);
}

// ---------------- main GEMM: 64 rows x 128 cols, 256 thr, 2 blocks/SM ----------
__device__ __forceinline__ void load_tile_A64(float* As, const float* __restrict__ A,
                                              int rowbase, int tid, int n) {
    const float4* av = (const float4*)A;
    float4* asv = (float4*)As;
#pragma unroll
    for (int i = 0; i < 8; i++) {
        int idx = tid + i * 256;          // 0..2047
        int r = idx >> 5;
        int grow = rowbase + r;
        int cr = (grow < n) ? grow : (n - 1);
        asv[idx] = av[cr * 32 + (idx & 31)];
    }
}

__device__ __forceinline__ void load_tile_B(float* Bs, const float* __restrict__ B,
                                            int tid) {
    const float4* bv = (const float4*)B;
    float4* bs = (float4*)Bs;
#pragma unroll
    for (int i = 0; i < 16; i++) bs[tid + i * 256] = bv[tid + i * 256];
}

__device__ __forceinline__ void gemm_compute(const float* As, const float* Bs,
                                             unsigned long long acc0[8],
                                             unsigned long long acc1[8],
                                             int warp, int lane) {
#pragma unroll 2
    for (int k0 = 0; k0 < HD; k0 += 4) {
        float4 avv[8];
#pragma unroll
        for (int r = 0; r < 8; r++)
            avv[r] = *(const float4*)&As[(warp * 8 + r) * HD + k0];
#pragma unroll
        for (int kk = 0; kk < 4; kk++) {
            const unsigned long long* bp =
                (const unsigned long long*)&Bs[(k0 + kk) * HD + lane * 4];
            unsigned long long b01 = bp[0];
            unsigned long long b23 = bp[1];
#pragma unroll
            for (int r = 0; r < 8; r++) {
                float a = (&avv[r].x)[kk];
                unsigned long long a2 = pk2(a, a);
                acc0[r] = fma2(a2, b01, acc0[r]);
                acc1[r] = fma2(a2, b23, acc1[r]);
            }
        }
    }
}

// EPI: 0 = +bias, 1 = plain, 2 = +deg*cvec+bias, relu, 3 = +bias, LN, relu, (+res)
template <int EPI, bool TWOA>
__global__ void __launch_bounds__(256) gemm_k(
    const float* __restrict__ A0, const float* __restrict__ A1,
    const float* __restrict__ B0, const float* __restrict__ B1,
    const float* __restrict__ bias,
    const float* __restrict__ degf, const float* __restrict__ cvec,
    const float* __restrict__ lng, const float* __restrict__ lnb,
    int addres, float* __restrict__ Out, int n) {
    extern __shared__ float sm[];
    float* Bs = sm;                 // 128 x 128
    float* As = sm + 128 * HD;      // 64 x 128
    int tid = threadIdx.x;
    int rowbase = blockIdx.x * 64;

    load_tile_B(Bs, B0, tid);
    load_tile_A64(As, A0, rowbase, tid, n);
    __syncthreads();

    unsigned long long acc0[8], acc1[8];
#pragma unroll
    for (int r = 0; r < 8; r++) { acc0[r] = 0ULL; acc1[r] = 0ULL; }

    int warp = tid >> 5, lane = tid & 31;
    gemm_compute(As, Bs, acc0, acc1, warp, lane);
    if (TWOA) {
        __syncthreads();
        load_tile_B(Bs, B1, tid);
        load_tile_A64(As, A1, rowbase, tid, n);
        __syncthreads();
        gemm_compute(As, Bs, acc0, acc1, warp, lane);
    }

    int col = lane * 4;
    int rb = rowbase + warp * 8;
#pragma unroll
    for (int r = 0; r < 8; r++) {
        int grow = rb + r;
        float o0, o1, o2, o3;
        upk2(acc0[r], o0, o1);
        upk2(acc1[r], o2, o3);
        if (EPI == 0) {
            o0 += bias[col + 0]; o1 += bias[col + 1];
            o2 += bias[col + 2]; o3 += bias[col + 3];
        }
        if (EPI == 2) {
            float dg = degf[(grow < n) ? grow : 0];
            o0 = fmaxf(o0 + dg * cvec[col + 0] + bias[col + 0], 0.0f);
            o1 = fmaxf(o1 + dg * cvec[col + 1] + bias[col + 1], 0.0f);
            o2 = fmaxf(o2 + dg * cvec[col + 2] + bias[col + 2], 0.0f);
            o3 = fmaxf(o3 + dg * cvec[col + 3] + bias[col + 3], 0.0f);
        }
        if (EPI == 3) {
            o0 += bias[col + 0]; o1 += bias[col + 1];
            o2 += bias[col + 2]; o3 += bias[col + 3];
            float s = o0 + o1 + o2 + o3;
            float sq = o0 * o0 + o1 * o1 + o2 * o2 + o3 * o3;
#pragma unroll
            for (int off = 16; off; off >>= 1) {
                s += __shfl_xor_sync(0xffffffffu, s, off);
                sq += __shfl_xor_sync(0xffffffffu, sq, off);
            }
            float mu = s * (1.0f / HD);
            float var = sq * (1.0f / HD) - mu * mu;
            float rstd = rsqrtf(var + 1e-5f);
            o0 = fmaxf((o0 - mu) * rstd * lng[col + 0] + lnb[col + 0], 0.0f);
            o1 = fmaxf((o1 - mu) * rstd * lng[col + 1] + lnb[col + 1], 0.0f);
            o2 = fmaxf((o2 - mu) * rstd * lng[col + 2] + lnb[col + 2], 0.0f);
            o3 = fmaxf((o3 - mu) * rstd * lng[col + 3] + lnb[col + 3], 0.0f);
            if (addres && grow < n) {
                const float4 hv = *(const float4*)&Out[grow * HD + col];
                o0 += hv.x; o1 += hv.y; o2 += hv.z; o3 += hv.w;
            }
        }
        if (grow < n) {
            *(float4*)&Out[grow * HD + col] = make_float4(o0, o1, o2, o3);
        }
    }
}

// ---------------- readout ------------------------------------------------------
__global__ void pool_k(const float* __restrict__ h,
                       const int* __restrict__ batch,
                       float* __restrict__ pooled, float* __restrict__ cnt) {
    int nidx = blockIdx.x * 8 + (threadIdx.x >> 5);
    int lane = threadIdx.x & 31;
    if (nidx >= NN) return;
    int g = batch[nidx];
    float4 v = *(const float4*)&h[nidx * HD + lane * 4];
    float* p = &pooled[g * HD + lane * 4];
    atomicAdd(p + 0, v.x);
    atomicAdd(p + 1, v.y);
    atomicAdd(p + 2, v.z);
    atomicAdd(p + 3, v.w);
    if (lane == 0) atomicAdd(&cnt[g], 1.0f);
}

__global__ void readout_k(const float* __restrict__ pooled,
                          const float* __restrict__ cnt,
                          const float* __restrict__ w1, const float* __restrict__ b1,
                          const float* __restrict__ w2, const float* __restrict__ b2,
                          const float* __restrict__ w3, const float* __restrict__ b3,
                          float* __restrict__ out) {
    __shared__ float p[HD];
    __shared__ float o1s[HD];
    __shared__ float o2s[64];
    int g = blockIdx.x, c = threadIdx.x;
    float cc = fmaxf(cnt[g], 1.0f);
    p[c] = pooled[g * HD + c] / cc;
    __syncthreads();
    float acc = b1[c];
    for (int k = 0; k < HD; k++) acc += p[k] * w1[k * HD + c];
    o1s[c] = fmaxf(acc, 0.0f);
    __syncthreads();
    if (c < 64) {
        float a = b2[c];
        for (int k = 0; k < HD; k++) a += o1s[k] * w2[k * 64 + c];
        o2s[c] = fmaxf(a, 0.0f);
    }
    __syncthreads();
    if (c == 0) {
        float a = b3[0];
        for (int k = 0; k < 64; k++) a += o2s[k] * w3[k];
        out[g] = a;
    }
}

// ---------------- launch --------------------------------------------------------
extern "C" void kernel_launch(void* const* d_in, const int* in_sizes, int n_in,
                              void* d_out, int out_size) {
    const float* x       = (const float*)d_in[0];
    const int*   ei      = (const int*)d_in[1];
    const float* pos     = (const float*)d_in[3];
    const int*   batch   = (const int*)d_in[4];
    const float* enc_w   = (const float*)d_in[5];
    const float* enc_b   = (const float*)d_in[6];
    const float* msg_w1  = (const float*)d_in[9];
    const float* msg_b1  = (const float*)d_in[10];
    const float* msg_w2  = (const float*)d_in[11];
    const float* msg_b2  = (const float*)d_in[12];
    const float* upd_w1  = (const float*)d_in[13];
    const float* upd_b1  = (const float*)d_in[14];
    const float* upd_w2  = (const float*)d_in[15];
    const float* upd_b2  = (const float*)d_in[16];
    const float* ln_g    = (const float*)d_in[17];
    const float* ln_b    = (const float*)d_in[18];
    const float* mlp_w1  = (const float*)d_in[19];
    const float* mlp_b1  = (const float*)d_in[20];
    const float* mlp_w2  = (const float*)d_in[21];
    const float* mlp_b2  = (const float*)d_in[22];
    const float* mlp_w3  = (const float*)d_in[23];
    const float* mlp_b3  = (const float*)d_in[24];
    float*       out     = (float*)d_out;

    float *h, *P1, *P2, *Yagg, *T, *degf, *W2U, *cvec, *pooled, *cnt, *edist;
    int *rowptr, *cursor, *bsum, *esrc;
    cudaGetSymbolAddress((void**)&h, d_h);
    cudaGetSymbolAddress((void**)&P1, d_P1);
    cudaGetSymbolAddress((void**)&P2, d_P2);
    cudaGetSymbolAddress((void**)&Yagg, d_Yagg);
    cudaGetSymbolAddress((void**)&T, d_T);
    cudaGetSymbolAddress((void**)&degf, d_degf);
    cudaGetSymbolAddress((void**)&W2U, d_W2U);
    cudaGetSymbolAddress((void**)&cvec, d_cvec);
    cudaGetSymbolAddress((void**)&pooled, d_pooled);
    cudaGetSymbolAddress((void**)&cnt, d_cnt);
    cudaGetSymbolAddress((void**)&rowptr, d_rowptr);
    cudaGetSymbolAddress((void**)&cursor, d_cursor);
    cudaGetSymbolAddress((void**)&bsum, d_bsum);
    cudaGetSymbolAddress((void**)&esrc, d_esrc);
    cudaGetSymbolAddress((void**)&edist, d_edist);

    const int SMEM = (128 * HD + 64 * HD) * 4;   // 96 KB
    cudaFuncSetAttribute(gemm_k<0, false>, cudaFuncAttributeMaxDynamicSharedMemorySize, SMEM);
    cudaFuncSetAttribute(gemm_k<1, false>, cudaFuncAttributeMaxDynamicSharedMemorySize, SMEM);
    cudaFuncSetAttribute(gemm_k<2, true>,  cudaFuncAttributeMaxDynamicSharedMemorySize, SMEM);
    cudaFuncSetAttribute(gemm_k<3, false>, cudaFuncAttributeMaxDynamicSharedMemorySize, SMEM);

    const int GB = (NN + 63) / 64;   // 782 blocks

    // ---- prep; launch #4 = layer-0 P1 GEMM so ncu captures it ----
    encoder_k<<<(NN + 15) / 16, 128>>>(x, enc_w, enc_b, h);               // 1
    zero_int<<<(NN + 255) / 256, 256>>>(cursor, NN);                      // 2
    count_k<<<(EE + 255) / 256, 256>>>(ei, cursor);                       // 3
    gemm_k<0, false><<<GB, 256, SMEM>>>(h, nullptr, msg_w1, nullptr,      // 4 (profiled)
                                        msg_b1, nullptr, nullptr,
                                        nullptr, nullptr, 0, P1, NN);
    scan_part<<<NB, 256>>>(cursor, rowptr, bsum);                         // 5
    scan_bsum<<<1, 256>>>(bsum);                                          // 6
    add_off<<<NB, 256>>>(rowptr, bsum, cursor);                           // 7
    degf_k<<<(NN + 255) / 256, 256>>>(rowptr, degf);                      // 8
    scatter_k<<<(EE + 255) / 256, 256>>>(ei, pos, cursor, esrc, edist);   // 9
    build_w2u<<<dim3(129, 4), 128>>>(msg_w2, msg_b2, upd_w1, W2U, cvec);  // 10
    zero_k<<<(NG * HD + 255) / 256, 256>>>(pooled, NG * HD);              // 11
    zero_k<<<1, 64>>>(cnt, NG);                                           // 12

    for (int l = 0; l < NLAY; l++) {
        const float* w1l = msg_w1 + l * 257 * HD;
        // P1 = h@W1a + b1 (layer 0 hoisted to launch #4) ; P2 = h@W1b
        if (l > 0) {
            gemm_k<0, false><<<GB, 256, SMEM>>>(h, nullptr, w1l, nullptr,
                                                msg_b1 + l * HD, nullptr, nullptr,
                                                nullptr, nullptr, 0, P1, NN);
        }
        gemm_k<1, false><<<GB, 256, SMEM>>>(h, nullptr, w1l + 128 * HD, nullptr,
                                            nullptr, nullptr, nullptr,
                                            nullptr, nullptr, 0, P2, NN);
        // CSR gather: Yagg[i] = sum_e relu(P1[i]+P2[src]+dist*w1c)
        aggregate_k<<<NN / 8, 256>>>(rowptr, esrc, edist, P1, P2,
                                     w1l + 256 * HD, Yagg);
        // T = relu(h@U1a + Yagg@W2U + deg*cvec + bu1)
        gemm_k<2, true><<<GB, 256, SMEM>>>(h, Yagg, upd_w1 + l * 256 * HD,
                                           W2U + l * HD * HD, upd_b1 + l * HD,
                                           degf, cvec + l * HD,
                                           nullptr, nullptr, 0, T, NN);
        // h = (l? h : 0) + relu(LN(T@U2 + bu2))
        gemm_k<3, false><<<GB, 256, SMEM>>>(T, nullptr, upd_w2 + l * HD * HD, nullptr,
                                            upd_b2 + l * HD, nullptr, nullptr,
                                            ln_g + l * HD, ln_b + l * HD,
                                            (l > 0) ? 1 : 0, h, NN);
    }

    pool_k<<<(NN + 7) / 8, 256>>>(h, batch, pooled, cnt);
    readout_k<<<NG, 128>>>(pooled, cnt, mlp_w1, mlp_b1, mlp_w2, mlp_b2,
                           mlp_w3, mlp_b3, out);
}

// round 8
// speedup vs baseline: 1.6192x; 1.0481x over previous
#include <cuda_runtime.h>

#define NN 50000
#define EE 500000
#define HD 128
#define NLAY 4
#define NG 64
#define NB 196  // (NN+255)/256 scan blocks

// ---------------- scratch (device globals) ------------------------------------
__device__ __align__(16) float d_h[NN * HD];
__device__ __align__(16) float d_P1[NN * HD];
__device__ __align__(16) float d_P2[NN * HD];
__device__ __align__(16) float d_Yagg[NN * HD];
__device__ __align__(16) float d_T[NN * HD];
__device__ __align__(16) float d_degf[NN];
__device__ __align__(16) float d_W2U[NLAY * HD * HD];
__device__ __align__(16) float d_cvec[NLAY * HD];
__device__ __align__(16) float d_pooled[NG * HD];
__device__ __align__(16) float d_cnt[NG];
// CSR
__device__ __align__(16) int   d_rowptr[NN + 1];
__device__ __align__(16) int   d_cursor[NN];
__device__ __align__(16) int   d_bsum[256];
__device__ __align__(16) int2  d_epack[EE];   // (src, dist bits)

// ---------------- helpers -------------------------------------------------------
__device__ __forceinline__ unsigned long long pk2(float lo, float hi) {
    unsigned long long r;
    asm("mov.b64 %0, {%1,%2};" : "=l"(r) : "f"(lo), "f"(hi));
    return r;
}
__device__ __forceinline__ void upk2(unsigned long long v, float& lo, float& hi) {
    asm("mov.b64 {%0,%1}, %2;" : "=f"(lo), "=f"(hi) : "l"(v));
}
__device__ __forceinline__ unsigned long long fma2(unsigned long long a,
                                                   unsigned long long b,
                                                   unsigned long long c) {
    unsigned long long d;
    asm("fma.rn.f32x2 %0, %1, %2, %3;" : "=l"(d) : "l"(a), "l"(b), "l"(c));
    return d;
}
__device__ __forceinline__ unsigned smem_u32(const void* p) {
    unsigned r;
    asm("{ .reg .u64 t; cvta.to.shared.u64 t, %1; cvt.u32.u64 %0, t; }"
        : "=r"(r) : "l"(p));
    return r;
}
__device__ __forceinline__ void cp16(unsigned saddr, const void* g) {
    asm volatile("cp.async.cg.shared.global [%0], [%1], 16;" :: "r"(saddr), "l"(g));
}
__device__ __forceinline__ void cp_commit_wait() {
    asm volatile("cp.async.commit_group;");
    asm volatile("cp.async.wait_group 0;");
}

// ---------------- tiny utility kernels ----------------------------------------
__global__ void zero_k(float* __restrict__ p, int n) {
    int i = blockIdx.x * blockDim.x + threadIdx.x;
    if (i < n) p[i] = 0.0f;
}
__global__ void zero_int(int* __restrict__ p, int n) {
    int i = blockIdx.x * blockDim.x + threadIdx.x;
    if (i < n) p[i] = 0;
}

// ---------------- CSR build ----------------------------------------------------
__global__ void count_k(const int* __restrict__ ei, int* __restrict__ deg) {
    int e = blockIdx.x * blockDim.x + threadIdx.x;
    if (e < EE) atomicAdd(&deg[ei[EE + e]], 1);
}

__global__ void scan_part(const int* __restrict__ deg, int* __restrict__ rowptr,
                          int* __restrict__ bsum) {
    __shared__ int s[256];
    int tid = threadIdx.x;
    int i = blockIdx.x * 256 + tid;
    int v = (i < NN) ? deg[i] : 0;
    s[tid] = v;
    __syncthreads();
#pragma unroll
    for (int off = 1; off < 256; off <<= 1) {
        int t = (tid >= off) ? s[tid - off] : 0;
        __syncthreads();
        s[tid] += t;
        __syncthreads();
    }
    if (i < NN) rowptr[i] = s[tid] - v;
    if (tid == 255) bsum[blockIdx.x] = s[255];
}

__global__ void scan_bsum(int* __restrict__ bsum) {
    __shared__ int s[256];
    int tid = threadIdx.x;
    int v = (tid < NB) ? bsum[tid] : 0;
    s[tid] = v;
    __syncthreads();
#pragma unroll
    for (int off = 1; off < 256; off <<= 1) {
        int t = (tid >= off) ? s[tid - off] : 0;
        __syncthreads();
        s[tid] += t;
        __syncthreads();
    }
    if (tid < NB) bsum[tid] = s[tid] - v;
}

__global__ void add_off(int* __restrict__ rowptr, const int* __restrict__ bsum,
                        int* __restrict__ cursor) {
    int i = blockIdx.x * 256 + threadIdx.x;
    if (i < NN) {
        int r = rowptr[i] + bsum[blockIdx.x];
        rowptr[i] = r;
        cursor[i] = r;
    }
    if (i == 0) rowptr[NN] = EE;
}

__global__ void degf_k(const int* __restrict__ rowptr, float* __restrict__ degf) {
    int i = blockIdx.x * blockDim.x + threadIdx.x;
    if (i < NN) degf[i] = (float)(rowptr[i + 1] - rowptr[i]);
}

__global__ void scatter_k(const int* __restrict__ ei,
                          const float* __restrict__ pos,
                          int* __restrict__ cursor,
                          int2* __restrict__ epack) {
    int e = blockIdx.x * blockDim.x + threadIdx.x;
    if (e >= EE) return;
    int s = ei[e];
    int t = ei[EE + e];
    float dx = pos[t * 3 + 0] - pos[s * 3 + 0];
    float dy = pos[t * 3 + 1] - pos[s * 3 + 1];
    float dz = pos[t * 3 + 2] - pos[s * 3 + 2];
    float dd = sqrtf(dx * dx + dy * dy + dz * dz);
    int p = atomicAdd(&cursor[t], 1);
    epack[p] = make_int2(s, __float_as_int(dd));
}

// ---------------- encoder: h = x @ enc_w + enc_b (K=15) -----------------------
__global__ void encoder_k(const float* __restrict__ x,
                          const float* __restrict__ w,
                          const float* __restrict__ b,
                          float* __restrict__ h) {
    __shared__ float ws[15 * HD];
    __shared__ float xs[16 * 15];
    __shared__ float bs[HD];
    int c = threadIdx.x;
    for (int i = c; i < 15 * HD; i += HD) ws[i] = w[i];
    bs[c] = b[c];
    int n0 = blockIdx.x * 16;
    for (int i = c; i < 16 * 15; i += HD) {
        int nn = i / 15, kk = i % 15;
        int g = n0 + nn;
        xs[i] = (g < NN) ? x[g * 15 + kk] : 0.0f;
    }
    __syncthreads();
    for (int r = 0; r < 16; r++) {
        int g = n0 + r;
        if (g >= NN) break;
        float acc = bs[c];
#pragma unroll
        for (int k = 0; k < 15; k++) acc += xs[r * 15 + k] * ws[k * HD + c];
        h[g * HD + c] = acc;
    }
}

// W2U[l] = msg_w2[l] @ U1b[l];  cvec[l] = msg_b2[l] @ U1b[l]
__global__ void build_w2u(const float* __restrict__ msg_w2,
                          const float* __restrict__ msg_b2,
                          const float* __restrict__ upd_w1,
                          float* __restrict__ W2U,
                          float* __restrict__ cvec) {
    int l = blockIdx.y, k = blockIdx.x, c = threadIdx.x;
    const float* u1b = upd_w1 + l * 256 * HD + 128 * HD;
    if (k < HD) {
        const float* wrow = msg_w2 + (l * HD + k) * HD;
        float acc = 0.0f;
        for (int j = 0; j < HD; j++) acc += wrow[j] * u1b[j * HD + c];
        W2U[(l * HD + k) * HD + c] = acc;
    } else {
        const float* brow = msg_b2 + l * HD;
        float acc = 0.0f;
        for (int j = 0; j < HD; j++) acc += brow[j] * u1b[j * HD + c];
        cvec[l * HD + c] = acc;
    }
}

// ---------------- CSR gather aggregation (packed edges, unroll 4) --------------
__global__ void __launch_bounds__(256) aggregate_k(
    const int* __restrict__ rowptr,
    const int2* __restrict__ epack,
    const float* __restrict__ P1,
    const float* __restrict__ P2,
    const float* __restrict__ w1c,
    float* __restrict__ Yagg) {
    int node = blockIdx.x * 8 + (threadIdx.x >> 5);
    int lane = threadIdx.x & 31;
    int c4 = lane * 4;
    const float4 cw = *(const float4*)&w1c[c4];
    const float4 p1 = *(const float4*)&P1[node * HD + c4];
    float a0 = 0.f, a1 = 0.f, a2 = 0.f, a3 = 0.f;
    float b0 = 0.f, b1 = 0.f, b2 = 0.f, b3 = 0.f;
    float c0 = 0.f, c1 = 0.f, c2 = 0.f, c3 = 0.f;
    float d0 = 0.f, d1 = 0.f, d2 = 0.f, d3 = 0.f;
    int beg = rowptr[node], end = rowptr[node + 1];
    int e = beg;
    for (; e + 3 < end; e += 4) {
        int2 q0 = epack[e], q1 = epack[e + 1], q2 = epack[e + 2], q3 = epack[e + 3];
        const float4 v0 = *(const float4*)&P2[q0.x * HD + c4];
        const float4 v1 = *(const float4*)&P2[q1.x * HD + c4];
        const float4 v2 = *(const float4*)&P2[q2.x * HD + c4];
        const float4 v3 = *(const float4*)&P2[q3.x * HD + c4];
        float dd0 = __int_as_float(q0.y), dd1 = __int_as_float(q1.y);
        float dd2 = __int_as_float(q2.y), dd3 = __int_as_float(q3.y);
        a0 += fmaxf(p1.x + v0.x + dd0 * cw.x, 0.0f);
        a1 += fmaxf(p1.y + v0.y + dd0 * cw.y, 0.0f);
        a2 += fmaxf(p1.z + v0.z + dd0 * cw.z, 0.0f);
        a3 += fmaxf(p1.w + v0.w + dd0 * cw.w, 0.0f);
        b0 += fmaxf(p1.x + v1.x + dd1 * cw.x, 0.0f);
        b1 += fmaxf(p1.y + v1.y + dd1 * cw.y, 0.0f);
        b2 += fmaxf(p1.z + v1.z + dd1 * cw.z, 0.0f);
        b3 += fmaxf(p1.w + v1.w + dd1 * cw.w, 0.0f);
        c0 += fmaxf(p1.x + v2.x + dd2 * cw.x, 0.0f);
        c1 += fmaxf(p1.y + v2.y + dd2 * cw.y, 0.0f);
        c2 += fmaxf(p1.z + v2.z + dd2 * cw.z, 0.0f);
        c3 += fmaxf(p1.w + v2.w + dd2 * cw.w, 0.0f);
        d0 += fmaxf(p1.x + v3.x + dd3 * cw.x, 0.0f);
        d1 += fmaxf(p1.y + v3.y + dd3 * cw.y, 0.0f);
        d2 += fmaxf(p1.z + v3.z + dd3 * cw.z, 0.0f);
        d3 += fmaxf(p1.w + v3.w + dd3 * cw.w, 0.0f);
    }
    for (; e < end; e++) {
        int2 q0 = epack[e];
        const float4 v0 = *(const float4*)&P2[q0.x * HD + c4];
        float dd0 = __int_as_float(q0.y);
        a0 += fmaxf(p1.x + v0.x + dd0 * cw.x, 0.0f);
        a1 += fmaxf(p1.y + v0.y + dd0 * cw.y, 0.0f);
        a2 += fmaxf(p1.z + v0.z + dd0 * cw.z, 0.0f);
        a3 += fmaxf(p1.w + v0.w + dd0 * cw.w, 0.0f);
    }
    *(float4*)&Yagg[node * HD + c4] = make_float4(
        (a0 + b0) + (c0 + d0), (a1 + b1) + (c1 + d1),
        (a2 + b2) + (c2 + d2), (a3 + b3) + (c3 + d3));
}

// ---------------- main GEMM: 64 rows x 128 cols, 256 thr, 2 blocks/SM ----------
__device__ __forceinline__ void loadA_cp(unsigned sA, const float* __restrict__ A,
                                         int rowbase, int tid, int n) {
#pragma unroll
    for (int i = 0; i < 8; i++) {
        int idx = tid + i * 256;          // 0..2047 float4 slots
        int r = idx >> 5;
        int grow = rowbase + r;
        int cr = (grow < n) ? grow : (n - 1);
        cp16(sA + idx * 16, A + cr * HD + (idx & 31) * 4);
    }
}

__device__ __forceinline__ void loadB_cp(unsigned sB, const float* __restrict__ B,
                                         int tid) {
#pragma unroll
    for (int i = 0; i < 16; i++) {
        int idx = tid + i * 256;          // 0..4095 float4 slots
        cp16(sB + idx * 16, B + idx * 4);
    }
}

__device__ __forceinline__ void gemm_compute(const float* As, const float* Bs,
                                             unsigned long long acc0[8],
                                             unsigned long long acc1[8],
                                             int warp, int lane) {
#pragma unroll 2
    for (int k0 = 0; k0 < HD; k0 += 4) {
        float4 avv[8];
#pragma unroll
        for (int r = 0; r < 8; r++)
            avv[r] = *(const float4*)&As[(warp * 8 + r) * HD + k0];
#pragma unroll
        for (int kk = 0; kk < 4; kk++) {
            const ulonglong2 bb =
                *(const ulonglong2*)&Bs[(k0 + kk) * HD + lane * 4];
#pragma unroll
            for (int r = 0; r < 8; r++) {
                float a = (&avv[r].x)[kk];
                unsigned long long a2 = pk2(a, a);
                acc0[r] = fma2(a2, bb.x, acc0[r]);
                acc1[r] = fma2(a2, bb.y, acc1[r]);
            }
        }
    }
}

// EPI: 0 = +bias, 1 = plain, 2 = +deg*cvec+bias, relu, 3 = +bias, LN, relu, (+res)
template <int EPI, bool TWOA>
__global__ void __launch_bounds__(256) gemm_k(
    const float* __restrict__ A0, const float* __restrict__ A1,
    const float* __restrict__ B0, const float* __restrict__ B1,
    const float* __restrict__ bias,
    const float* __restrict__ degf, const float* __restrict__ cvec,
    const float* __restrict__ lng, const float* __restrict__ lnb,
    int addres, float* __restrict__ Out, int n) {
    extern __shared__ float sm[];
    float* Bs = sm;                 // 128 x 128
    float* As = sm + 128 * HD;      // 64 x 128
    int tid = threadIdx.x;
    int rowbase = blockIdx.x * 64;
    unsigned sb = smem_u32(sm);
    unsigned sB = sb;
    unsigned sA = sb + 128 * HD * 4;

    loadB_cp(sB, B0, tid);
    loadA_cp(sA, A0, rowbase, tid, n);
    cp_commit_wait();
    __syncthreads();

    unsigned long long acc0[8], acc1[8];
#pragma unroll
    for (int r = 0; r < 8; r++) { acc0[r] = 0ULL; acc1[r] = 0ULL; }

    int warp = tid >> 5, lane = tid & 31;
    gemm_compute(As, Bs, acc0, acc1, warp, lane);
    if (TWOA) {
        __syncthreads();
        loadB_cp(sB, B1, tid);
        loadA_cp(sA, A1, rowbase, tid, n);
        cp_commit_wait();
        __syncthreads();
        gemm_compute(As, Bs, acc0, acc1, warp, lane);
    }

    int col = lane * 4;
    int rb = rowbase + warp * 8;

    // hoisted per-column vectors
    float4 bv = make_float4(0.f, 0.f, 0.f, 0.f);
    if (EPI == 0 || EPI == 2 || EPI == 3) bv = *(const float4*)&bias[col];
    float4 cv = make_float4(0.f, 0.f, 0.f, 0.f);
    if (EPI == 2) cv = *(const float4*)&cvec[col];
    float4 gv = make_float4(0.f, 0.f, 0.f, 0.f), lv = gv;
    if (EPI == 3) {
        gv = *(const float4*)&lng[col];
        lv = *(const float4*)&lnb[col];
    }

#pragma unroll
    for (int r = 0; r < 8; r++) {
        int grow = rb + r;
        float o0, o1, o2, o3;
        upk2(acc0[r], o0, o1);
        upk2(acc1[r], o2, o3);
        if (EPI == 0) {
            o0 += bv.x; o1 += bv.y; o2 += bv.z; o3 += bv.w;
        }
        if (EPI == 2) {
            float dg = degf[(grow < n) ? grow : 0];
            o0 = fmaxf(o0 + dg * cv.x + bv.x, 0.0f);
            o1 = fmaxf(o1 + dg * cv.y + bv.y, 0.0f);
            o2 = fmaxf(o2 + dg * cv.z + bv.z, 0.0f);
            o3 = fmaxf(o3 + dg * cv.w + bv.w, 0.0f);
        }
        if (EPI == 3) {
            o0 += bv.x; o1 += bv.y; o2 += bv.z; o3 += bv.w;
            float s = o0 + o1 + o2 + o3;
            float sq = o0 * o0 + o1 * o1 + o2 * o2 + o3 * o3;
#pragma unroll
            for (int off = 16; off; off >>= 1) {
                s += __shfl_xor_sync(0xffffffffu, s, off);
                sq += __shfl_xor_sync(0xffffffffu, sq, off);
            }
            float mu = s * (1.0f / HD);
            float var = sq * (1.0f / HD) - mu * mu;
            float rstd = rsqrtf(var + 1e-5f);
            o0 = fmaxf((o0 - mu) * rstd * gv.x + lv.x, 0.0f);
            o1 = fmaxf((o1 - mu) * rstd * gv.y + lv.y, 0.0f);
            o2 = fmaxf((o2 - mu) * rstd * gv.z + lv.z, 0.0f);
            o3 = fmaxf((o3 - mu) * rstd * gv.w + lv.w, 0.0f);
            if (addres && grow < n) {
                const float4 hv = *(const float4*)&Out[grow * HD + col];
                o0 += hv.x; o1 += hv.y; o2 += hv.z; o3 += hv.w;
            }
        }
        if (grow < n) {
            *(float4*)&Out[grow * HD + col] = make_float4(o0, o1, o2, o3);
        }
    }
}

// ---------------- readout ------------------------------------------------------
__global__ void pool_k(const float* __restrict__ h,
                       const int* __restrict__ batch,
                       float* __restrict__ pooled, float* __restrict__ cnt) {
    int nidx = blockIdx.x * 8 + (threadIdx.x >> 5);
    int lane = threadIdx.x & 31;
    if (nidx >= NN) return;
    int g = batch[nidx];
    float4 v = *(const float4*)&h[nidx * HD + lane * 4];
    float* p = &pooled[g * HD + lane * 4];
    atomicAdd(p + 0, v.x);
    atomicAdd(p + 1, v.y);
    atomicAdd(p + 2, v.z);
    atomicAdd(p + 3, v.w);
    if (lane == 0) atomicAdd(&cnt[g], 1.0f);
}

__global__ void readout_k(const float* __restrict__ pooled,
                          const float* __restrict__ cnt,
                          const float* __restrict__ w1, const float* __restrict__ b1,
                          const float* __restrict__ w2, const float* __restrict__ b2,
                          const float* __restrict__ w3, const float* __restrict__ b3,
                          float* __restrict__ out) {
    __shared__ float p[HD];
    __shared__ float o1s[HD];
    __shared__ float o2s[64];
    int g = blockIdx.x, c = threadIdx.x;
    float cc = fmaxf(cnt[g], 1.0f);
    p[c] = pooled[g * HD + c] / cc;
    __syncthreads();
    float acc = b1[c];
    for (int k = 0; k < HD; k++) acc += p[k] * w1[k * HD + c];
    o1s[c] = fmaxf(acc, 0.0f);
    __syncthreads();
    if (c < 64) {
        float a = b2[c];
        for (int k = 0; k < HD; k++) a += o1s[k] * w2[k * 64 + c];
        o2s[c] = fmaxf(a, 0.0f);
    }
    __syncthreads();
    if (c == 0) {
        float a = b3[0];
        for (int k = 0; k < 64; k++) a += o2s[k] * w3[k];
        out[g] = a;
    }
}

// ---------------- launch --------------------------------------------------------
extern "C" void kernel_launch(void* const* d_in, const int* in_sizes, int n_in,
                              void* d_out, int out_size) {
    const float* x       = (const float*)d_in[0];
    const int*   ei      = (const int*)d_in[1];
    const float* pos     = (const float*)d_in[3];
    const int*   batch   = (const int*)d_in[4];
    const float* enc_w   = (const float*)d_in[5];
    const float* enc_b   = (const float*)d_in[6];
    const float* msg_w1  = (const float*)d_in[9];
    const float* msg_b1  = (const float*)d_in[10];
    const float* msg_w2  = (const float*)d_in[11];
    const float* msg_b2  = (const float*)d_in[12];
    const float* upd_w1  = (const float*)d_in[13];
    const float* upd_b1  = (const float*)d_in[14];
    const float* upd_w2  = (const float*)d_in[15];
    const float* upd_b2  = (const float*)d_in[16];
    const float* ln_g    = (const float*)d_in[17];
    const float* ln_b    = (const float*)d_in[18];
    const float* mlp_w1  = (const float*)d_in[19];
    const float* mlp_b1  = (const float*)d_in[20];
    const float* mlp_w2  = (const float*)d_in[21];
    const float* mlp_b2  = (const float*)d_in[22];
    const float* mlp_w3  = (const float*)d_in[23];
    const float* mlp_b3  = (const float*)d_in[24];
    float*       out     = (float*)d_out;

    float *h, *P1, *P2, *Yagg, *T, *degf, *W2U, *cvec, *pooled, *cnt;
    int *rowptr, *cursor, *bsum;
    int2 *epack;
    cudaGetSymbolAddress((void**)&h, d_h);
    cudaGetSymbolAddress((void**)&P1, d_P1);
    cudaGetSymbolAddress((void**)&P2, d_P2);
    cudaGetSymbolAddress((void**)&Yagg, d_Yagg);
    cudaGetSymbolAddress((void**)&T, d_T);
    cudaGetSymbolAddress((void**)&degf, d_degf);
    cudaGetSymbolAddress((void**)&W2U, d_W2U);
    cudaGetSymbolAddress((void**)&cvec, d_cvec);
    cudaGetSymbolAddress((void**)&pooled, d_pooled);
    cudaGetSymbolAddress((void**)&cnt, d_cnt);
    cudaGetSymbolAddress((void**)&rowptr, d_rowptr);
    cudaGetSymbolAddress((void**)&cursor, d_cursor);
    cudaGetSymbolAddress((void**)&bsum, d_bsum);
    cudaGetSymbolAddress((void**)&epack, d_epack);

    const int SMEM = (128 * HD + 64 * HD) * 4;   // 96 KB
    cudaFuncSetAttribute(gemm_k<0, false>, cudaFuncAttributeMaxDynamicSharedMemorySize, SMEM);
    cudaFuncSetAttribute(gemm_k<1, false>, cudaFuncAttributeMaxDynamicSharedMemorySize, SMEM);
    cudaFuncSetAttribute(gemm_k<2, true>,  cudaFuncAttributeMaxDynamicSharedMemorySize, SMEM);
    cudaFuncSetAttribute(gemm_k<3, false>, cudaFuncAttributeMaxDynamicSharedMemorySize, SMEM);

    const int GB = (NN + 63) / 64;   // 782 blocks

    // ---- prep; launch #4 = layer-0 P1 GEMM so ncu captures it ----
    encoder_k<<<(NN + 15) / 16, 128>>>(x, enc_w, enc_b, h);               // 1
    zero_int<<<(NN + 255) / 256, 256>>>(cursor, NN);                      // 2
    count_k<<<(EE + 255) / 256, 256>>>(ei, cursor);                       // 3
    gemm_k<0, false><<<GB, 256, SMEM>>>(h, nullptr, msg_w1, nullptr,      // 4 (profiled)
                                        msg_b1, nullptr, nullptr,
                                        nullptr, nullptr, 0, P1, NN);
    scan_part<<<NB, 256>>>(cursor, rowptr, bsum);                         // 5
    scan_bsum<<<1, 256>>>(bsum);                                          // 6
    add_off<<<NB, 256>>>(rowptr, bsum, cursor);                           // 7
    degf_k<<<(NN + 255) / 256, 256>>>(rowptr, degf);                      // 8
    scatter_k<<<(EE + 255) / 256, 256>>>(ei, pos, cursor, epack);         // 9
    build_w2u<<<dim3(129, 4), 128>>>(msg_w2, msg_b2, upd_w1, W2U, cvec);  // 10
    zero_k<<<(NG * HD + 255) / 256, 256>>>(pooled, NG * HD);              // 11
    zero_k<<<1, 64>>>(cnt, NG);                                           // 12

    for (int l = 0; l < NLAY; l++) {
        const float* w1l = msg_w1 + l * 257 * HD;
        // P1 = h@W1a + b1 (layer 0 hoisted to launch #4) ; P2 = h@W1b
        if (l > 0) {
            gemm_k<0, false><<<GB, 256, SMEM>>>(h, nullptr, w1l, nullptr,
                                                msg_b1 + l * HD, nullptr, nullptr,
                                                nullptr, nullptr, 0, P1, NN);
        }
        gemm_k<1, false><<<GB, 256, SMEM>>>(h, nullptr, w1l + 128 * HD, nullptr,
                                            nullptr, nullptr, nullptr,
                                            nullptr, nullptr, 0, P2, NN);
        // CSR gather: Yagg[i] = sum_e relu(P1[i]+P2[src]+dist*w1c)
        aggregate_k<<<NN / 8, 256>>>(rowptr, epack, P1, P2,
                                     w1l + 256 * HD, Yagg);
        // T = relu(h@U1a + Yagg@W2U + deg*cvec + bu1)
        gemm_k<2, true><<<GB, 256, SMEM>>>(h, Yagg, upd_w1 + l * 256 * HD,
                                           W2U + l * HD * HD, upd_b1 + l * HD,
                                           degf, cvec + l * HD,
                                           nullptr, nullptr, 0, T, NN);
        // h = (l? h : 0) + relu(LN(T@U2 + bu2))
        gemm_k<3, false><<<GB, 256, SMEM>>>(T, nullptr, upd_w2 + l * HD * HD, nullptr,
                                            upd_b2 + l * HD, nullptr, nullptr,
                                            ln_g + l * HD, ln_b + l * HD,
                                            (l > 0) ? 1 : 0, h, NN);
    }

    pool_k<<<(NN + 7) / 8, 256>>>(h, batch, pooled, cnt);
    readout_k<<<NG, 128>>>(pooled, cnt, mlp_w1, mlp_b1, mlp_w2, mlp_b2,
                           mlp_w3, mlp_b3, out);
}

// round 11
// speedup vs baseline: 1.7783x; 1.0983x over previous
#include <cuda_runtime.h>
#include <cuda_bf16.h>

#define NN 50000
#define EE 500000
#define HD 128
#define NLAY 4
#define NG 64
#define NB 196  // (NN+255)/256 scan blocks

// ---------------- scratch (device globals) ------------------------------------
__device__ __align__(16) float d_h[NN * HD];
__device__ __align__(16) float d_P1[NN * HD];
__device__ __align__(16) float d_P2[NN * HD];
__device__ __align__(16) float d_Yagg[NN * HD];
__device__ __align__(16) float d_T[NN * HD];
__device__ __align__(16) float d_degf[NN];
__device__ __align__(16) float d_W2U[NLAY * HD * HD];
__device__ __align__(16) float d_cvec[NLAY * HD];
__device__ __align__(16) float d_pooled[NG * HD];
__device__ __align__(16) float d_cnt[NG];
// transposed + bf16-split message weights: 8 matrices (4 layers x {W1a,W1b}), [N=128][K=128]
__device__ __align__(16) __nv_bfloat16 d_wth[8 * HD * HD];
__device__ __align__(16) __nv_bfloat16 d_wtl[8 * HD * HD];
// CSR
__device__ __align__(16) int   d_rowptr[NN + 1];
__device__ __align__(16) int   d_cursor[NN];
__device__ __align__(16) int   d_bsum[256];
__device__ __align__(16) int2  d_epack[EE];   // (src, dist bits)

// ---------------- generic helpers ----------------------------------------------
__device__ __forceinline__ unsigned long long pk2(float lo, float hi) {
    unsigned long long r;
    asm("mov.b64 %0, {%1,%2};" : "=l"(r) : "f"(lo), "f"(hi));
    return r;
}
__device__ __forceinline__ void upk2(unsigned long long v, float& lo, float& hi) {
    asm("mov.b64 {%0,%1}, %2;" : "=f"(lo), "=f"(hi) : "l"(v));
}
__device__ __forceinline__ unsigned long long fma2(unsigned long long a,
                                                   unsigned long long b,
                                                   unsigned long long c) {
    unsigned long long d;
    asm("fma.rn.f32x2 %0, %1, %2, %3;" : "=l"(d) : "l"(a), "l"(b), "l"(c));
    return d;
}
__device__ __forceinline__ unsigned smem_u32(const void* p) {
    unsigned r;
    asm("{ .reg .u64 t; cvta.to.shared.u64 t, %1; cvt.u32.u64 %0, t; }"
        : "=r"(r) : "l"(p));
    return r;
}
__device__ __forceinline__ void cp16(unsigned saddr, const void* g) {
    asm volatile("cp.async.cg.shared.global [%0], [%1], 16;" :: "r"(saddr), "l"(g));
}
__device__ __forceinline__ void cp_commit_wait() {
    asm volatile("cp.async.commit_group;");
    asm volatile("cp.async.wait_group 0;");
}

// ---------------- mma.sync bf16 (sm_80-baseline PTX; runs on tensor pipe) ------
__device__ __forceinline__ void mma_bf16(float c[4], const unsigned a[4],
                                         unsigned b0, unsigned b1) {
    asm volatile(
        "mma.sync.aligned.m16n8k16.row.col.f32.bf16.bf16.f32 "
        "{%0,%1,%2,%3}, {%4,%5,%6,%7}, {%8,%9}, {%0,%1,%2,%3};"
        : "+f"(c[0]), "+f"(c[1]), "+f"(c[2]), "+f"(c[3])
        : "r"(a[0]), "r"(a[1]), "r"(a[2]), "r"(a[3]), "r"(b0), "r"(b1));
}

__device__ __forceinline__ void split2(float2 f, unsigned& hi, unsigned& lo) {
    __nv_bfloat16 hx = __float2bfloat16(f.x), hy = __float2bfloat16(f.y);
    __nv_bfloat16 lx = __float2bfloat16(f.x - __bfloat162float(hx));
    __nv_bfloat16 ly = __float2bfloat16(f.y - __bfloat162float(hy));
    hi = ((unsigned)__bfloat16_as_ushort(hy) << 16) | __bfloat16_as_ushort(hx);
    lo = ((unsigned)__bfloat16_as_ushort(ly) << 16) | __bfloat16_as_ushort(lx);
}

// ---------------- tensor-core fused P1/P2 kernel --------------------------------
// Block: 512 thr (16 warps), 128 rows. Warps 0-7 -> P1, 8-15 -> P2; warp = 16 rows.
// B tiles (weights, [n][k] bf16 hi/lo) in smem, padded stride 68 words (conflict-free).
#define BST 68                              // words per B row
#define BTILE (HD * BST * 4)                // 34816 B per matrix
#define SM_P12_TOTAL (4 * BTILE)            // 139264 B

__global__ void __launch_bounds__(512) p12_tc(
    const float* __restrict__ A,
    const __nv_bfloat16* __restrict__ WhA, const __nv_bfloat16* __restrict__ WlA,
    const __nv_bfloat16* __restrict__ WhB, const __nv_bfloat16* __restrict__ WlB,
    const float* __restrict__ bias,
    float* __restrict__ O1, float* __restrict__ O2) {
    extern __shared__ char smc[];
    unsigned sb = smem_u32(smc);
    int tid = threadIdx.x;
    int wid = tid >> 5, lane = tid & 31;
    int g = lane >> 2, tig = lane & 3;

    // load 4 weight matrices into padded smem via cp.async
    // 4 matrices x 128 rows x 16 chunks (16B each) = 8192 chunks total
    {
        const __nv_bfloat16* srcs[4] = {WhA, WlA, WhB, WlB};
#pragma unroll
        for (int i = 0; i < 16; i++) {
            int c = tid + i * 512;          // 0..8191 16B-chunks
            int m = c >> 11;                // matrix 0..3
            int c2 = c & 2047;
            int r = c2 >> 4;                // n row 0..127
            int kc = (c2 & 15) * 8;         // k start 0..120 (8 bf16 per 16B)
            cp16(sb + m * BTILE + (r * BST + (kc >> 1)) * 4, srcs[m] + r * HD + kc);
        }
    }
    cp_commit_wait();
    __syncthreads();

    int pr = wid >> 3;                      // 0 -> P1, 1 -> P2
    int rowbase = blockIdx.x * 128 + (wid & 7) * 16;
    int r0 = rowbase + g, r1 = rowbase + g + 8;
    int cr0 = (r0 < NN) ? r0 : (NN - 1);
    int cr1 = (r1 < NN) ? r1 : (NN - 1);
    const char* smBh = smc + pr * 2 * BTILE;
    const char* smBl = smBh + BTILE;

    float acc[16][4];
#pragma unroll
    for (int i = 0; i < 16; i++)
#pragma unroll
        for (int j = 0; j < 4; j++) acc[i][j] = 0.0f;

#pragma unroll
    for (int ks = 0; ks < 8; ks++) {
        int k0 = ks * 16;
        float2 f00 = *(const float2*)(A + cr0 * HD + k0 + tig * 2);
        float2 f10 = *(const float2*)(A + cr1 * HD + k0 + tig * 2);
        float2 f01 = *(const float2*)(A + cr0 * HD + k0 + tig * 2 + 8);
        float2 f11 = *(const float2*)(A + cr1 * HD + k0 + tig * 2 + 8);
        unsigned ahi[4], alo[4];
        split2(f00, ahi[0], alo[0]);
        split2(f10, ahi[1], alo[1]);
        split2(f01, ahi[2], alo[2]);
        split2(f11, ahi[3], alo[3]);
#pragma unroll
        for (int t = 0; t < 16; t++) {
            int n = t * 8 + g;
            int w0 = (n * BST + (k0 >> 1) + tig) * 4;
            unsigned bh0 = *(const unsigned*)(smBh + w0);
            unsigned bh1 = *(const unsigned*)(smBh + w0 + 16);
            unsigned bl0 = *(const unsigned*)(smBl + w0);
            unsigned bl1 = *(const unsigned*)(smBl + w0 + 16);
            mma_bf16(acc[t], ahi, bh0, bh1);
            mma_bf16(acc[t], ahi, bl0, bl1);
            mma_bf16(acc[t], alo, bh0, bh1);
        }
    }

    float* Op = pr ? O2 : O1;
#pragma unroll
    for (int t = 0; t < 16; t++) {
        int col = t * 8 + tig * 2;
        float2 v0 = make_float2(acc[t][0], acc[t][1]);
        float2 v1 = make_float2(acc[t][2], acc[t][3]);
        if (pr == 0) {
            float2 bv = *(const float2*)&bias[col];
            v0.x += bv.x; v0.y += bv.y;
            v1.x += bv.x; v1.y += bv.y;
        }
        if (r0 < NN) *(float2*)(Op + r0 * HD + col) = v0;
        if (r1 < NN) *(float2*)(Op + r1 * HD + col) = v1;
    }
}

// transpose + bf16-split the 8 message weight matrices -> Wt[n][k]
__global__ void tcw_k(const float* __restrict__ msg_w1,
                      __nv_bfloat16* __restrict__ wth,
                      __nv_bfloat16* __restrict__ wtl) {
    int n = blockIdx.x;         // 0..127 output row (N)
    int m = blockIdx.y;         // matrix id 0..7
    int k = threadIdx.x;        // 0..127
    int l = m >> 1, part = m & 1;
    const float* W = msg_w1 + l * 257 * HD + part * 128 * HD;
    float v = W[k * HD + n];
    __nv_bfloat16 h = __float2bfloat16(v);
    wth[m * HD * HD + n * HD + k] = h;
    wtl[m * HD * HD + n * HD + k] = __float2bfloat16(v - __bfloat162float(h));
}

// ---------------- tiny utility kernels ----------------------------------------
__global__ void zero_k(float* __restrict__ p, int n) {
    int i = blockIdx.x * blockDim.x + threadIdx.x;
    if (i < n) p[i] = 0.0f;
}
__global__ void zero_int(int* __restrict__ p, int n) {
    int i = blockIdx.x * blockDim.x + threadIdx.x;
    if (i < n) p[i] = 0;
}

// ---------------- CSR build ----------------------------------------------------
__global__ void count_k(const int* __restrict__ ei, int* __restrict__ deg) {
    int e = blockIdx.x * blockDim.x + threadIdx.x;
    if (e < EE) atomicAdd(&deg[ei[EE + e]], 1);
}

__global__ void scan_part(const int* __restrict__ deg, int* __restrict__ rowptr,
                          int* __restrict__ bsum) {
    __shared__ int s[256];
    int tid = threadIdx.x;
    int i = blockIdx.x * 256 + tid;
    int v = (i < NN) ? deg[i] : 0;
    s[tid] = v;
    __syncthreads();
#pragma unroll
    for (int off = 1; off < 256; off <<= 1) {
        int t = (tid >= off) ? s[tid - off] : 0;
        __syncthreads();
        s[tid] += t;
        __syncthreads();
    }
    if (i < NN) rowptr[i] = s[tid] - v;
    if (tid == 255) bsum[blockIdx.x] = s[255];
}

__global__ void scan_bsum(int* __restrict__ bsum) {
    __shared__ int s[256];
    int tid = threadIdx.x;
    int v = (tid < NB) ? bsum[tid] : 0;
    s[tid] = v;
    __syncthreads();
#pragma unroll
    for (int off = 1; off < 256; off <<= 1) {
        int t = (tid >= off) ? s[tid - off] : 0;
        __syncthreads();
        s[tid] += t;
        __syncthreads();
    }
    if (tid < NB) bsum[tid] = s[tid] - v;
}

__global__ void add_off(int* __restrict__ rowptr, const int* __restrict__ bsum,
                        int* __restrict__ cursor) {
    int i = blockIdx.x * 256 + threadIdx.x;
    if (i < NN) {
        int r = rowptr[i] + bsum[blockIdx.x];
        rowptr[i] = r;
        cursor[i] = r;
    }
    if (i == 0) rowptr[NN] = EE;
}

__global__ void degf_k(const int* __restrict__ rowptr, float* __restrict__ degf) {
    int i = blockIdx.x * blockDim.x + threadIdx.x;
    if (i < NN) degf[i] = (float)(rowptr[i + 1] - rowptr[i]);
}

__global__ void scatter_k(const int* __restrict__ ei,
                          const float* __restrict__ pos,
                          int* __restrict__ cursor,
                          int2* __restrict__ epack) {
    int e = blockIdx.x * blockDim.x + threadIdx.x;
    if (e >= EE) return;
    int s = ei[e];
    int t = ei[EE + e];
    float dx = pos[t * 3 + 0] - pos[s * 3 + 0];
    float dy = pos[t * 3 + 1] - pos[s * 3 + 1];
    float dz = pos[t * 3 + 2] - pos[s * 3 + 2];
    float dd = sqrtf(dx * dx + dy * dy + dz * dz);
    int p = atomicAdd(&cursor[t], 1);
    epack[p] = make_int2(s, __float_as_int(dd));
}

// ---------------- encoder: h = x @ enc_w + enc_b (K=15) -----------------------
__global__ void encoder_k(const float* __restrict__ x,
                          const float* __restrict__ w,
                          const float* __restrict__ b,
                          float* __restrict__ h) {
    __shared__ float ws[15 * HD];
    __shared__ float xs[16 * 15];
    __shared__ float bs[HD];
    int c = threadIdx.x;
    for (int i = c; i < 15 * HD; i += HD) ws[i] = w[i];
    bs[c] = b[c];
    int n0 = blockIdx.x * 16;
    for (int i = c; i < 16 * 15; i += HD) {
        int nn = i / 15, kk = i % 15;
        int g = n0 + nn;
        xs[i] = (g < NN) ? x[g * 15 + kk] : 0.0f;
    }
    __syncthreads();
    for (int r = 0; r < 16; r++) {
        int g = n0 + r;
        if (g >= NN) break;
        float acc = bs[c];
#pragma unroll
        for (int k = 0; k < 15; k++) acc += xs[r * 15 + k] * ws[k * HD + c];
        h[g * HD + c] = acc;
    }
}

// W2U[l] = msg_w2[l] @ U1b[l];  cvec[l] = msg_b2[l] @ U1b[l]
__global__ void build_w2u(const float* __restrict__ msg_w2,
                          const float* __restrict__ msg_b2,
                          const float* __restrict__ upd_w1,
                          float* __restrict__ W2U,
                          float* __restrict__ cvec) {
    int l = blockIdx.y, k = blockIdx.x, c = threadIdx.x;
    const float* u1b = upd_w1 + l * 256 * HD + 128 * HD;
    if (k < HD) {
        const float* wrow = msg_w2 + (l * HD + k) * HD;
        float acc = 0.0f;
        for (int j = 0; j < HD; j++) acc += wrow[j] * u1b[j * HD + c];
        W2U[(l * HD + k) * HD + c] = acc;
    } else {
        const float* brow = msg_b2 + l * HD;
        float acc = 0.0f;
        for (int j = 0; j < HD; j++) acc += brow[j] * u1b[j * HD + c];
        cvec[l * HD + c] = acc;
    }
}

// ---------------- CSR gather aggregation (packed edges, unroll 4) --------------
__global__ void __launch_bounds__(256) aggregate_k(
    const int* __restrict__ rowptr,
    const int2* __restrict__ epack,
    const float* __restrict__ P1,
    const float* __restrict__ P2,
    const float* __restrict__ w1c,
    float* __restrict__ Yagg) {
    int node = blockIdx.x * 8 + (threadIdx.x >> 5);
    int lane = threadIdx.x & 31;
    int c4 = lane * 4;
    const float4 cw = *(const float4*)&w1c[c4];
    const float4 p1 = *(const float4*)&P1[node * HD + c4];
    float a0 = 0.f, a1 = 0.f, a2 = 0.f, a3 = 0.f;
    float b0 = 0.f, b1 = 0.f, b2 = 0.f, b3 = 0.f;
    float c0 = 0.f, c1 = 0.f, c2 = 0.f, c3 = 0.f;
    float d0 = 0.f, d1 = 0.f, d2 = 0.f, d3 = 0.f;
    int beg = rowptr[node], end = rowptr[node + 1];
    int e = beg;
    for (; e + 3 < end; e += 4) {
        int2 q0 = epack[e], q1 = epack[e + 1], q2 = epack[e + 2], q3 = epack[e + 3];
        const float4 v0 = *(const float4*)&P2[q0.x * HD + c4];
        const float4 v1 = *(const float4*)&P2[q1.x * HD + c4];
        const float4 v2 = *(const float4*)&P2[q2.x * HD + c4];
        const float4 v3 = *(const float4*)&P2[q3.x * HD + c4];
        float dd0 = __int_as_float(q0.y), dd1 = __int_as_float(q1.y);
        float dd2 = __int_as_float(q2.y), dd3 = __int_as_float(q3.y);
        a0 += fmaxf(p1.x + v0.x + dd0 * cw.x, 0.0f);
        a1 += fmaxf(p1.y + v0.y + dd0 * cw.y, 0.0f);
        a2 += fmaxf(p1.z + v0.z + dd0 * cw.z, 0.0f);
        a3 += fmaxf(p1.w + v0.w + dd0 * cw.w, 0.0f);
        b0 += fmaxf(p1.x + v1.x + dd1 * cw.x, 0.0f);
        b1 += fmaxf(p1.y + v1.y + dd1 * cw.y, 0.0f);
        b2 += fmaxf(p1.z + v1.z + dd1 * cw.z, 0.0f);
        b3 += fmaxf(p1.w + v1.w + dd1 * cw.w, 0.0f);
        c0 += fmaxf(p1.x + v2.x + dd2 * cw.x, 0.0f);
        c1 += fmaxf(p1.y + v2.y + dd2 * cw.y, 0.0f);
        c2 += fmaxf(p1.z + v2.z + dd2 * cw.z, 0.0f);
        c3 += fmaxf(p1.w + v2.w + dd2 * cw.w, 0.0f);
        d0 += fmaxf(p1.x + v3.x + dd3 * cw.x, 0.0f);
        d1 += fmaxf(p1.y + v3.y + dd3 * cw.y, 0.0f);
        d2 += fmaxf(p1.z + v3.z + dd3 * cw.z, 0.0f);
        d3 += fmaxf(p1.w + v3.w + dd3 * cw.w, 0.0f);
    }
    for (; e < end; e++) {
        int2 q0 = epack[e];
        const float4 v0 = *(const float4*)&P2[q0.x * HD + c4];
        float dd0 = __int_as_float(q0.y);
        a0 += fmaxf(p1.x + v0.x + dd0 * cw.x, 0.0f);
        a1 += fmaxf(p1.y + v0.y + dd0 * cw.y, 0.0f);
        a2 += fmaxf(p1.z + v0.z + dd0 * cw.z, 0.0f);
        a3 += fmaxf(p1.w + v0.w + dd0 * cw.w, 0.0f);
    }
    *(float4*)&Yagg[node * HD + c4] = make_float4(
        (a0 + b0) + (c0 + d0), (a1 + b1) + (c1 + d1),
        (a2 + b2) + (c2 + d2), (a3 + b3) + (c3 + d3));
}

// ---------------- FFMA GEMM (EPI 2/3): 64x128 tile, 256 thr, 2 blocks/SM -------
__device__ __forceinline__ void loadA_cp(unsigned sA, const float* __restrict__ A,
                                         int rowbase, int tid, int n) {
#pragma unroll
    for (int i = 0; i < 8; i++) {
        int idx = tid + i * 256;
        int r = idx >> 5;
        int grow = rowbase + r;
        int cr = (grow < n) ? grow : (n - 1);
        cp16(sA + idx * 16, A + cr * HD + (idx & 31) * 4);
    }
}

__device__ __forceinline__ void loadB_cp(unsigned sB, const float* __restrict__ B,
                                         int tid) {
#pragma unroll
    for (int i = 0; i < 16; i++) {
        int idx = tid + i * 256;
        cp16(sB + idx * 16, B + idx * 4);
    }
}

__device__ __forceinline__ void gemm_compute(const float* As, const float* Bs,
                                             unsigned long long acc0[8],
                                             unsigned long long acc1[8],
                                             int warp, int lane) {
#pragma unroll 2
    for (int k0 = 0; k0 < HD; k0 += 4) {
        float4 avv[8];
#pragma unroll
        for (int r = 0; r < 8; r++)
            avv[r] = *(const float4*)&As[(warp * 8 + r) * HD + k0];
#pragma unroll
        for (int kk = 0; kk < 4; kk++) {
            const ulonglong2 bb =
                *(const ulonglong2*)&Bs[(k0 + kk) * HD + lane * 4];
#pragma unroll
            for (int r = 0; r < 8; r++) {
                float a = (&avv[r].x)[kk];
                unsigned long long a2 = pk2(a, a);
                acc0[r] = fma2(a2, bb.x, acc0[r]);
                acc1[r] = fma2(a2, bb.y, acc1[r]);
            }
        }
    }
}

// EPI: 2 = +deg*cvec+bias, relu (TWOA)   3 = +bias, LN, relu, (+res)
template <int EPI, bool TWOA>
__global__ void __launch_bounds__(256) gemm_k(
    const float* __restrict__ A0, const float* __restrict__ A1,
    const float* __restrict__ B0, const float* __restrict__ B1,
    const float* __restrict__ bias,
    const float* __restrict__ degf, const float* __restrict__ cvec,
    const float* __restrict__ lng, const float* __restrict__ lnb,
    int addres, float* __restrict__ Out, int n) {
    extern __shared__ float sm[];
    float* Bs = sm;
    float* As = sm + 128 * HD;
    int tid = threadIdx.x;
    int rowbase = blockIdx.x * 64;
    unsigned sb = smem_u32(sm);
    unsigned sB = sb;
    unsigned sA = sb + 128 * HD * 4;

    loadB_cp(sB, B0, tid);
    loadA_cp(sA, A0, rowbase, tid, n);
    cp_commit_wait();
    __syncthreads();

    unsigned long long acc0[8], acc1[8];
#pragma unroll
    for (int r = 0; r < 8; r++) { acc0[r] = 0ULL; acc1[r] = 0ULL; }

    int warp = tid >> 5, lane = tid & 31;
    gemm_compute(As, Bs, acc0, acc1, warp, lane);
    if (TWOA) {
        __syncthreads();
        loadB_cp(sB, B1, tid);
        loadA_cp(sA, A1, rowbase, tid, n);
        cp_commit_wait();
        __syncthreads();
        gemm_compute(As, Bs, acc0, acc1, warp, lane);
    }

    int col = lane * 4;
    int rb = rowbase + warp * 8;
    float4 bv = *(const float4*)&bias[col];
    float4 cv = make_float4(0.f, 0.f, 0.f, 0.f);
    if (EPI == 2) cv = *(const float4*)&cvec[col];
    float4 gv = make_float4(0.f, 0.f, 0.f, 0.f), lv = gv;
    if (EPI == 3) {
        gv = *(const float4*)&lng[col];
        lv = *(const float4*)&lnb[col];
    }

#pragma unroll
    for (int r = 0; r < 8; r++) {
        int grow = rb + r;
        float o0, o1, o2, o3;
        upk2(acc0[r], o0, o1);
        upk2(acc1[r], o2, o3);
        if (EPI == 2) {
            float dg = degf[(grow < n) ? grow : 0];
            o0 = fmaxf(o0 + dg * cv.x + bv.x, 0.0f);
            o1 = fmaxf(o1 + dg * cv.y + bv.y, 0.0f);
            o2 = fmaxf(o2 + dg * cv.z + bv.z, 0.0f);
            o3 = fmaxf(o3 + dg * cv.w + bv.w, 0.0f);
        }
        if (EPI == 3) {
            o0 += bv.x; o1 += bv.y; o2 += bv.z; o3 += bv.w;
            float s = o0 + o1 + o2 + o3;
            float sq = o0 * o0 + o1 * o1 + o2 * o2 + o3 * o3;
#pragma unroll
            for (int off = 16; off; off >>= 1) {
                s += __shfl_xor_sync(0xffffffffu, s, off);
                sq += __shfl_xor_sync(0xffffffffu, sq, off);
            }
            float mu = s * (1.0f / HD);
            float var = sq * (1.0f / HD) - mu * mu;
            float rstd = rsqrtf(var + 1e-5f);
            o0 = fmaxf((o0 - mu) * rstd * gv.x + lv.x, 0.0f);
            o1 = fmaxf((o1 - mu) * rstd * gv.y + lv.y, 0.0f);
            o2 = fmaxf((o2 - mu) * rstd * gv.z + lv.z, 0.0f);
            o3 = fmaxf((o3 - mu) * rstd * gv.w + lv.w, 0.0f);
            if (addres && grow < n) {
                const float4 hv = *(const float4*)&Out[grow * HD + col];
                o0 += hv.x; o1 += hv.y; o2 += hv.z; o3 += hv.w;
            }
        }
        if (grow < n) {
            *(float4*)&Out[grow * HD + col] = make_float4(o0, o1, o2, o3);
        }
    }
}

// ---------------- readout ------------------------------------------------------
__global__ void pool_k(const float* __restrict__ h,
                       const int* __restrict__ batch,
                       float* __restrict__ pooled, float* __restrict__ cnt) {
    int nidx = blockIdx.x * 8 + (threadIdx.x >> 5);
    int lane = threadIdx.x & 31;
    if (nidx >= NN) return;
    int g = batch[nidx];
    float4 v = *(const float4*)&h[nidx * HD + lane * 4];
    float* p = &pooled[g * HD + lane * 4];
    atomicAdd(p + 0, v.x);
    atomicAdd(p + 1, v.y);
    atomicAdd(p + 2, v.z);
    atomicAdd(p + 3, v.w);
    if (lane == 0) atomicAdd(&cnt[g], 1.0f);
}

__global__ void readout_k(const float* __restrict__ pooled,
                          const float* __restrict__ cnt,
                          const float* __restrict__ w1, const float* __restrict__ b1,
                          const float* __restrict__ w2, const float* __restrict__ b2,
                          const float* __restrict__ w3, const float* __restrict__ b3,
                          float* __restrict__ out) {
    __shared__ float p[HD];
    __shared__ float o1s[HD];
    __shared__ float o2s[64];
    int g = blockIdx.x, c = threadIdx.x;
    float cc = fmaxf(cnt[g], 1.0f);
    p[c] = pooled[g * HD + c] / cc;
    __syncthreads();
    float acc = b1[c];
    for (int k = 0; k < HD; k++) acc += p[k] * w1[k * HD + c];
    o1s[c] = fmaxf(acc, 0.0f);
    __syncthreads();
    if (c < 64) {
        float a = b2[c];
        for (int k = 0; k < HD; k++) a += o1s[k] * w2[k * 64 + c];
        o2s[c] = fmaxf(a, 0.0f);
    }
    __syncthreads();
    if (c == 0) {
        float a = b3[0];
        for (int k = 0; k < 64; k++) a += o2s[k] * w3[k];
        out[g] = a;
    }
}

// ---------------- launch --------------------------------------------------------
extern "C" void kernel_launch(void* const* d_in, const int* in_sizes, int n_in,
                              void* d_out, int out_size) {
    const float* x       = (const float*)d_in[0];
    const int*   ei      = (const int*)d_in[1];
    const float* pos     = (const float*)d_in[3];
    const int*   batch   = (const int*)d_in[4];
    const float* enc_w   = (const float*)d_in[5];
    const float* enc_b   = (const float*)d_in[6];
    const float* msg_w1  = (const float*)d_in[9];
    const float* msg_b1  = (const float*)d_in[10];
    const float* msg_w2  = (const float*)d_in[11];
    const float* msg_b2  = (const float*)d_in[12];
    const float* upd_w1  = (const float*)d_in[13];
    const float* upd_b1  = (const float*)d_in[14];
    const float* upd_w2  = (const float*)d_in[15];
    const float* upd_b2  = (const float*)d_in[16];
    const float* ln_g    = (const float*)d_in[17];
    const float* ln_b    = (const float*)d_in[18];
    const float* mlp_w1  = (const float*)d_in[19];
    const float* mlp_b1  = (const float*)d_in[20];
    const float* mlp_w2  = (const float*)d_in[21];
    const float* mlp_b2  = (const float*)d_in[22];
    const float* mlp_w3  = (const float*)d_in[23];
    const float* mlp_b3  = (const float*)d_in[24];
    float*       out     = (float*)d_out;

    float *h, *P1, *P2, *Yagg, *T, *degf, *W2U, *cvec, *pooled, *cnt;
    int *rowptr, *cursor, *bsum;
    int2 *epack;
    __nv_bfloat16 *wth, *wtl;
    cudaGetSymbolAddress((void**)&h, d_h);
    cudaGetSymbolAddress((void**)&P1, d_P1);
    cudaGetSymbolAddress((void**)&P2, d_P2);
    cudaGetSymbolAddress((void**)&Yagg, d_Yagg);
    cudaGetSymbolAddress((void**)&T, d_T);
    cudaGetSymbolAddress((void**)&degf, d_degf);
    cudaGetSymbolAddress((void**)&W2U, d_W2U);
    cudaGetSymbolAddress((void**)&cvec, d_cvec);
    cudaGetSymbolAddress((void**)&pooled, d_pooled);
    cudaGetSymbolAddress((void**)&cnt, d_cnt);
    cudaGetSymbolAddress((void**)&rowptr, d_rowptr);
    cudaGetSymbolAddress((void**)&cursor, d_cursor);
    cudaGetSymbolAddress((void**)&bsum, d_bsum);
    cudaGetSymbolAddress((void**)&epack, d_epack);
    cudaGetSymbolAddress((void**)&wth, d_wth);
    cudaGetSymbolAddress((void**)&wtl, d_wtl);

    const int SMEM = (128 * HD + 64 * HD) * 4;   // 96 KB
    cudaFuncSetAttribute(gemm_k<2, true>,  cudaFuncAttributeMaxDynamicSharedMemorySize, SMEM);
    cudaFuncSetAttribute(gemm_k<3, false>, cudaFuncAttributeMaxDynamicSharedMemorySize, SMEM);
    cudaFuncSetAttribute(p12_tc, cudaFuncAttributeMaxDynamicSharedMemorySize, SM_P12_TOTAL);

    const int GB  = (NN + 63) / 64;     // 782 FFMA gemm blocks
    const int GTB = (NN + 127) / 128;   // 391 tensor gemm blocks

    // ---- prep; launch #4 = layer-0 tensor P12 so ncu captures it ----
    encoder_k<<<(NN + 15) / 16, 128>>>(x, enc_w, enc_b, h);               // 1
    tcw_k<<<dim3(128, 8), 128>>>(msg_w1, wth, wtl);                       // 2
    zero_int<<<(NN + 255) / 256, 256>>>(cursor, NN);                      // 3
    p12_tc<<<GTB, 512, SM_P12_TOTAL>>>(h,                                  // 4 (profiled)
        wth + 0 * HD * HD, wtl + 0 * HD * HD,
        wth + 1 * HD * HD, wtl + 1 * HD * HD,
        msg_b1, P1, P2);
    count_k<<<(EE + 255) / 256, 256>>>(ei, cursor);                       // 5
    scan_part<<<NB, 256>>>(cursor, rowptr, bsum);                         // 6
    scan_bsum<<<1, 256>>>(bsum);                                          // 7
    add_off<<<NB, 256>>>(rowptr, bsum, cursor);                           // 8
    degf_k<<<(NN + 255) / 256, 256>>>(rowptr, degf);                      // 9
    scatter_k<<<(EE + 255) / 256, 256>>>(ei, pos, cursor, epack);         // 10
    build_w2u<<<dim3(129, 4), 128>>>(msg_w2, msg_b2, upd_w1, W2U, cvec);  // 11
    zero_k<<<(NG * HD + 255) / 256, 256>>>(pooled, NG * HD);              // 12
    zero_k<<<1, 64>>>(cnt, NG);                                           // 13

    for (int l = 0; l < NLAY; l++) {
        const float* w1l = msg_w1 + l * 257 * HD;
        if (l > 0) {
            p12_tc<<<GTB, 512, SM_P12_TOTAL>>>(h,
                wth + (2 * l + 0) * HD * HD, wtl + (2 * l + 0) * HD * HD,
                wth + (2 * l + 1) * HD * HD, wtl + (2 * l + 1) * HD * HD,
                msg_b1 + l * HD, P1, P2);
        }
        // CSR gather: Yagg[i] = sum_e relu(P1[i]+P2[src]+dist*w1c)
        aggregate_k<<<NN / 8, 256>>>(rowptr, epack, P1, P2,
                                     w1l + 256 * HD, Yagg);
        // T = relu(h@U1a + Yagg@W2U + deg*cvec + bu1)
        gemm_k<2, true><<<GB, 256, SMEM>>>(h, Yagg, upd_w1 + l * 256 * HD,
                                           W2U + l * HD * HD, upd_b1 + l * HD,
                                           degf, cvec + l * HD,
                                           nullptr, nullptr, 0, T, NN);
        // h = (l? h : 0) + relu(LN(T@U2 + bu2))
        gemm_k<3, false><<<GB, 256, SMEM>>>(T, nullptr, upd_w2 + l * HD * HD, nullptr,
                                            upd_b2 + l * HD, nullptr, nullptr,
                                            ln_g + l * HD, ln_b + l * HD,
                                            (l > 0) ? 1 : 0, h, NN);
    }

    pool_k<<<(NN + 7) / 8, 256>>>(h, batch, pooled, cnt);
    readout_k<<<NG, 128>>>(pooled, cnt, mlp_w1, mlp_b1, mlp_w2, mlp_b2,
                           mlp_w3, mlp_b3, out);
}

// round 12
// speedup vs baseline: 2.0396x; 1.1469x over previous
#include <cuda_runtime.h>
#include <cuda_bf16.h>

#define NN 50000
#define EE 500000
#define HD 128
#define NLAY 4
#define NG 64
#define NB 196  // (NN+255)/256 scan blocks

// interleaved split-weight matrices: 20 x [128 n][128 words]
//   word[kw*2]   = bf16x2 hi for k = 2kw, 2kw+1
//   word[kw*2+1] = bf16x2 lo
// idx 0..7  = msg W1a/W1b (2l+part) ; 8..11 = U1a[l] ; 12..15 = W2U[l] ; 16..19 = U2[l]
__device__ __align__(16) unsigned d_wi[20 * 16384];

// ---------------- scratch ------------------------------------------------------
__device__ __align__(16) float d_h[NN * HD];
__device__ __align__(16) float d_P1[NN * HD];
__device__ __align__(16) float d_P2[NN * HD];
__device__ __align__(16) float d_Yagg[NN * HD];
__device__ __align__(16) float d_T[NN * HD];
__device__ __align__(16) float d_degf[NN];
__device__ __align__(16) float d_W2U[NLAY * HD * HD];
__device__ __align__(16) float d_cvec[NLAY * HD];
__device__ __align__(16) float d_pooled[NG * HD];
__device__ __align__(16) float d_cnt[NG];
__device__ __align__(16) int   d_rowptr[NN + 1];
__device__ __align__(16) int   d_cursor[NN];
__device__ __align__(16) int   d_bsum[256];
__device__ __align__(16) int2  d_epack[EE];

// ---------------- helpers -------------------------------------------------------
__device__ __forceinline__ unsigned smem_u32(const void* p) {
    unsigned r;
    asm("{ .reg .u64 t; cvta.to.shared.u64 t, %1; cvt.u32.u64 %0, t; }"
        : "=r"(r) : "l"(p));
    return r;
}
__device__ __forceinline__ void cp16(unsigned saddr, const void* g) {
    asm volatile("cp.async.cg.shared.global [%0], [%1], 16;" :: "r"(saddr), "l"(g));
}
__device__ __forceinline__ void cp_commit_wait() {
    asm volatile("cp.async.commit_group;");
    asm volatile("cp.async.wait_group 0;");
}

__device__ __forceinline__ void mma_bf16(float c[4], const unsigned a[4],
                                         unsigned b0, unsigned b1) {
    asm volatile(
        "mma.sync.aligned.m16n8k16.row.col.f32.bf16.bf16.f32 "
        "{%0,%1,%2,%3}, {%4,%5,%6,%7}, {%8,%9}, {%0,%1,%2,%3};"
        : "+f"(c[0]), "+f"(c[1]), "+f"(c[2]), "+f"(c[3])
        : "r"(a[0]), "r"(a[1]), "r"(a[2]), "r"(a[3]), "r"(b0), "r"(b1));
}

__device__ __forceinline__ void split2(float2 f, unsigned& hi, unsigned& lo) {
    __nv_bfloat16 hx = __float2bfloat16(f.x), hy = __float2bfloat16(f.y);
    __nv_bfloat16 lx = __float2bfloat16(f.x - __bfloat162float(hx));
    __nv_bfloat16 ly = __float2bfloat16(f.y - __bfloat162float(hy));
    hi = ((unsigned)__bfloat16_as_ushort(hy) << 16) | __bfloat16_as_ushort(hx);
    lo = ((unsigned)__bfloat16_as_ushort(ly) << 16) | __bfloat16_as_ushort(lx);
}

// ---------------- HMMA building blocks ------------------------------------------
// smem B tile: 128 n rows x 136 words (hi/lo interleaved), 69632 B per matrix.
#define BROW 136
#define BTILE 69632

// stage nmats interleaved matrices from d_wi into smem (padded rows)
__device__ __forceinline__ void stageB(unsigned sb, const unsigned* __restrict__ wi,
                                       int nmats, int tid, int nthr) {
    int total = nmats * 4096;            // 16B-chunks (4 words each)
    for (int c = tid; c < total; c += nthr) {
        int p = c >> 12;
        int c2 = c & 4095;
        int n = c2 >> 5;
        int c4 = c2 & 31;
        cp16(sb + (unsigned)(p * BTILE) + (unsigned)((n * BROW + c4 * 4) * 4),
             wi + p * 16384 + n * 128 + c4 * 4);
    }
}

// load + split A fragments for one k0 step (rows cr0, cr1)
__device__ __forceinline__ void loadA_frag(const float* __restrict__ A,
                                           int cr0, int cr1, int k0, int tig,
                                           unsigned ahi[4], unsigned alo[4]) {
    float2 f00 = *(const float2*)(A + cr0 * HD + k0 + tig * 2);
    float2 f10 = *(const float2*)(A + cr1 * HD + k0 + tig * 2);
    float2 f01 = *(const float2*)(A + cr0 * HD + k0 + tig * 2 + 8);
    float2 f11 = *(const float2*)(A + cr1 * HD + k0 + tig * 2 + 8);
    split2(f00, ahi[0], alo[0]);
    split2(f10, ahi[1], alo[1]);
    split2(f01, ahi[2], alo[2]);
    split2(f11, ahi[3], alo[3]);
}

// 3-term split mma across 16 n-tiles for one k0 step
__device__ __forceinline__ void mma3_tiles(float acc[16][4], const char* __restrict__ smB,
                                           int k0, int g, int tig,
                                           const unsigned ahi[4], const unsigned alo[4]) {
    int kwofs = ((k0 >> 1) + tig) * 2;
#pragma unroll
    for (int t = 0; t < 16; t++) {
        int n = t * 8 + g;
        const char* base = smB + (n * BROW + kwofs) * 4;
        unsigned long long q0 = *(const unsigned long long*)(base);
        unsigned long long q1 = *(const unsigned long long*)(base + 32);
        unsigned bh0 = (unsigned)q0, bl0 = (unsigned)(q0 >> 32);
        unsigned bh1 = (unsigned)q1, bl1 = (unsigned)(q1 >> 32);
        mma_bf16(acc[t], ahi, bh0, bh1);
        mma_bf16(acc[t], ahi, bl0, bl1);
        mma_bf16(acc[t], alo, bh0, bh1);
    }
}

// ---------------- p12: fused P1/P2 message GEMM ---------------------------------
// 512 thr, 16 warps; warps 0-7 -> P1 (W1a), 8-15 -> P2 (W1b); 128 rows/block.
__global__ void __launch_bounds__(512) p12_tc(
    const float* __restrict__ A,
    const unsigned* __restrict__ wiA, const unsigned* __restrict__ wiB,
    const float* __restrict__ bias,
    float* __restrict__ O1, float* __restrict__ O2) {
    extern __shared__ char smc[];
    unsigned sb = smem_u32(smc);
    int tid = threadIdx.x;
    int wid = tid >> 5, lane = tid & 31;
    int g = lane >> 2, tig = lane & 3;

    // matrix 0 = W1a, matrix 1 = W1b (wiA and wiB are adjacent: wiB = wiA+16384)
    stageB(sb, wiA, 2, tid, 512);
    cp_commit_wait();
    __syncthreads();

    int pr = wid >> 3;
    int rowbase = blockIdx.x * 128 + (wid & 7) * 16;
    int r0 = rowbase + g, r1 = rowbase + g + 8;
    int cr0 = (r0 < NN) ? r0 : (NN - 1);
    int cr1 = (r1 < NN) ? r1 : (NN - 1);
    const char* smB = smc + pr * BTILE;
    (void)wiB;

    float acc[16][4];
#pragma unroll
    for (int i = 0; i < 16; i++)
#pragma unroll
        for (int j = 0; j < 4; j++) acc[i][j] = 0.0f;

#pragma unroll
    for (int ks = 0; ks < 8; ks++) {
        int k0 = ks * 16;
        unsigned ahi[4], alo[4];
        loadA_frag(A, cr0, cr1, k0, tig, ahi, alo);
        mma3_tiles(acc, smB, k0, g, tig, ahi, alo);
    }

    float* Op = pr ? O2 : O1;
#pragma unroll
    for (int t = 0; t < 16; t++) {
        int col = t * 8 + tig * 2;
        float2 v0 = make_float2(acc[t][0], acc[t][1]);
        float2 v1 = make_float2(acc[t][2], acc[t][3]);
        if (pr == 0) {
            float2 bv = *(const float2*)&bias[col];
            v0.x += bv.x; v0.y += bv.y;
            v1.x += bv.x; v1.y += bv.y;
        }
        if (r0 < NN) *(float2*)(Op + r0 * HD + col) = v0;
        if (r1 < NN) *(float2*)(Op + r1 * HD + col) = v1;
    }
}

// ---------------- upd2: T = relu(h@U1a + Yagg@W2U + deg*cvec + bias) ------------
// 512 thr, 16 warps x 16 rows = 256 rows/block; both products into one accumulator.
__global__ void __launch_bounds__(512) upd2_tc(
    const float* __restrict__ A0, const float* __restrict__ A1,
    const unsigned* __restrict__ wi0, const unsigned* __restrict__ wi1,
    const float* __restrict__ bias, const float* __restrict__ degf,
    const float* __restrict__ cvec, float* __restrict__ Out) {
    extern __shared__ char smc[];
    unsigned sb = smem_u32(smc);
    int tid = threadIdx.x;
    int wid = tid >> 5, lane = tid & 31;
    int g = lane >> 2, tig = lane & 3;

    stageB(sb, wi0, 1, tid, 512);
    stageB(sb + BTILE, wi1, 1, tid, 512);
    cp_commit_wait();
    __syncthreads();

    int rowbase = blockIdx.x * 256 + wid * 16;
    int r0 = rowbase + g, r1 = rowbase + g + 8;
    int cr0 = (r0 < NN) ? r0 : (NN - 1);
    int cr1 = (r1 < NN) ? r1 : (NN - 1);

    float acc[16][4];
#pragma unroll
    for (int i = 0; i < 16; i++)
#pragma unroll
        for (int j = 0; j < 4; j++) acc[i][j] = 0.0f;

#pragma unroll
    for (int ks = 0; ks < 8; ks++) {
        int k0 = ks * 16;
        unsigned ahi[4], alo[4];
        loadA_frag(A0, cr0, cr1, k0, tig, ahi, alo);
        mma3_tiles(acc, smc, k0, g, tig, ahi, alo);
        loadA_frag(A1, cr0, cr1, k0, tig, ahi, alo);
        mma3_tiles(acc, smc + BTILE, k0, g, tig, ahi, alo);
    }

    float dg0 = degf[cr0], dg1 = degf[cr1];
#pragma unroll
    for (int t = 0; t < 16; t++) {
        int col = t * 8 + tig * 2;
        float2 bv = *(const float2*)&bias[col];
        float2 cv = *(const float2*)&cvec[col];
        float2 v0, v1;
        v0.x = fmaxf(acc[t][0] + dg0 * cv.x + bv.x, 0.0f);
        v0.y = fmaxf(acc[t][1] + dg0 * cv.y + bv.y, 0.0f);
        v1.x = fmaxf(acc[t][2] + dg1 * cv.x + bv.x, 0.0f);
        v1.y = fmaxf(acc[t][3] + dg1 * cv.y + bv.y, 0.0f);
        if (r0 < NN) *(float2*)(Out + r0 * HD + col) = v0;
        if (r1 < NN) *(float2*)(Out + r1 * HD + col) = v1;
    }
}

// ---------------- upd3: h = (res? h:0) + relu(LN(T@U2 + bias)) ------------------
// 256 thr, 8 warps x 16 rows = 128 rows/block; 2 blocks/SM (69.6 KB smem).
__global__ void __launch_bounds__(256) upd3_tc(
    const float* __restrict__ A,
    const unsigned* __restrict__ wiU,
    const float* __restrict__ bias,
    const float* __restrict__ lng, const float* __restrict__ lnb,
    int addres, float* __restrict__ Out) {
    extern __shared__ char smc[];
    unsigned sb = smem_u32(smc);
    int tid = threadIdx.x;
    int wid = tid >> 5, lane = tid & 31;
    int g = lane >> 2, tig = lane & 3;

    stageB(sb, wiU, 1, tid, 256);
    cp_commit_wait();
    __syncthreads();

    int rowbase = blockIdx.x * 128 + wid * 16;
    int r0 = rowbase + g, r1 = rowbase + g + 8;
    int cr0 = (r0 < NN) ? r0 : (NN - 1);
    int cr1 = (r1 < NN) ? r1 : (NN - 1);

    float acc[16][4];
#pragma unroll
    for (int i = 0; i < 16; i++)
#pragma unroll
        for (int j = 0; j < 4; j++) acc[i][j] = 0.0f;

#pragma unroll
    for (int ks = 0; ks < 8; ks++) {
        int k0 = ks * 16;
        unsigned ahi[4], alo[4];
        loadA_frag(A, cr0, cr1, k0, tig, ahi, alo);
        mma3_tiles(acc, smc, k0, g, tig, ahi, alo);
    }

    // bias + rowwise LN stats (rows r0, r1 span the lane-quad: tig 0..3, 16 t-tiles)
    float s0 = 0.f, sq0 = 0.f, s1 = 0.f, sq1 = 0.f;
#pragma unroll
    for (int t = 0; t < 16; t++) {
        int col = t * 8 + tig * 2;
        float2 bv = *(const float2*)&bias[col];
        acc[t][0] += bv.x; acc[t][1] += bv.y;
        acc[t][2] += bv.x; acc[t][3] += bv.y;
        s0 += acc[t][0] + acc[t][1];
        sq0 += acc[t][0] * acc[t][0] + acc[t][1] * acc[t][1];
        s1 += acc[t][2] + acc[t][3];
        sq1 += acc[t][2] * acc[t][2] + acc[t][3] * acc[t][3];
    }
#pragma unroll
    for (int off = 1; off <= 2; off <<= 1) {
        s0 += __shfl_xor_sync(0xffffffffu, s0, off);
        sq0 += __shfl_xor_sync(0xffffffffu, sq0, off);
        s1 += __shfl_xor_sync(0xffffffffu, s1, off);
        sq1 += __shfl_xor_sync(0xffffffffu, sq1, off);
    }
    float mu0 = s0 * (1.0f / HD);
    float mu1 = s1 * (1.0f / HD);
    float rstd0 = rsqrtf(sq0 * (1.0f / HD) - mu0 * mu0 + 1e-5f);
    float rstd1 = rsqrtf(sq1 * (1.0f / HD) - mu1 * mu1 + 1e-5f);

#pragma unroll
    for (int t = 0; t < 16; t++) {
        int col = t * 8 + tig * 2;
        float2 gv = *(const float2*)&lng[col];
        float2 lv = *(const float2*)&lnb[col];
        float2 v0, v1;
        v0.x = fmaxf((acc[t][0] - mu0) * rstd0 * gv.x + lv.x, 0.0f);
        v0.y = fmaxf((acc[t][1] - mu0) * rstd0 * gv.y + lv.y, 0.0f);
        v1.x = fmaxf((acc[t][2] - mu1) * rstd1 * gv.x + lv.x, 0.0f);
        v1.y = fmaxf((acc[t][3] - mu1) * rstd1 * gv.y + lv.y, 0.0f);
        if (r0 < NN) {
            if (addres) {
                float2 hv = *(const float2*)(Out + r0 * HD + col);
                v0.x += hv.x; v0.y += hv.y;
            }
            *(float2*)(Out + r0 * HD + col) = v0;
        }
        if (r1 < NN) {
            if (addres) {
                float2 hv = *(const float2*)(Out + r1 * HD + col);
                v1.x += hv.x; v1.y += hv.y;
            }
            *(float2*)(Out + r1 * HD + col) = v1;
        }
    }
}

// ---------------- weight transpose + split + interleave -------------------------
__device__ __forceinline__ void split_store(unsigned* __restrict__ dst,
                                            int m, int n, int kw,
                                            float v0, float v1) {
    __nv_bfloat16 h0 = __float2bfloat16(v0), h1 = __float2bfloat16(v1);
    __nv_bfloat16 l0 = __float2bfloat16(v0 - __bfloat162float(h0));
    __nv_bfloat16 l1 = __float2bfloat16(v1 - __bfloat162float(h1));
    dst[m * 16384 + n * 128 + kw * 2] =
        ((unsigned)__bfloat16_as_ushort(h1) << 16) | __bfloat16_as_ushort(h0);
    dst[m * 16384 + n * 128 + kw * 2 + 1] =
        ((unsigned)__bfloat16_as_ushort(l1) << 16) | __bfloat16_as_ushort(l0);
}

__global__ void split_msg(const float* __restrict__ msg_w1, unsigned* __restrict__ wi) {
    int n = blockIdx.x, m = blockIdx.y, kw = threadIdx.x;   // 64 thr
    int l = m >> 1, part = m & 1;
    const float* W = msg_w1 + l * 257 * HD + part * 128 * HD;
    split_store(wi, m, n, kw, W[(2 * kw) * HD + n], W[(2 * kw + 1) * HD + n]);
}

__global__ void split_upd(const float* __restrict__ upd_w1,
                          const float* __restrict__ W2U,
                          const float* __restrict__ upd_w2,
                          unsigned* __restrict__ wi) {
    int n = blockIdx.x, m2 = blockIdx.y, kw = threadIdx.x;  // 64 thr, m2 0..11
    const float* W;
    if (m2 < 4)       W = upd_w1 + m2 * 256 * HD;           // U1a rows 0..127
    else if (m2 < 8)  W = W2U + (m2 - 4) * HD * HD;
    else              W = upd_w2 + (m2 - 8) * HD * HD;
    split_store(wi, 8 + m2, n, kw, W[(2 * kw) * HD + n], W[(2 * kw + 1) * HD + n]);
}

// ---------------- tiny utility kernels ------------------------------------------
__global__ void zero_k(float* __restrict__ p, int n) {
    int i = blockIdx.x * blockDim.x + threadIdx.x;
    if (i < n) p[i] = 0.0f;
}
__global__ void zero_int(int* __restrict__ p, int n) {
    int i = blockIdx.x * blockDim.x + threadIdx.x;
    if (i < n) p[i] = 0;
}

// ---------------- CSR build ------------------------------------------------------
__global__ void count_k(const int* __restrict__ ei, int* __restrict__ deg) {
    int e = blockIdx.x * blockDim.x + threadIdx.x;
    if (e < EE) atomicAdd(&deg[ei[EE + e]], 1);
}

__global__ void scan_part(const int* __restrict__ deg, int* __restrict__ rowptr,
                          int* __restrict__ bsum) {
    __shared__ int s[256];
    int tid = threadIdx.x;
    int i = blockIdx.x * 256 + tid;
    int v = (i < NN) ? deg[i] : 0;
    s[tid] = v;
    __syncthreads();
#pragma unroll
    for (int off = 1; off < 256; off <<= 1) {
        int t = (tid >= off) ? s[tid - off] : 0;
        __syncthreads();
        s[tid] += t;
        __syncthreads();
    }
    if (i < NN) rowptr[i] = s[tid] - v;
    if (tid == 255) bsum[blockIdx.x] = s[255];
}

__global__ void scan_bsum(int* __restrict__ bsum) {
    __shared__ int s[256];
    int tid = threadIdx.x;
    int v = (tid < NB) ? bsum[tid] : 0;
    s[tid] = v;
    __syncthreads();
#pragma unroll
    for (int off = 1; off < 256; off <<= 1) {
        int t = (tid >= off) ? s[tid - off] : 0;
        __syncthreads();
        s[tid] += t;
        __syncthreads();
    }
    if (tid < NB) bsum[tid] = s[tid] - v;
}

__global__ void add_off(int* __restrict__ rowptr, const int* __restrict__ bsum,
                        int* __restrict__ cursor) {
    int i = blockIdx.x * 256 + threadIdx.x;
    if (i < NN) {
        int r = rowptr[i] + bsum[blockIdx.x];
        rowptr[i] = r;
        cursor[i] = r;
    }
    if (i == 0) rowptr[NN] = EE;
}

__global__ void degf_k(const int* __restrict__ rowptr, float* __restrict__ degf) {
    int i = blockIdx.x * blockDim.x + threadIdx.x;
    if (i < NN) degf[i] = (float)(rowptr[i + 1] - rowptr[i]);
}

__global__ void scatter_k(const int* __restrict__ ei,
                          const float* __restrict__ pos,
                          int* __restrict__ cursor,
                          int2* __restrict__ epack) {
    int e = blockIdx.x * blockDim.x + threadIdx.x;
    if (e >= EE) return;
    int s = ei[e];
    int t = ei[EE + e];
    float dx = pos[t * 3 + 0] - pos[s * 3 + 0];
    float dy = pos[t * 3 + 1] - pos[s * 3 + 1];
    float dz = pos[t * 3 + 2] - pos[s * 3 + 2];
    float dd = sqrtf(dx * dx + dy * dy + dz * dz);
    int p = atomicAdd(&cursor[t], 1);
    epack[p] = make_int2(s, __float_as_int(dd));
}

// ---------------- encoder: h = x @ enc_w + enc_b (K=15) --------------------------
__global__ void encoder_k(const float* __restrict__ x,
                          const float* __restrict__ w,
                          const float* __restrict__ b,
                          float* __restrict__ h) {
    __shared__ float ws[15 * HD];
    __shared__ float xs[16 * 15];
    __shared__ float bs[HD];
    int c = threadIdx.x;
    for (int i = c; i < 15 * HD; i += HD) ws[i] = w[i];
    bs[c] = b[c];
    int n0 = blockIdx.x * 16;
    for (int i = c; i < 16 * 15; i += HD) {
        int nn = i / 15, kk = i % 15;
        int g = n0 + nn;
        xs[i] = (g < NN) ? x[g * 15 + kk] : 0.0f;
    }
    __syncthreads();
    for (int r = 0; r < 16; r++) {
        int g = n0 + r;
        if (g >= NN) break;
        float acc = bs[c];
#pragma unroll
        for (int k = 0; k < 15; k++) acc += xs[r * 15 + k] * ws[k * HD + c];
        h[g * HD + c] = acc;
    }
}

// W2U[l] = msg_w2[l] @ U1b[l];  cvec[l] = msg_b2[l] @ U1b[l]
__global__ void build_w2u(const float* __restrict__ msg_w2,
                          const float* __restrict__ msg_b2,
                          const float* __restrict__ upd_w1,
                          float* __restrict__ W2U,
                          float* __restrict__ cvec) {
    int l = blockIdx.y, k = blockIdx.x, c = threadIdx.x;
    const float* u1b = upd_w1 + l * 256 * HD + 128 * HD;
    if (k < HD) {
        const float* wrow = msg_w2 + (l * HD + k) * HD;
        float acc = 0.0f;
        for (int j = 0; j < HD; j++) acc += wrow[j] * u1b[j * HD + c];
        W2U[(l * HD + k) * HD + c] = acc;
    } else {
        const float* brow = msg_b2 + l * HD;
        float acc = 0.0f;
        for (int j = 0; j < HD; j++) acc += brow[j] * u1b[j * HD + c];
        cvec[l * HD + c] = acc;
    }
}

// ---------------- CSR gather aggregation (packed edges, unroll 4) ---------------
__global__ void __launch_bounds__(256) aggregate_k(
    const int* __restrict__ rowptr,
    const int2* __restrict__ epack,
    const float* __restrict__ P1,
    const float* __restrict__ P2,
    const float* __restrict__ w1c,
    float* __restrict__ Yagg) {
    int node = blockIdx.x * 8 + (threadIdx.x >> 5);
    int lane = threadIdx.x & 31;
    int c4 = lane * 4;
    const float4 cw = *(const float4*)&w1c[c4];
    const float4 p1 = *(const float4*)&P1[node * HD + c4];
    float a0 = 0.f, a1 = 0.f, a2 = 0.f, a3 = 0.f;
    float b0 = 0.f, b1 = 0.f, b2 = 0.f, b3 = 0.f;
    float c0 = 0.f, c1 = 0.f, c2 = 0.f, c3 = 0.f;
    float d0 = 0.f, d1 = 0.f, d2 = 0.f, d3 = 0.f;
    int beg = rowptr[node], end = rowptr[node + 1];
    int e = beg;
    for (; e + 3 < end; e += 4) {
        int2 q0 = epack[e], q1 = epack[e + 1], q2 = epack[e + 2], q3 = epack[e + 3];
        const float4 v0 = *(const float4*)&P2[q0.x * HD + c4];
        const float4 v1 = *(const float4*)&P2[q1.x * HD + c4];
        const float4 v2 = *(const float4*)&P2[q2.x * HD + c4];
        const float4 v3 = *(const float4*)&P2[q3.x * HD + c4];
        float dd0 = __int_as_float(q0.y), dd1 = __int_as_float(q1.y);
        float dd2 = __int_as_float(q2.y), dd3 = __int_as_float(q3.y);
        a0 += fmaxf(p1.x + v0.x + dd0 * cw.x, 0.0f);
        a1 += fmaxf(p1.y + v0.y + dd0 * cw.y, 0.0f);
        a2 += fmaxf(p1.z + v0.z + dd0 * cw.z, 0.0f);
        a3 += fmaxf(p1.w + v0.w + dd0 * cw.w, 0.0f);
        b0 += fmaxf(p1.x + v1.x + dd1 * cw.x, 0.0f);
        b1 += fmaxf(p1.y + v1.y + dd1 * cw.y, 0.0f);
        b2 += fmaxf(p1.z + v1.z + dd1 * cw.z, 0.0f);
        b3 += fmaxf(p1.w + v1.w + dd1 * cw.w, 0.0f);
        c0 += fmaxf(p1.x + v2.x + dd2 * cw.x, 0.0f);
        c1 += fmaxf(p1.y + v2.y + dd2 * cw.y, 0.0f);
        c2 += fmaxf(p1.z + v2.z + dd2 * cw.z, 0.0f);
        c3 += fmaxf(p1.w + v2.w + dd2 * cw.w, 0.0f);
        d0 += fmaxf(p1.x + v3.x + dd3 * cw.x, 0.0f);
        d1 += fmaxf(p1.y + v3.y + dd3 * cw.y, 0.0f);
        d2 += fmaxf(p1.z + v3.z + dd3 * cw.z, 0.0f);
        d3 += fmaxf(p1.w + v3.w + dd3 * cw.w, 0.0f);
    }
    for (; e < end; e++) {
        int2 q0 = epack[e];
        const float4 v0 = *(const float4*)&P2[q0.x * HD + c4];
        float dd0 = __int_as_float(q0.y);
        a0 += fmaxf(p1.x + v0.x + dd0 * cw.x, 0.0f);
        a1 += fmaxf(p1.y + v0.y + dd0 * cw.y, 0.0f);
        a2 += fmaxf(p1.z + v0.z + dd0 * cw.z, 0.0f);
        a3 += fmaxf(p1.w + v0.w + dd0 * cw.w, 0.0f);
    }
    *(float4*)&Yagg[node * HD + c4] = make_float4(
        (a0 + b0) + (c0 + d0), (a1 + b1) + (c1 + d1),
        (a2 + b2) + (c2 + d2), (a3 + b3) + (c3 + d3));
}

// ---------------- readout --------------------------------------------------------
__global__ void pool_k(const float* __restrict__ h,
                       const int* __restrict__ batch,
                       float* __restrict__ pooled, float* __restrict__ cnt) {
    int nidx = blockIdx.x * 8 + (threadIdx.x >> 5);
    int lane = threadIdx.x & 31;
    if (nidx >= NN) return;
    int g = batch[nidx];
    float4 v = *(const float4*)&h[nidx * HD + lane * 4];
    float* p = &pooled[g * HD + lane * 4];
    atomicAdd(p + 0, v.x);
    atomicAdd(p + 1, v.y);
    atomicAdd(p + 2, v.z);
    atomicAdd(p + 3, v.w);
    if (lane == 0) atomicAdd(&cnt[g], 1.0f);
}

__global__ void readout_k(const float* __restrict__ pooled,
                          const float* __restrict__ cnt,
                          const float* __restrict__ w1, const float* __restrict__ b1,
                          const float* __restrict__ w2, const float* __restrict__ b2,
                          const float* __restrict__ w3, const float* __restrict__ b3,
                          float* __restrict__ out) {
    __shared__ float p[HD];
    __shared__ float o1s[HD];
    __shared__ float o2s[64];
    int g = blockIdx.x, c = threadIdx.x;
    float cc = fmaxf(cnt[g], 1.0f);
    p[c] = pooled[g * HD + c] / cc;
    __syncthreads();
    float acc = b1[c];
    for (int k = 0; k < HD; k++) acc += p[k] * w1[k * HD + c];
    o1s[c] = fmaxf(acc, 0.0f);
    __syncthreads();
    if (c < 64) {
        float a = b2[c];
        for (int k = 0; k < HD; k++) a += o1s[k] * w2[k * 64 + c];
        o2s[c] = fmaxf(a, 0.0f);
    }
    __syncthreads();
    if (c == 0) {
        float a = b3[0];
        for (int k = 0; k < 64; k++) a += o2s[k] * w3[k];
        out[g] = a;
    }
}

// ---------------- launch ----------------------------------------------------------
extern "C" void kernel_launch(void* const* d_in, const int* in_sizes, int n_in,
                              void* d_out, int out_size) {
    const float* x       = (const float*)d_in[0];
    const int*   ei      = (const int*)d_in[1];
    const float* pos     = (const float*)d_in[3];
    const int*   batch   = (const int*)d_in[4];
    const float* enc_w   = (const float*)d_in[5];
    const float* enc_b   = (const float*)d_in[6];
    const float* msg_w1  = (const float*)d_in[9];
    const float* msg_b1  = (const float*)d_in[10];
    const float* msg_w2  = (const float*)d_in[11];
    const float* msg_b2  = (const float*)d_in[12];
    const float* upd_w1  = (const float*)d_in[13];
    const float* upd_b1  = (const float*)d_in[14];
    const float* upd_w2  = (const float*)d_in[15];
    const float* upd_b2  = (const float*)d_in[16];
    const float* ln_g    = (const float*)d_in[17];
    const float* ln_b    = (const float*)d_in[18];
    const float* mlp_w1  = (const float*)d_in[19];
    const float* mlp_b1  = (const float*)d_in[20];
    const float* mlp_w2  = (const float*)d_in[21];
    const float* mlp_b2  = (const float*)d_in[22];
    const float* mlp_w3  = (const float*)d_in[23];
    const float* mlp_b3  = (const float*)d_in[24];
    float*       out     = (float*)d_out;

    float *h, *P1, *P2, *Yagg, *T, *degf, *W2U, *cvec, *pooled, *cnt;
    int *rowptr, *cursor, *bsum;
    int2 *epack;
    unsigned *wi;
    cudaGetSymbolAddress((void**)&h, d_h);
    cudaGetSymbolAddress((void**)&P1, d_P1);
    cudaGetSymbolAddress((void**)&P2, d_P2);
    cudaGetSymbolAddress((void**)&Yagg, d_Yagg);
    cudaGetSymbolAddress((void**)&T, d_T);
    cudaGetSymbolAddress((void**)&degf, d_degf);
    cudaGetSymbolAddress((void**)&W2U, d_W2U);
    cudaGetSymbolAddress((void**)&cvec, d_cvec);
    cudaGetSymbolAddress((void**)&pooled, d_pooled);
    cudaGetSymbolAddress((void**)&cnt, d_cnt);
    cudaGetSymbolAddress((void**)&rowptr, d_rowptr);
    cudaGetSymbolAddress((void**)&cursor, d_cursor);
    cudaGetSymbolAddress((void**)&bsum, d_bsum);
    cudaGetSymbolAddress((void**)&epack, d_epack);
    cudaGetSymbolAddress((void**)&wi, d_wi);

    const int SM2B = 2 * BTILE;   // 139264 (p12, upd2)
    const int SM1B = BTILE;       // 69632  (upd3)
    cudaFuncSetAttribute(p12_tc,  cudaFuncAttributeMaxDynamicSharedMemorySize, SM2B);
    cudaFuncSetAttribute(upd2_tc, cudaFuncAttributeMaxDynamicSharedMemorySize, SM2B);
    cudaFuncSetAttribute(upd3_tc, cudaFuncAttributeMaxDynamicSharedMemorySize, SM1B);

    const int G128 = (NN + 127) / 128;   // 391
    const int G256 = (NN + 255) / 256;   // 196

    // ---- prep; launch #4 = layer-0 p12 so ncu captures it ----
    encoder_k<<<(NN + 15) / 16, 128>>>(x, enc_w, enc_b, h);               // 1
    split_msg<<<dim3(128, 8), 64>>>(msg_w1, wi);                          // 2
    zero_int<<<(NN + 255) / 256, 256>>>(cursor, NN);                      // 3
    p12_tc<<<G128, 512, SM2B>>>(h, wi, wi + 16384, msg_b1, P1, P2);       // 4 (profiled)
    count_k<<<(EE + 255) / 256, 256>>>(ei, cursor);                       // 5
    scan_part<<<NB, 256>>>(cursor, rowptr, bsum);                         // 6
    scan_bsum<<<1, 256>>>(bsum);                                          // 7
    add_off<<<NB, 256>>>(rowptr, bsum, cursor);                           // 8
    degf_k<<<(NN + 255) / 256, 256>>>(rowptr, degf);                      // 9
    scatter_k<<<(EE + 255) / 256, 256>>>(ei, pos, cursor, epack);         // 10
    build_w2u<<<dim3(129, 4), 128>>>(msg_w2, msg_b2, upd_w1, W2U, cvec);  // 11
    split_upd<<<dim3(128, 12), 64>>>(upd_w1, W2U, upd_w2, wi);            // 12
    zero_k<<<(NG * HD + 255) / 256, 256>>>(pooled, NG * HD);              // 13
    zero_k<<<1, 64>>>(cnt, NG);                                           // 14

    for (int l = 0; l < NLAY; l++) {
        const float* w1l = msg_w1 + l * 257 * HD;
        if (l > 0) {
            p12_tc<<<G128, 512, SM2B>>>(h, wi + (2 * l) * 16384,
                                        wi + (2 * l + 1) * 16384,
                                        msg_b1 + l * HD, P1, P2);
        }
        aggregate_k<<<NN / 8, 256>>>(rowptr, epack, P1, P2,
                                     w1l + 256 * HD, Yagg);
        upd2_tc<<<G256, 512, SM2B>>>(h, Yagg,
                                     wi + (8 + l) * 16384, wi + (12 + l) * 16384,
                                     upd_b1 + l * HD, degf, cvec + l * HD, T);
        upd3_tc<<<G128, 256, SM1B>>>(T, wi + (16 + l) * 16384,
                                     upd_b2 + l * HD, ln_g + l * HD, ln_b + l * HD,
                                     (l > 0) ? 1 : 0, h);
    }

    pool_k<<<(NN + 7) / 8, 256>>>(h, batch, pooled, cnt);
    readout_k<<<NG, 128>>>(pooled, cnt, mlp_w1, mlp_b1, mlp_w2, mlp_b2,
                           mlp_w3, mlp_b3, out);
}

// round 13
// speedup vs baseline: 2.1231x; 1.0409x over previous
#include <cuda_runtime.h>
#include <cuda_bf16.h>

#define NN 50000
#define EE 500000
#define HD 128
#define NLAY 4
#define NG 64
#define NB 196  // (NN+255)/256 scan blocks
#define G128 391

// interleaved split-weight matrices: 20 x [128 n][128 words]
//   word[kw*2] = bf16x2 hi (k=2kw,2kw+1); word[kw*2+1] = bf16x2 lo
// idx 0..7 = msg W1a/W1b (2l+part) ; 8..11 = U1a[l] ; 12..15 = W2U[l] ; 16..19 = U2[l]
__device__ __align__(16) unsigned d_wi[20 * 16384];

// ---------------- scratch ------------------------------------------------------
__device__ __align__(16) float d_h[NN * HD];
__device__ __align__(16) float d_P1[NN * HD];
__device__ __align__(16) float d_P2[NN * HD];
__device__ __align__(16) float d_Yagg[NN * HD];
__device__ __align__(16) float d_T[NN * HD];
__device__ __align__(16) float d_degf[NN];
__device__ __align__(16) float d_W2U[NLAY * HD * HD];
__device__ __align__(16) float d_cvec[NLAY * HD];
__device__ __align__(16) float d_pooled[NG * HD];
__device__ __align__(16) float d_cnt[NG];
__device__ __align__(16) int   d_rowptr[NN + 1];
__device__ __align__(16) int   d_cursor[NN];
__device__ __align__(16) int   d_bsum[256];
__device__ __align__(16) int2  d_epack[EE];

// ---------------- helpers -------------------------------------------------------
__device__ __forceinline__ unsigned smem_u32(const void* p) {
    unsigned r;
    asm("{ .reg .u64 t; cvta.to.shared.u64 t, %1; cvt.u32.u64 %0, t; }"
        : "=r"(r) : "l"(p));
    return r;
}
__device__ __forceinline__ void cp16(unsigned saddr, const void* g) {
    asm volatile("cp.async.cg.shared.global [%0], [%1], 16;" :: "r"(saddr), "l"(g));
}
__device__ __forceinline__ void cp_commit_wait() {
    asm volatile("cp.async.commit_group;");
    asm volatile("cp.async.wait_group 0;");
}

__device__ __forceinline__ void mma_bf16(float c[4], const unsigned a[4],
                                         unsigned b0, unsigned b1) {
    asm volatile(
        "mma.sync.aligned.m16n8k16.row.col.f32.bf16.bf16.f32 "
        "{%0,%1,%2,%3}, {%4,%5,%6,%7}, {%8,%9}, {%0,%1,%2,%3};"
        : "+f"(c[0]), "+f"(c[1]), "+f"(c[2]), "+f"(c[3])
        : "r"(a[0]), "r"(a[1]), "r"(a[2]), "r"(a[3]), "r"(b0), "r"(b1));
}

__device__ __forceinline__ void split2(float2 f, unsigned& hi, unsigned& lo) {
    __nv_bfloat16 hx = __float2bfloat16(f.x), hy = __float2bfloat16(f.y);
    __nv_bfloat16 lx = __float2bfloat16(f.x - __bfloat162float(hx));
    __nv_bfloat16 ly = __float2bfloat16(f.y - __bfloat162float(hy));
    hi = ((unsigned)__bfloat16_as_ushort(hy) << 16) | __bfloat16_as_ushort(hx);
    lo = ((unsigned)__bfloat16_as_ushort(ly) << 16) | __bfloat16_as_ushort(lx);
}

// ---------------- HMMA building blocks ------------------------------------------
// smem B tile: 128 n rows x 136 words (hi/lo interleaved), 69632 B per matrix.
#define BROW 136
#define BTILE 69632

__device__ __forceinline__ void stageB(unsigned sb, const unsigned* __restrict__ wi,
                                       int tid, int nthr) {
    for (int c = tid; c < 4096; c += nthr) {   // 16B-chunks (4 words each)
        int n = c >> 5;
        int c4 = c & 31;
        cp16(sb + (unsigned)((n * BROW + c4 * 4) * 4), wi + n * 128 + c4 * 4);
    }
}

__device__ __forceinline__ void loadA_frag(const float* __restrict__ A,
                                           int cr0, int cr1, int k0, int tig,
                                           unsigned ahi[4], unsigned alo[4]) {
    float2 f00 = *(const float2*)(A + cr0 * HD + k0 + tig * 2);
    float2 f10 = *(const float2*)(A + cr1 * HD + k0 + tig * 2);
    float2 f01 = *(const float2*)(A + cr0 * HD + k0 + tig * 2 + 8);
    float2 f11 = *(const float2*)(A + cr1 * HD + k0 + tig * 2 + 8);
    split2(f00, ahi[0], alo[0]);
    split2(f10, ahi[1], alo[1]);
    split2(f01, ahi[2], alo[2]);
    split2(f11, ahi[3], alo[3]);
}

__device__ __forceinline__ void mma3_tiles(float acc[16][4], const char* __restrict__ smB,
                                           int k0, int g, int tig,
                                           const unsigned ahi[4], const unsigned alo[4]) {
    int kwofs = ((k0 >> 1) + tig) * 2;
#pragma unroll
    for (int t = 0; t < 16; t++) {
        int n = t * 8 + g;
        const char* base = smB + (n * BROW + kwofs) * 4;
        unsigned long long q0 = *(const unsigned long long*)(base);
        unsigned long long q1 = *(const unsigned long long*)(base + 32);
        unsigned bh0 = (unsigned)q0, bl0 = (unsigned)(q0 >> 32);
        unsigned bh1 = (unsigned)q1, bl1 = (unsigned)(q1 >> 32);
        mma_bf16(acc[t], ahi, bh0, bh1);
        mma_bf16(acc[t], ahi, bl0, bl1);
        mma_bf16(acc[t], alo, bh0, bh1);
    }
}

// ---------------- p12: P1/P2 message GEMM, one product per block ----------------
// 256 thr, 8 warps x 16 rows = 128 rows. Blocks [0,391) -> P1, [391,782) -> P2.
__global__ void __launch_bounds__(256) p12_tc(
    const float* __restrict__ A,
    const unsigned* __restrict__ wiPair,     // [W1a | W1b] adjacent
    const float* __restrict__ bias,
    float* __restrict__ O1, float* __restrict__ O2) {
    extern __shared__ char smc[];
    unsigned sb = smem_u32(smc);
    int tid = threadIdx.x;
    int wid = tid >> 5, lane = tid & 31;
    int g = lane >> 2, tig = lane & 3;

    int pr = (blockIdx.x >= G128) ? 1 : 0;
    int blk = blockIdx.x - pr * G128;

    stageB(sb, wiPair + pr * 16384, tid, 256);
    cp_commit_wait();
    __syncthreads();

    int rowbase = blk * 128 + wid * 16;
    int r0 = rowbase + g, r1 = rowbase + g + 8;
    int cr0 = (r0 < NN) ? r0 : (NN - 1);
    int cr1 = (r1 < NN) ? r1 : (NN - 1);

    float acc[16][4];
#pragma unroll
    for (int i = 0; i < 16; i++)
#pragma unroll
        for (int j = 0; j < 4; j++) acc[i][j] = 0.0f;

#pragma unroll
    for (int ks = 0; ks < 8; ks++) {
        int k0 = ks * 16;
        unsigned ahi[4], alo[4];
        loadA_frag(A, cr0, cr1, k0, tig, ahi, alo);
        mma3_tiles(acc, smc, k0, g, tig, ahi, alo);
    }

    float* Op = pr ? O2 : O1;
#pragma unroll
    for (int t = 0; t < 16; t++) {
        int col = t * 8 + tig * 2;
        float2 v0 = make_float2(acc[t][0], acc[t][1]);
        float2 v1 = make_float2(acc[t][2], acc[t][3]);
        if (pr == 0) {
            float2 bv = *(const float2*)&bias[col];
            v0.x += bv.x; v0.y += bv.y;
            v1.x += bv.x; v1.y += bv.y;
        }
        if (r0 < NN) *(float2*)(Op + r0 * HD + col) = v0;
        if (r1 < NN) *(float2*)(Op + r1 * HD + col) = v1;
    }
}

// ---------------- upd2: T = relu(h@U1a + Yagg@W2U + deg*cvec + bias) ------------
// 256 thr, 8 warps x 16 rows = 128 rows; sequential staging of the 2 matrices.
__global__ void __launch_bounds__(256) upd2_tc(
    const float* __restrict__ A0, const float* __restrict__ A1,
    const unsigned* __restrict__ wi0, const unsigned* __restrict__ wi1,
    const float* __restrict__ bias, const float* __restrict__ degf,
    const float* __restrict__ cvec, float* __restrict__ Out) {
    extern __shared__ char smc[];
    unsigned sb = smem_u32(smc);
    int tid = threadIdx.x;
    int wid = tid >> 5, lane = tid & 31;
    int g = lane >> 2, tig = lane & 3;

    stageB(sb, wi0, tid, 256);
    cp_commit_wait();
    __syncthreads();

    int rowbase = blockIdx.x * 128 + wid * 16;
    int r0 = rowbase + g, r1 = rowbase + g + 8;
    int cr0 = (r0 < NN) ? r0 : (NN - 1);
    int cr1 = (r1 < NN) ? r1 : (NN - 1);

    float acc[16][4];
#pragma unroll
    for (int i = 0; i < 16; i++)
#pragma unroll
        for (int j = 0; j < 4; j++) acc[i][j] = 0.0f;

#pragma unroll
    for (int ks = 0; ks < 8; ks++) {
        int k0 = ks * 16;
        unsigned ahi[4], alo[4];
        loadA_frag(A0, cr0, cr1, k0, tig, ahi, alo);
        mma3_tiles(acc, smc, k0, g, tig, ahi, alo);
    }
    __syncthreads();                 // all warps done reading matrix 0
    stageB(sb, wi1, tid, 256);
    cp_commit_wait();
    __syncthreads();
#pragma unroll
    for (int ks = 0; ks < 8; ks++) {
        int k0 = ks * 16;
        unsigned ahi[4], alo[4];
        loadA_frag(A1, cr0, cr1, k0, tig, ahi, alo);
        mma3_tiles(acc, smc, k0, g, tig, ahi, alo);
    }

    float dg0 = degf[cr0], dg1 = degf[cr1];
#pragma unroll
    for (int t = 0; t < 16; t++) {
        int col = t * 8 + tig * 2;
        float2 bv = *(const float2*)&bias[col];
        float2 cv = *(const float2*)&cvec[col];
        float2 v0, v1;
        v0.x = fmaxf(acc[t][0] + dg0 * cv.x + bv.x, 0.0f);
        v0.y = fmaxf(acc[t][1] + dg0 * cv.y + bv.y, 0.0f);
        v1.x = fmaxf(acc[t][2] + dg1 * cv.x + bv.x, 0.0f);
        v1.y = fmaxf(acc[t][3] + dg1 * cv.y + bv.y, 0.0f);
        if (r0 < NN) *(float2*)(Out + r0 * HD + col) = v0;
        if (r1 < NN) *(float2*)(Out + r1 * HD + col) = v1;
    }
}

// ---------------- upd3: h = (res? h:0) + relu(LN(T@U2 + bias)) ------------------
__global__ void __launch_bounds__(256) upd3_tc(
    const float* __restrict__ A,
    const unsigned* __restrict__ wiU,
    const float* __restrict__ bias,
    const float* __restrict__ lng, const float* __restrict__ lnb,
    int addres, float* __restrict__ Out) {
    extern __shared__ char smc[];
    unsigned sb = smem_u32(smc);
    int tid = threadIdx.x;
    int wid = tid >> 5, lane = tid & 31;
    int g = lane >> 2, tig = lane & 3;

    stageB(sb, wiU, tid, 256);
    cp_commit_wait();
    __syncthreads();

    int rowbase = blockIdx.x * 128 + wid * 16;
    int r0 = rowbase + g, r1 = rowbase + g + 8;
    int cr0 = (r0 < NN) ? r0 : (NN - 1);
    int cr1 = (r1 < NN) ? r1 : (NN - 1);

    float acc[16][4];
#pragma unroll
    for (int i = 0; i < 16; i++)
#pragma unroll
        for (int j = 0; j < 4; j++) acc[i][j] = 0.0f;

#pragma unroll
    for (int ks = 0; ks < 8; ks++) {
        int k0 = ks * 16;
        unsigned ahi[4], alo[4];
        loadA_frag(A, cr0, cr1, k0, tig, ahi, alo);
        mma3_tiles(acc, smc, k0, g, tig, ahi, alo);
    }

    float s0 = 0.f, sq0 = 0.f, s1 = 0.f, sq1 = 0.f;
#pragma unroll
    for (int t = 0; t < 16; t++) {
        int col = t * 8 + tig * 2;
        float2 bv = *(const float2*)&bias[col];
        acc[t][0] += bv.x; acc[t][1] += bv.y;
        acc[t][2] += bv.x; acc[t][3] += bv.y;
        s0 += acc[t][0] + acc[t][1];
        sq0 += acc[t][0] * acc[t][0] + acc[t][1] * acc[t][1];
        s1 += acc[t][2] + acc[t][3];
        sq1 += acc[t][2] * acc[t][2] + acc[t][3] * acc[t][3];
    }
#pragma unroll
    for (int off = 1; off <= 2; off <<= 1) {
        s0 += __shfl_xor_sync(0xffffffffu, s0, off);
        sq0 += __shfl_xor_sync(0xffffffffu, sq0, off);
        s1 += __shfl_xor_sync(0xffffffffu, s1, off);
        sq1 += __shfl_xor_sync(0xffffffffu, sq1, off);
    }
    float mu0 = s0 * (1.0f / HD);
    float mu1 = s1 * (1.0f / HD);
    float rstd0 = rsqrtf(sq0 * (1.0f / HD) - mu0 * mu0 + 1e-5f);
    float rstd1 = rsqrtf(sq1 * (1.0f / HD) - mu1 * mu1 + 1e-5f);

#pragma unroll
    for (int t = 0; t < 16; t++) {
        int col = t * 8 + tig * 2;
        float2 gv = *(const float2*)&lng[col];
        float2 lv = *(const float2*)&lnb[col];
        float2 v0, v1;
        v0.x = fmaxf((acc[t][0] - mu0) * rstd0 * gv.x + lv.x, 0.0f);
        v0.y = fmaxf((acc[t][1] - mu0) * rstd0 * gv.y + lv.y, 0.0f);
        v1.x = fmaxf((acc[t][2] - mu1) * rstd1 * gv.x + lv.x, 0.0f);
        v1.y = fmaxf((acc[t][3] - mu1) * rstd1 * gv.y + lv.y, 0.0f);
        if (r0 < NN) {
            if (addres) {
                float2 hv = *(const float2*)(Out + r0 * HD + col);
                v0.x += hv.x; v0.y += hv.y;
            }
            *(float2*)(Out + r0 * HD + col) = v0;
        }
        if (r1 < NN) {
            if (addres) {
                float2 hv = *(const float2*)(Out + r1 * HD + col);
                v1.x += hv.x; v1.y += hv.y;
            }
            *(float2*)(Out + r1 * HD + col) = v1;
        }
    }
}

// ---------------- weight transpose + split + interleave -------------------------
__device__ __forceinline__ void split_store(unsigned* __restrict__ dst,
                                            int m, int n, int kw,
                                            float v0, float v1) {
    __nv_bfloat16 h0 = __float2bfloat16(v0), h1 = __float2bfloat16(v1);
    __nv_bfloat16 l0 = __float2bfloat16(v0 - __bfloat162float(h0));
    __nv_bfloat16 l1 = __float2bfloat16(v1 - __bfloat162float(h1));
    dst[m * 16384 + n * 128 + kw * 2] =
        ((unsigned)__bfloat16_as_ushort(h1) << 16) | __bfloat16_as_ushort(h0);
    dst[m * 16384 + n * 128 + kw * 2 + 1] =
        ((unsigned)__bfloat16_as_ushort(l1) << 16) | __bfloat16_as_ushort(l0);
}

__global__ void split_msg(const float* __restrict__ msg_w1, unsigned* __restrict__ wi) {
    int n = blockIdx.x, m = blockIdx.y, kw = threadIdx.x;   // 64 thr
    int l = m >> 1, part = m & 1;
    const float* W = msg_w1 + l * 257 * HD + part * 128 * HD;
    split_store(wi, m, n, kw, W[(2 * kw) * HD + n], W[(2 * kw + 1) * HD + n]);
}

__global__ void split_upd(const float* __restrict__ upd_w1,
                          const float* __restrict__ W2U,
                          const float* __restrict__ upd_w2,
                          unsigned* __restrict__ wi) {
    int n = blockIdx.x, m2 = blockIdx.y, kw = threadIdx.x;  // 64 thr, m2 0..11
    const float* W;
    if (m2 < 4)       W = upd_w1 + m2 * 256 * HD;
    else if (m2 < 8)  W = W2U + (m2 - 4) * HD * HD;
    else              W = upd_w2 + (m2 - 8) * HD * HD;
    split_store(wi, 8 + m2, n, kw, W[(2 * kw) * HD + n], W[(2 * kw + 1) * HD + n]);
}

// ---------------- tiny utility kernels ------------------------------------------
__global__ void zero_k(float* __restrict__ p, int n) {
    int i = blockIdx.x * blockDim.x + threadIdx.x;
    if (i < n) p[i] = 0.0f;
}
__global__ void zero_int(int* __restrict__ p, int n) {
    int i = blockIdx.x * blockDim.x + threadIdx.x;
    if (i < n) p[i] = 0;
}

// ---------------- CSR build ------------------------------------------------------
__global__ void count_k(const int* __restrict__ ei, int* __restrict__ deg) {
    int e = blockIdx.x * blockDim.x + threadIdx.x;
    if (e < EE) atomicAdd(&deg[ei[EE + e]], 1);
}

__global__ void scan_part(const int* __restrict__ deg, int* __restrict__ rowptr,
                          int* __restrict__ bsum) {
    __shared__ int s[256];
    int tid = threadIdx.x;
    int i = blockIdx.x * 256 + tid;
    int v = (i < NN) ? deg[i] : 0;
    s[tid] = v;
    __syncthreads();
#pragma unroll
    for (int off = 1; off < 256; off <<= 1) {
        int t = (tid >= off) ? s[tid - off] : 0;
        __syncthreads();
        s[tid] += t;
        __syncthreads();
    }
    if (i < NN) rowptr[i] = s[tid] - v;
    if (tid == 255) bsum[blockIdx.x] = s[255];
}

__global__ void scan_bsum(int* __restrict__ bsum) {
    __shared__ int s[256];
    int tid = threadIdx.x;
    int v = (tid < NB) ? bsum[tid] : 0;
    s[tid] = v;
    __syncthreads();
#pragma unroll
    for (int off = 1; off < 256; off <<= 1) {
        int t = (tid >= off) ? s[tid - off] : 0;
        __syncthreads();
        s[tid] += t;
        __syncthreads();
    }
    if (tid < NB) bsum[tid] = s[tid] - v;
}

__global__ void add_off(int* __restrict__ rowptr, const int* __restrict__ bsum,
                        int* __restrict__ cursor) {
    int i = blockIdx.x * 256 + threadIdx.x;
    if (i < NN) {
        int r = rowptr[i] + bsum[blockIdx.x];
        rowptr[i] = r;
        cursor[i] = r;
    }
    if (i == 0) rowptr[NN] = EE;
}

__global__ void degf_k(const int* __restrict__ rowptr, float* __restrict__ degf) {
    int i = blockIdx.x * blockDim.x + threadIdx.x;
    if (i < NN) degf[i] = (float)(rowptr[i + 1] - rowptr[i]);
}

__global__ void scatter_k(const int* __restrict__ ei,
                          const float* __restrict__ pos,
                          int* __restrict__ cursor,
                          int2* __restrict__ epack) {
    int e = blockIdx.x * blockDim.x + threadIdx.x;
    if (e >= EE) return;
    int s = ei[e];
    int t = ei[EE + e];
    float dx = pos[t * 3 + 0] - pos[s * 3 + 0];
    float dy = pos[t * 3 + 1] - pos[s * 3 + 1];
    float dz = pos[t * 3 + 2] - pos[s * 3 + 2];
    float dd = sqrtf(dx * dx + dy * dy + dz * dz);
    int p = atomicAdd(&cursor[t], 1);
    epack[p] = make_int2(s, __float_as_int(dd));
}

// ---------------- encoder: h = x @ enc_w + enc_b (K=15) --------------------------
__global__ void encoder_k(const float* __restrict__ x,
                          const float* __restrict__ w,
                          const float* __restrict__ b,
                          float* __restrict__ h) {
    __shared__ float ws[15 * HD];
    __shared__ float xs[16 * 15];
    __shared__ float bs[HD];
    int c = threadIdx.x;
    for (int i = c; i < 15 * HD; i += HD) ws[i] = w[i];
    bs[c] = b[c];
    int n0 = blockIdx.x * 16;
    for (int i = c; i < 16 * 15; i += HD) {
        int nn = i / 15, kk = i % 15;
        int g = n0 + nn;
        xs[i] = (g < NN) ? x[g * 15 + kk] : 0.0f;
    }
    __syncthreads();
    for (int r = 0; r < 16; r++) {
        int g = n0 + r;
        if (g >= NN) break;
        float acc = bs[c];
#pragma unroll
        for (int k = 0; k < 15; k++) acc += xs[r * 15 + k] * ws[k * HD + c];
        h[g * HD + c] = acc;
    }
}

// W2U[l] = msg_w2[l] @ U1b[l];  cvec[l] = msg_b2[l] @ U1b[l]
__global__ void build_w2u(const float* __restrict__ msg_w2,
                          const float* __restrict__ msg_b2,
                          const float* __restrict__ upd_w1,
                          float* __restrict__ W2U,
                          float* __restrict__ cvec) {
    int l = blockIdx.y, k = blockIdx.x, c = threadIdx.x;
    const float* u1b = upd_w1 + l * 256 * HD + 128 * HD;
    if (k < HD) {
        const float* wrow = msg_w2 + (l * HD + k) * HD;
        float acc = 0.0f;
        for (int j = 0; j < HD; j++) acc += wrow[j] * u1b[j * HD + c];
        W2U[(l * HD + k) * HD + c] = acc;
    } else {
        const float* brow = msg_b2 + l * HD;
        float acc = 0.0f;
        for (int j = 0; j < HD; j++) acc += brow[j] * u1b[j * HD + c];
        cvec[l * HD + c] = acc;
    }
}

// ---------------- CSR gather aggregation (packed edges, unroll 4) ---------------
__global__ void __launch_bounds__(256) aggregate_k(
    const int* __restrict__ rowptr,
    const int2* __restrict__ epack,
    const float* __restrict__ P1,
    const float* __restrict__ P2,
    const float* __restrict__ w1c,
    float* __restrict__ Yagg) {
    int node = blockIdx.x * 8 + (threadIdx.x >> 5);
    int lane = threadIdx.x & 31;
    int c4 = lane * 4;
    const float4 cw = *(const float4*)&w1c[c4];
    const float4 p1 = *(const float4*)&P1[node * HD + c4];
    float a0 = 0.f, a1 = 0.f, a2 = 0.f, a3 = 0.f;
    float b0 = 0.f, b1 = 0.f, b2 = 0.f, b3 = 0.f;
    float c0 = 0.f, c1 = 0.f, c2 = 0.f, c3 = 0.f;
    float d0 = 0.f, d1 = 0.f, d2 = 0.f, d3 = 0.f;
    int beg = rowptr[node], end = rowptr[node + 1];
    int e = beg;
    for (; e + 3 < end; e += 4) {
        int2 q0 = epack[e], q1 = epack[e + 1], q2 = epack[e + 2], q3 = epack[e + 3];
        const float4 v0 = *(const float4*)&P2[q0.x * HD + c4];
        const float4 v1 = *(const float4*)&P2[q1.x * HD + c4];
        const float4 v2 = *(const float4*)&P2[q2.x * HD + c4];
        const float4 v3 = *(const float4*)&P2[q3.x * HD + c4];
        float dd0 = __int_as_float(q0.y), dd1 = __int_as_float(q1.y);
        float dd2 = __int_as_float(q2.y), dd3 = __int_as_float(q3.y);
        a0 += fmaxf(p1.x + v0.x + dd0 * cw.x, 0.0f);
        a1 += fmaxf(p1.y + v0.y + dd0 * cw.y, 0.0f);
        a2 += fmaxf(p1.z + v0.z + dd0 * cw.z, 0.0f);
        a3 += fmaxf(p1.w + v0.w + dd0 * cw.w, 0.0f);
        b0 += fmaxf(p1.x + v1.x + dd1 * cw.x, 0.0f);
        b1 += fmaxf(p1.y + v1.y + dd1 * cw.y, 0.0f);
        b2 += fmaxf(p1.z + v1.z + dd1 * cw.z, 0.0f);
        b3 += fmaxf(p1.w + v1.w + dd1 * cw.w, 0.0f);
        c0 += fmaxf(p1.x + v2.x + dd2 * cw.x, 0.0f);
        c1 += fmaxf(p1.y + v2.y + dd2 * cw.y, 0.0f);
        c2 += fmaxf(p1.z + v2.z + dd2 * cw.z, 0.0f);
        c3 += fmaxf(p1.w + v2.w + dd2 * cw.w, 0.0f);
        d0 += fmaxf(p1.x + v3.x + dd3 * cw.x, 0.0f);
        d1 += fmaxf(p1.y + v3.y + dd3 * cw.y, 0.0f);
        d2 += fmaxf(p1.z + v3.z + dd3 * cw.z, 0.0f);
        d3 += fmaxf(p1.w + v3.w + dd3 * cw.w, 0.0f);
    }
    for (; e < end; e++) {
        int2 q0 = epack[e];
        const float4 v0 = *(const float4*)&P2[q0.x * HD + c4];
        float dd0 = __int_as_float(q0.y);
        a0 += fmaxf(p1.x + v0.x + dd0 * cw.x, 0.0f);
        a1 += fmaxf(p1.y + v0.y + dd0 * cw.y, 0.0f);
        a2 += fmaxf(p1.z + v0.z + dd0 * cw.z, 0.0f);
        a3 += fmaxf(p1.w + v0.w + dd0 * cw.w, 0.0f);
    }
    *(float4*)&Yagg[node * HD + c4] = make_float4(
        (a0 + b0) + (c0 + d0), (a1 + b1) + (c1 + d1),
        (a2 + b2) + (c2 + d2), (a3 + b3) + (c3 + d3));
}

// ---------------- readout --------------------------------------------------------
__global__ void pool_k(const float* __restrict__ h,
                       const int* __restrict__ batch,
                       float* __restrict__ pooled, float* __restrict__ cnt) {
    int nidx = blockIdx.x * 8 + (threadIdx.x >> 5);
    int lane = threadIdx.x & 31;
    if (nidx >= NN) return;
    int g = batch[nidx];
    float4 v = *(const float4*)&h[nidx * HD + lane * 4];
    float* p = &pooled[g * HD + lane * 4];
    atomicAdd(p + 0, v.x);
    atomicAdd(p + 1, v.y);
    atomicAdd(p + 2, v.z);
    atomicAdd(p + 3, v.w);
    if (lane == 0) atomicAdd(&cnt[g], 1.0f);
}

__global__ void readout_k(const float* __restrict__ pooled,
                          const float* __restrict__ cnt,
                          const float* __restrict__ w1, const float* __restrict__ b1,
                          const float* __restrict__ w2, const float* __restrict__ b2,
                          const float* __restrict__ w3, const float* __restrict__ b3,
                          float* __restrict__ out) {
    __shared__ float p[HD];
    __shared__ float o1s[HD];
    __shared__ float o2s[64];
    int g = blockIdx.x, c = threadIdx.x;
    float cc = fmaxf(cnt[g], 1.0f);
    p[c] = pooled[g * HD + c] / cc;
    __syncthreads();
    float acc = b1[c];
    for (int k = 0; k < HD; k++) acc += p[k] * w1[k * HD + c];
    o1s[c] = fmaxf(acc, 0.0f);
    __syncthreads();
    if (c < 64) {
        float a = b2[c];
        for (int k = 0; k < HD; k++) a += o1s[k] * w2[k * 64 + c];
        o2s[c] = fmaxf(a, 0.0f);
    }
    __syncthreads();
    if (c == 0) {
        float a = b3[0];
        for (int k = 0; k < 64; k++) a += o2s[k] * w3[k];
        out[g] = a;
    }
}

// ---------------- launch ----------------------------------------------------------
extern "C" void kernel_launch(void* const* d_in, const int* in_sizes, int n_in,
                              void* d_out, int out_size) {
    const float* x       = (const float*)d_in[0];
    const int*   ei      = (const int*)d_in[1];
    const float* pos     = (const float*)d_in[3];
    const int*   batch   = (const int*)d_in[4];
    const float* enc_w   = (const float*)d_in[5];
    const float* enc_b   = (const float*)d_in[6];
    const float* msg_w1  = (const float*)d_in[9];
    const float* msg_b1  = (const float*)d_in[10];
    const float* msg_w2  = (const float*)d_in[11];
    const float* msg_b2  = (const float*)d_in[12];
    const float* upd_w1  = (const float*)d_in[13];
    const float* upd_b1  = (const float*)d_in[14];
    const float* upd_w2  = (const float*)d_in[15];
    const float* upd_b2  = (const float*)d_in[16];
    const float* ln_g    = (const float*)d_in[17];
    const float* ln_b    = (const float*)d_in[18];
    const float* mlp_w1  = (const float*)d_in[19];
    const float* mlp_b1  = (const float*)d_in[20];
    const float* mlp_w2  = (const float*)d_in[21];
    const float* mlp_b2  = (const float*)d_in[22];
    const float* mlp_w3  = (const float*)d_in[23];
    const float* mlp_b3  = (const float*)d_in[24];
    float*       out     = (float*)d_out;

    float *h, *P1, *P2, *Yagg, *T, *degf, *W2U, *cvec, *pooled, *cnt;
    int *rowptr, *cursor, *bsum;
    int2 *epack;
    unsigned *wi;
    cudaGetSymbolAddress((void**)&h, d_h);
    cudaGetSymbolAddress((void**)&P1, d_P1);
    cudaGetSymbolAddress((void**)&P2, d_P2);
    cudaGetSymbolAddress((void**)&Yagg, d_Yagg);
    cudaGetSymbolAddress((void**)&T, d_T);
    cudaGetSymbolAddress((void**)&degf, d_degf);
    cudaGetSymbolAddress((void**)&W2U, d_W2U);
    cudaGetSymbolAddress((void**)&cvec, d_cvec);
    cudaGetSymbolAddress((void**)&pooled, d_pooled);
    cudaGetSymbolAddress((void**)&cnt, d_cnt);
    cudaGetSymbolAddress((void**)&rowptr, d_rowptr);
    cudaGetSymbolAddress((void**)&cursor, d_cursor);
    cudaGetSymbolAddress((void**)&bsum, d_bsum);
    cudaGetSymbolAddress((void**)&epack, d_epack);
    cudaGetSymbolAddress((void**)&wi, d_wi);

    cudaFuncSetAttribute(p12_tc,  cudaFuncAttributeMaxDynamicSharedMemorySize, BTILE);
    cudaFuncSetAttribute(upd2_tc, cudaFuncAttributeMaxDynamicSharedMemorySize, BTILE);
    cudaFuncSetAttribute(upd3_tc, cudaFuncAttributeMaxDynamicSharedMemorySize, BTILE);

    // ---- prep; launch #4 = layer-0 p12 so ncu captures it ----
    encoder_k<<<(NN + 15) / 16, 128>>>(x, enc_w, enc_b, h);               // 1
    split_msg<<<dim3(128, 8), 64>>>(msg_w1, wi);                          // 2
    zero_int<<<(NN + 255) / 256, 256>>>(cursor, NN);                      // 3
    p12_tc<<<2 * G128, 256, BTILE>>>(h, wi, msg_b1, P1, P2);              // 4 (profiled)
    count_k<<<(EE + 255) / 256, 256>>>(ei, cursor);                       // 5
    scan_part<<<NB, 256>>>(cursor, rowptr, bsum);                         // 6
    scan_bsum<<<1, 256>>>(bsum);                                          // 7
    add_off<<<NB, 256>>>(rowptr, bsum, cursor);                           // 8
    degf_k<<<(NN + 255) / 256, 256>>>(rowptr, degf);                      // 9
    scatter_k<<<(EE + 255) / 256, 256>>>(ei, pos, cursor, epack);         // 10
    build_w2u<<<dim3(129, 4), 128>>>(msg_w2, msg_b2, upd_w1, W2U, cvec);  // 11
    split_upd<<<dim3(128, 12), 64>>>(upd_w1, W2U, upd_w2, wi);            // 12
    zero_k<<<(NG * HD + 255) / 256, 256>>>(pooled, NG * HD);              // 13
    zero_k<<<1, 64>>>(cnt, NG);                                           // 14

    for (int l = 0; l < NLAY; l++) {
        const float* w1l = msg_w1 + l * 257 * HD;
        if (l > 0) {
            p12_tc<<<2 * G128, 256, BTILE>>>(h, wi + (2 * l) * 16384,
                                             msg_b1 + l * HD, P1, P2);
        }
        aggregate_k<<<NN / 8, 256>>>(rowptr, epack, P1, P2,
                                     w1l + 256 * HD, Yagg);
        upd2_tc<<<G128, 256, BTILE>>>(h, Yagg,
                                      wi + (8 + l) * 16384, wi + (12 + l) * 16384,
                                      upd_b1 + l * HD, degf, cvec + l * HD, T);
        upd3_tc<<<G128, 256, BTILE>>>(T, wi + (16 + l) * 16384,
                                      upd_b2 + l * HD, ln_g + l * HD, ln_b + l * HD,
                                      (l > 0) ? 1 : 0, h);
    }

    pool_k<<<(NN + 7) / 8, 256>>>(h, batch, pooled, cnt);
    readout_k<<<NG, 128>>>(pooled, cnt, mlp_w1, mlp_b1, mlp_w2, mlp_b2,
                           mlp_w3, mlp_b3, out);
}

// round 14
// speedup vs baseline: 2.1651x; 1.0198x over previous
#include <cuda_runtime.h>
#include <cuda_bf16.h>

#define NN 50000
#define EE 500000
#define HD 128
#define NLAY 4
#define NG 64
#define NB 196
#define G128 391

// interleaved split-weight matrices: 20 x [128 n][128 words]
// word[kw*2] = bf16x2 hi (k=2kw,2kw+1); word[kw*2+1] = bf16x2 lo
// idx 0..7 = msg W1a/W1b ; 8..11 = U1a[l] ; 12..15 = W2U[l] ; 16..19 = U2[l]
__device__ __align__(16) unsigned d_wi[20 * 16384];

__device__ __align__(16) float d_h[NN * HD];
__device__ __align__(16) float d_P1[NN * HD];
__device__ __align__(16) float d_P2[NN * HD];
__device__ __align__(16) float d_Yagg[NN * HD];
__device__ __align__(16) float d_T[NN * HD];
__device__ __align__(16) float d_degf[NN];
__device__ __align__(16) float d_W2U[NLAY * HD * HD];
__device__ __align__(16) float d_cvec[NLAY * HD];
__device__ __align__(16) float d_pooled[NG * HD];
__device__ __align__(16) float d_cnt[NG];
__device__ __align__(16) int   d_rowptr[NN + 1];
__device__ __align__(16) int   d_cursor[NN];
__device__ __align__(16) int   d_bsum[256];
__device__ __align__(16) int2  d_epack[EE];

// ---------------- helpers -------------------------------------------------------
__device__ __forceinline__ unsigned smem_u32(const void* p) {
    unsigned r;
    asm("{ .reg .u64 t; cvta.to.shared.u64 t, %1; cvt.u32.u64 %0, t; }"
        : "=r"(r) : "l"(p));
    return r;
}
__device__ __forceinline__ void cp16(unsigned saddr, const void* g) {
    asm volatile("cp.async.cg.shared.global [%0], [%1], 16;" :: "r"(saddr), "l"(g));
}
__device__ __forceinline__ void cp_commit_wait() {
    asm volatile("cp.async.commit_group;");
    asm volatile("cp.async.wait_group 0;");
}

__device__ __forceinline__ void mma_bf16(float c[4], const unsigned a[4],
                                         unsigned b0, unsigned b1) {
    asm volatile(
        "mma.sync.aligned.m16n8k16.row.col.f32.bf16.bf16.f32 "
        "{%0,%1,%2,%3}, {%4,%5,%6,%7}, {%8,%9}, {%0,%1,%2,%3};"
        : "+f"(c[0]), "+f"(c[1]), "+f"(c[2]), "+f"(c[3])
        : "r"(a[0]), "r"(a[1]), "r"(a[2]), "r"(a[3]), "r"(b0), "r"(b1));
}

// fast split: packed cvt + reconstruct-hi + packed cvt of residual
__device__ __forceinline__ void split2(float2 f, unsigned& hi, unsigned& lo) {
    unsigned h;
    asm("cvt.rn.bf16x2.f32 %0, %1, %2;" : "=r"(h) : "f"(f.y), "f"(f.x));
    float h0 = __uint_as_float(h << 16);
    float h1 = __uint_as_float(h & 0xFFFF0000u);
    unsigned l;
    float ry = f.y - h1, rx = f.x - h0;
    asm("cvt.rn.bf16x2.f32 %0, %1, %2;" : "=r"(l) : "f"(ry), "f"(rx));
    hi = h; lo = l;
}

// ---------------- HMMA building blocks ------------------------------------------
#define BROW 136
#define BTILE 69632

__device__ __forceinline__ void stageB(unsigned sb, const unsigned* __restrict__ wi,
                                       int tid, int nthr) {
    for (int c = tid; c < 4096; c += nthr) {
        int n = c >> 5;
        int c4 = c & 31;
        cp16(sb + (unsigned)((n * BROW + c4 * 4) * 4), wi + n * 128 + c4 * 4);
    }
}

__device__ __forceinline__ void loadA_frag(const float* __restrict__ A,
                                           int cr0, int cr1, int k0, int tig,
                                           unsigned ahi[4], unsigned alo[4]) {
    float2 f00 = *(const float2*)(A + cr0 * HD + k0 + tig * 2);
    float2 f10 = *(const float2*)(A + cr1 * HD + k0 + tig * 2);
    float2 f01 = *(const float2*)(A + cr0 * HD + k0 + tig * 2 + 8);
    float2 f11 = *(const float2*)(A + cr1 * HD + k0 + tig * 2 + 8);
    split2(f00, ahi[0], alo[0]);
    split2(f10, ahi[1], alo[1]);
    split2(f01, ahi[2], alo[2]);
    split2(f11, ahi[3], alo[3]);
}

// 32x64 warp tile: 8 n-tiles, 2 row-sets sharing each B fragment
__device__ __forceinline__ void mma_step64(float acc0[8][4], float acc1[8][4],
                                           const char* __restrict__ smB,
                                           int k0, int nbase, int tig,
                                           const unsigned ahi0[4], const unsigned alo0[4],
                                           const unsigned ahi1[4], const unsigned alo1[4]) {
    int kwofs = ((k0 >> 1) + tig) * 2;
#pragma unroll
    for (int t = 0; t < 8; t++) {
        int n = nbase + t * 8;
        const char* base = smB + (n * BROW + kwofs) * 4;
        unsigned long long q0 = *(const unsigned long long*)(base);
        unsigned long long q1 = *(const unsigned long long*)(base + 32);
        unsigned bh0 = (unsigned)q0, bl0 = (unsigned)(q0 >> 32);
        unsigned bh1 = (unsigned)q1, bl1 = (unsigned)(q1 >> 32);
        mma_bf16(acc0[t], ahi0, bh0, bh1);
        mma_bf16(acc0[t], ahi0, bl0, bl1);
        mma_bf16(acc0[t], alo0, bh0, bh1);
        mma_bf16(acc1[t], ahi1, bh0, bh1);
        mma_bf16(acc1[t], ahi1, bl0, bl1);
        mma_bf16(acc1[t], alo1, bh0, bh1);
    }
}

// ---------------- p12: P1/P2 message GEMM ---------------------------------------
// 256 thr, 8 warps = 4 rowgroups x 2 colgroups; warp = 32 rows x 64 cols.
// Blocks [0,391) -> P1, [391,782) -> P2.
__global__ void __launch_bounds__(256, 2) p12_tc(
    const float* __restrict__ A,
    const unsigned* __restrict__ wiPair,
    const float* __restrict__ bias,
    float* __restrict__ O1, float* __restrict__ O2) {
    extern __shared__ char smc[];
    unsigned sb = smem_u32(smc);
    int tid = threadIdx.x;
    int wid = tid >> 5, lane = tid & 31;
    int g = lane >> 2, tig = lane & 3;
    int rg = wid >> 1, cg = wid & 1;

    int pr = (blockIdx.x >= G128) ? 1 : 0;
    int blk = blockIdx.x - pr * G128;

    stageB(sb, wiPair + pr * 16384, tid, 256);
    cp_commit_wait();
    __syncthreads();

    int rowbase = blk * 128 + rg * 32;
    int rA0 = rowbase + g, rA1 = rowbase + g + 8;
    int rB0 = rowbase + g + 16, rB1 = rowbase + g + 24;
    int cA0 = (rA0 < NN) ? rA0 : (NN - 1);
    int cA1 = (rA1 < NN) ? rA1 : (NN - 1);
    int cB0 = (rB0 < NN) ? rB0 : (NN - 1);
    int cB1 = (rB1 < NN) ? rB1 : (NN - 1);
    int nbase = cg * 64 + g;

    float acc0[8][4], acc1[8][4];
#pragma unroll
    for (int i = 0; i < 8; i++)
#pragma unroll
        for (int j = 0; j < 4; j++) { acc0[i][j] = 0.0f; acc1[i][j] = 0.0f; }

#pragma unroll
    for (int ks = 0; ks < 8; ks++) {
        int k0 = ks * 16;
        unsigned ahi0[4], alo0[4], ahi1[4], alo1[4];
        loadA_frag(A, cA0, cA1, k0, tig, ahi0, alo0);
        loadA_frag(A, cB0, cB1, k0, tig, ahi1, alo1);
        mma_step64(acc0, acc1, smc, k0, nbase, tig, ahi0, alo0, ahi1, alo1);
    }

    float* Op = pr ? O2 : O1;
#pragma unroll
    for (int t = 0; t < 8; t++) {
        int col = cg * 64 + t * 8 + tig * 2;
        float2 bv = make_float2(0.f, 0.f);
        if (pr == 0) bv = *(const float2*)&bias[col];
        float2 v;
        v = make_float2(acc0[t][0] + bv.x, acc0[t][1] + bv.y);
        if (rA0 < NN) *(float2*)(Op + rA0 * HD + col) = v;
        v = make_float2(acc0[t][2] + bv.x, acc0[t][3] + bv.y);
        if (rA1 < NN) *(float2*)(Op + rA1 * HD + col) = v;
        v = make_float2(acc1[t][0] + bv.x, acc1[t][1] + bv.y);
        if (rB0 < NN) *(float2*)(Op + rB0 * HD + col) = v;
        v = make_float2(acc1[t][2] + bv.x, acc1[t][3] + bv.y);
        if (rB1 < NN) *(float2*)(Op + rB1 * HD + col) = v;
    }
}

// ---------------- upd2: T = relu(h@U1a + Yagg@W2U + deg*cvec + bias) ------------
// 32x64 warp tile; sequential staging of the two matrices.
__global__ void __launch_bounds__(256, 2) upd2_tc(
    const float* __restrict__ A0, const float* __restrict__ A1,
    const unsigned* __restrict__ wi0, const unsigned* __restrict__ wi1,
    const float* __restrict__ bias, const float* __restrict__ degf,
    const float* __restrict__ cvec, float* __restrict__ Out) {
    extern __shared__ char smc[];
    unsigned sb = smem_u32(smc);
    int tid = threadIdx.x;
    int wid = tid >> 5, lane = tid & 31;
    int g = lane >> 2, tig = lane & 3;
    int rg = wid >> 1, cg = wid & 1;

    stageB(sb, wi0, tid, 256);
    cp_commit_wait();
    __syncthreads();

    int rowbase = blockIdx.x * 128 + rg * 32;
    int rA0 = rowbase + g, rA1 = rowbase + g + 8;
    int rB0 = rowbase + g + 16, rB1 = rowbase + g + 24;
    int cA0 = (rA0 < NN) ? rA0 : (NN - 1);
    int cA1 = (rA1 < NN) ? rA1 : (NN - 1);
    int cB0 = (rB0 < NN) ? rB0 : (NN - 1);
    int cB1 = (rB1 < NN) ? rB1 : (NN - 1);
    int nbase = cg * 64 + g;

    float acc0[8][4], acc1[8][4];
#pragma unroll
    for (int i = 0; i < 8; i++)
#pragma unroll
        for (int j = 0; j < 4; j++) { acc0[i][j] = 0.0f; acc1[i][j] = 0.0f; }

#pragma unroll
    for (int ks = 0; ks < 8; ks++) {
        int k0 = ks * 16;
        unsigned ahi0[4], alo0[4], ahi1[4], alo1[4];
        loadA_frag(A0, cA0, cA1, k0, tig, ahi0, alo0);
        loadA_frag(A0, cB0, cB1, k0, tig, ahi1, alo1);
        mma_step64(acc0, acc1, smc, k0, nbase, tig, ahi0, alo0, ahi1, alo1);
    }
    __syncthreads();
    stageB(sb, wi1, tid, 256);
    cp_commit_wait();
    __syncthreads();
#pragma unroll
    for (int ks = 0; ks < 8; ks++) {
        int k0 = ks * 16;
        unsigned ahi0[4], alo0[4], ahi1[4], alo1[4];
        loadA_frag(A1, cA0, cA1, k0, tig, ahi0, alo0);
        loadA_frag(A1, cB0, cB1, k0, tig, ahi1, alo1);
        mma_step64(acc0, acc1, smc, k0, nbase, tig, ahi0, alo0, ahi1, alo1);
    }

    float dgA0 = degf[cA0], dgA1 = degf[cA1];
    float dgB0 = degf[cB0], dgB1 = degf[cB1];
#pragma unroll
    for (int t = 0; t < 8; t++) {
        int col = cg * 64 + t * 8 + tig * 2;
        float2 bv = *(const float2*)&bias[col];
        float2 cv = *(const float2*)&cvec[col];
        float2 v;
        v.x = fmaxf(acc0[t][0] + dgA0 * cv.x + bv.x, 0.0f);
        v.y = fmaxf(acc0[t][1] + dgA0 * cv.y + bv.y, 0.0f);
        if (rA0 < NN) *(float2*)(Out + rA0 * HD + col) = v;
        v.x = fmaxf(acc0[t][2] + dgA1 * cv.x + bv.x, 0.0f);
        v.y = fmaxf(acc0[t][3] + dgA1 * cv.y + bv.y, 0.0f);
        if (rA1 < NN) *(float2*)(Out + rA1 * HD + col) = v;
        v.x = fmaxf(acc1[t][0] + dgB0 * cv.x + bv.x, 0.0f);
        v.y = fmaxf(acc1[t][1] + dgB0 * cv.y + bv.y, 0.0f);
        if (rB0 < NN) *(float2*)(Out + rB0 * HD + col) = v;
        v.x = fmaxf(acc1[t][2] + dgB1 * cv.x + bv.x, 0.0f);
        v.y = fmaxf(acc1[t][3] + dgB1 * cv.y + bv.y, 0.0f);
        if (rB1 < NN) *(float2*)(Out + rB1 * HD + col) = v;
    }
}

// ---------------- upd3: h = (res? h:0) + relu(LN(T@U2 + bias)) ------------------
// keeps 16x128 warp tile (LN needs the full row inside one warp)
__global__ void __launch_bounds__(256, 2) upd3_tc(
    const float* __restrict__ A,
    const unsigned* __restrict__ wiU,
    const float* __restrict__ bias,
    const float* __restrict__ lng, const float* __restrict__ lnb,
    int addres, float* __restrict__ Out) {
    extern __shared__ char smc[];
    unsigned sb = smem_u32(smc);
    int tid = threadIdx.x;
    int wid = tid >> 5, lane = tid & 31;
    int g = lane >> 2, tig = lane & 3;

    stageB(sb, wiU, tid, 256);
    cp_commit_wait();
    __syncthreads();

    int rowbase = blockIdx.x * 128 + wid * 16;
    int r0 = rowbase + g, r1 = rowbase + g + 8;
    int cr0 = (r0 < NN) ? r0 : (NN - 1);
    int cr1 = (r1 < NN) ? r1 : (NN - 1);

    float acc[16][4];
#pragma unroll
    for (int i = 0; i < 16; i++)
#pragma unroll
        for (int j = 0; j < 4; j++) acc[i][j] = 0.0f;

#pragma unroll
    for (int ks = 0; ks < 8; ks++) {
        int k0 = ks * 16;
        unsigned ahi[4], alo[4];
        loadA_frag(A, cr0, cr1, k0, tig, ahi, alo);
        int kwofs = ((k0 >> 1) + tig) * 2;
#pragma unroll
        for (int t = 0; t < 16; t++) {
            int n = t * 8 + g;
            const char* base = smc + (n * BROW + kwofs) * 4;
            unsigned long long q0 = *(const unsigned long long*)(base);
            unsigned long long q1 = *(const unsigned long long*)(base + 32);
            unsigned bh0 = (unsigned)q0, bl0 = (unsigned)(q0 >> 32);
            unsigned bh1 = (unsigned)q1, bl1 = (unsigned)(q1 >> 32);
            mma_bf16(acc[t], ahi, bh0, bh1);
            mma_bf16(acc[t], ahi, bl0, bl1);
            mma_bf16(acc[t], alo, bh0, bh1);
        }
    }

    float s0 = 0.f, sq0 = 0.f, s1 = 0.f, sq1 = 0.f;
#pragma unroll
    for (int t = 0; t < 16; t++) {
        int col = t * 8 + tig * 2;
        float2 bv = *(const float2*)&bias[col];
        acc[t][0] += bv.x; acc[t][1] += bv.y;
        acc[t][2] += bv.x; acc[t][3] += bv.y;
        s0 += acc[t][0] + acc[t][1];
        sq0 += acc[t][0] * acc[t][0] + acc[t][1] * acc[t][1];
        s1 += acc[t][2] + acc[t][3];
        sq1 += acc[t][2] * acc[t][2] + acc[t][3] * acc[t][3];
    }
#pragma unroll
    for (int off = 1; off <= 2; off <<= 1) {
        s0 += __shfl_xor_sync(0xffffffffu, s0, off);
        sq0 += __shfl_xor_sync(0xffffffffu, sq0, off);
        s1 += __shfl_xor_sync(0xffffffffu, s1, off);
        sq1 += __shfl_xor_sync(0xffffffffu, sq1, off);
    }
    float mu0 = s0 * (1.0f / HD);
    float mu1 = s1 * (1.0f / HD);
    float rstd0 = rsqrtf(sq0 * (1.0f / HD) - mu0 * mu0 + 1e-5f);
    float rstd1 = rsqrtf(sq1 * (1.0f / HD) - mu1 * mu1 + 1e-5f);

#pragma unroll
    for (int t = 0; t < 16; t++) {
        int col = t * 8 + tig * 2;
        float2 gv = *(const float2*)&lng[col];
        float2 lv = *(const float2*)&lnb[col];
        float2 v0, v1;
        v0.x = fmaxf((acc[t][0] - mu0) * rstd0 * gv.x + lv.x, 0.0f);
        v0.y = fmaxf((acc[t][1] - mu0) * rstd0 * gv.y + lv.y, 0.0f);
        v1.x = fmaxf((acc[t][2] - mu1) * rstd1 * gv.x + lv.x, 0.0f);
        v1.y = fmaxf((acc[t][3] - mu1) * rstd1 * gv.y + lv.y, 0.0f);
        if (r0 < NN) {
            if (addres) {
                float2 hv = *(const float2*)(Out + r0 * HD + col);
                v0.x += hv.x; v0.y += hv.y;
            }
            *(float2*)(Out + r0 * HD + col) = v0;
        }
        if (r1 < NN) {
            if (addres) {
                float2 hv = *(const float2*)(Out + r1 * HD + col);
                v1.x += hv.x; v1.y += hv.y;
            }
            *(float2*)(Out + r1 * HD + col) = v1;
        }
    }
}

// ---------------- weight transpose + split + interleave -------------------------
__device__ __forceinline__ void split_store(unsigned* __restrict__ dst,
                                            int m, int n, int kw,
                                            float v0, float v1) {
    __nv_bfloat16 h0 = __float2bfloat16(v0), h1 = __float2bfloat16(v1);
    __nv_bfloat16 l0 = __float2bfloat16(v0 - __bfloat162float(h0));
    __nv_bfloat16 l1 = __float2bfloat16(v1 - __bfloat162float(h1));
    dst[m * 16384 + n * 128 + kw * 2] =
        ((unsigned)__bfloat16_as_ushort(h1) << 16) | __bfloat16_as_ushort(h0);
    dst[m * 16384 + n * 128 + kw * 2 + 1] =
        ((unsigned)__bfloat16_as_ushort(l1) << 16) | __bfloat16_as_ushort(l0);
}

__global__ void split_msg(const float* __restrict__ msg_w1, unsigned* __restrict__ wi) {
    int n = blockIdx.x, m = blockIdx.y, kw = threadIdx.x;
    int l = m >> 1, part = m & 1;
    const float* W = msg_w1 + l * 257 * HD + part * 128 * HD;
    split_store(wi, m, n, kw, W[(2 * kw) * HD + n], W[(2 * kw + 1) * HD + n]);
}

__global__ void split_upd(const float* __restrict__ upd_w1,
                          const float* __restrict__ W2U,
                          const float* __restrict__ upd_w2,
                          unsigned* __restrict__ wi) {
    int n = blockIdx.x, m2 = blockIdx.y, kw = threadIdx.x;
    const float* W;
    if (m2 < 4)       W = upd_w1 + m2 * 256 * HD;
    else if (m2 < 8)  W = W2U + (m2 - 4) * HD * HD;
    else              W = upd_w2 + (m2 - 8) * HD * HD;
    split_store(wi, 8 + m2, n, kw, W[(2 * kw) * HD + n], W[(2 * kw + 1) * HD + n]);
}

// ---------------- tiny utility kernels ------------------------------------------
__global__ void zero_k(float* __restrict__ p, int n) {
    int i = blockIdx.x * blockDim.x + threadIdx.x;
    if (i < n) p[i] = 0.0f;
}
__global__ void zero_int(int* __restrict__ p, int n) {
    int i = blockIdx.x * blockDim.x + threadIdx.x;
    if (i < n) p[i] = 0;
}

// ---------------- CSR build ------------------------------------------------------
__global__ void count_k(const int* __restrict__ ei, int* __restrict__ deg) {
    int e = blockIdx.x * blockDim.x + threadIdx.x;
    if (e < EE) atomicAdd(&deg[ei[EE + e]], 1);
}

__global__ void scan_part(const int* __restrict__ deg, int* __restrict__ rowptr,
                          int* __restrict__ bsum) {
    __shared__ int s[256];
    int tid = threadIdx.x;
    int i = blockIdx.x * 256 + tid;
    int v = (i < NN) ? deg[i] : 0;
    s[tid] = v;
    __syncthreads();
#pragma unroll
    for (int off = 1; off < 256; off <<= 1) {
        int t = (tid >= off) ? s[tid - off] : 0;
        __syncthreads();
        s[tid] += t;
        __syncthreads();
    }
    if (i < NN) rowptr[i] = s[tid] - v;
    if (tid == 255) bsum[blockIdx.x] = s[255];
}

__global__ void scan_bsum(int* __restrict__ bsum) {
    __shared__ int s[256];
    int tid = threadIdx.x;
    int v = (tid < NB) ? bsum[tid] : 0;
    s[tid] = v;
    __syncthreads();
#pragma unroll
    for (int off = 1; off < 256; off <<= 1) {
        int t = (tid >= off) ? s[tid - off] : 0;
        __syncthreads();
        s[tid] += t;
        __syncthreads();
    }
    if (tid < NB) bsum[tid] = s[tid] - v;
}

__global__ void add_off(int* __restrict__ rowptr, const int* __restrict__ bsum,
                        int* __restrict__ cursor) {
    int i = blockIdx.x * 256 + threadIdx.x;
    if (i < NN) {
        int r = rowptr[i] + bsum[blockIdx.x];
        rowptr[i] = r;
        cursor[i] = r;
    }
    if (i == 0) rowptr[NN] = EE;
}

__global__ void degf_k(const int* __restrict__ rowptr, float* __restrict__ degf) {
    int i = blockIdx.x * blockDim.x + threadIdx.x;
    if (i < NN) degf[i] = (float)(rowptr[i + 1] - rowptr[i]);
}

__global__ void scatter_k(const int* __restrict__ ei,
                          const float* __restrict__ pos,
                          int* __restrict__ cursor,
                          int2* __restrict__ epack) {
    int e = blockIdx.x * blockDim.x + threadIdx.x;
    if (e >= EE) return;
    int s = ei[e];
    int t = ei[EE + e];
    float dx = pos[t * 3 + 0] - pos[s * 3 + 0];
    float dy = pos[t * 3 + 1] - pos[s * 3 + 1];
    float dz = pos[t * 3 + 2] - pos[s * 3 + 2];
    float dd = sqrtf(dx * dx + dy * dy + dz * dz);
    int p = atomicAdd(&cursor[t], 1);
    epack[p] = make_int2(s, __float_as_int(dd));
}

// ---------------- encoder --------------------------------------------------------
__global__ void encoder_k(const float* __restrict__ x,
                          const float* __restrict__ w,
                          const float* __restrict__ b,
                          float* __restrict__ h) {
    __shared__ float ws[15 * HD];
    __shared__ float xs[16 * 15];
    __shared__ float bs[HD];
    int c = threadIdx.x;
    for (int i = c; i < 15 * HD; i += HD) ws[i] = w[i];
    bs[c] = b[c];
    int n0 = blockIdx.x * 16;
    for (int i = c; i < 16 * 15; i += HD) {
        int nn = i / 15, kk = i % 15;
        int g = n0 + nn;
        xs[i] = (g < NN) ? x[g * 15 + kk] : 0.0f;
    }
    __syncthreads();
    for (int r = 0; r < 16; r++) {
        int g = n0 + r;
        if (g >= NN) break;
        float acc = bs[c];
#pragma unroll
        for (int k = 0; k < 15; k++) acc += xs[r * 15 + k] * ws[k * HD + c];
        h[g * HD + c] = acc;
    }
}

__global__ void build_w2u(const float* __restrict__ msg_w2,
                          const float* __restrict__ msg_b2,
                          const float* __restrict__ upd_w1,
                          float* __restrict__ W2U,
                          float* __restrict__ cvec) {
    int l = blockIdx.y, k = blockIdx.x, c = threadIdx.x;
    const float* u1b = upd_w1 + l * 256 * HD + 128 * HD;
    if (k < HD) {
        const float* wrow = msg_w2 + (l * HD + k) * HD;
        float acc = 0.0f;
        for (int j = 0; j < HD; j++) acc += wrow[j] * u1b[j * HD + c];
        W2U[(l * HD + k) * HD + c] = acc;
    } else {
        const float* brow = msg_b2 + l * HD;
        float acc = 0.0f;
        for (int j = 0; j < HD; j++) acc += brow[j] * u1b[j * HD + c];
        cvec[l * HD + c] = acc;
    }
}

// ---------------- CSR gather aggregation ----------------------------------------
__global__ void __launch_bounds__(256) aggregate_k(
    const int* __restrict__ rowptr,
    const int2* __restrict__ epack,
    const float* __restrict__ P1,
    const float* __restrict__ P2,
    const float* __restrict__ w1c,
    float* __restrict__ Yagg) {
    int node = blockIdx.x * 8 + (threadIdx.x >> 5);
    int lane = threadIdx.x & 31;
    int c4 = lane * 4;
    const float4 cw = *(const float4*)&w1c[c4];
    const float4 p1 = *(const float4*)&P1[node * HD + c4];
    float a0 = 0.f, a1 = 0.f, a2 = 0.f, a3 = 0.f;
    float b0 = 0.f, b1 = 0.f, b2 = 0.f, b3 = 0.f;
    float c0 = 0.f, c1 = 0.f, c2 = 0.f, c3 = 0.f;
    float d0 = 0.f, d1 = 0.f, d2 = 0.f, d3 = 0.f;
    int beg = rowptr[node], end = rowptr[node + 1];
    int e = beg;
    for (; e + 3 < end; e += 4) {
        int2 q0 = epack[e], q1 = epack[e + 1], q2 = epack[e + 2], q3 = epack[e + 3];
        const float4 v0 = *(const float4*)&P2[q0.x * HD + c4];
        const float4 v1 = *(const float4*)&P2[q1.x * HD + c4];
        const float4 v2 = *(const float4*)&P2[q2.x * HD + c4];
        const float4 v3 = *(const float4*)&P2[q3.x * HD + c4];
        float dd0 = __int_as_float(q0.y), dd1 = __int_as_float(q1.y);
        float dd2 = __int_as_float(q2.y), dd3 = __int_as_float(q3.y);
        a0 += fmaxf(p1.x + v0.x + dd0 * cw.x, 0.0f);
        a1 += fmaxf(p1.y + v0.y + dd0 * cw.y, 0.0f);
        a2 += fmaxf(p1.z + v0.z + dd0 * cw.z, 0.0f);
        a3 += fmaxf(p1.w + v0.w + dd0 * cw.w, 0.0f);
        b0 += fmaxf(p1.x + v1.x + dd1 * cw.x, 0.0f);
        b1 += fmaxf(p1.y + v1.y + dd1 * cw.y, 0.0f);
        b2 += fmaxf(p1.z + v1.z + dd1 * cw.z, 0.0f);
        b3 += fmaxf(p1.w + v1.w + dd1 * cw.w, 0.0f);
        c0 += fmaxf(p1.x + v2.x + dd2 * cw.x, 0.0f);
        c1 += fmaxf(p1.y + v2.y + dd2 * cw.y, 0.0f);
        c2 += fmaxf(p1.z + v2.z + dd2 * cw.z, 0.0f);
        c3 += fmaxf(p1.w + v2.w + dd2 * cw.w, 0.0f);
        d0 += fmaxf(p1.x + v3.x + dd3 * cw.x, 0.0f);
        d1 += fmaxf(p1.y + v3.y + dd3 * cw.y, 0.0f);
        d2 += fmaxf(p1.z + v3.z + dd3 * cw.z, 0.0f);
        d3 += fmaxf(p1.w + v3.w + dd3 * cw.w, 0.0f);
    }
    for (; e < end; e++) {
        int2 q0 = epack[e];
        const float4 v0 = *(const float4*)&P2[q0.x * HD + c4];
        float dd0 = __int_as_float(q0.y);
        a0 += fmaxf(p1.x + v0.x + dd0 * cw.x, 0.0f);
        a1 += fmaxf(p1.y + v0.y + dd0 * cw.y, 0.0f);
        a2 += fmaxf(p1.z + v0.z + dd0 * cw.z, 0.0f);
        a3 += fmaxf(p1.w + v0.w + dd0 * cw.w, 0.0f);
    }
    *(float4*)&Yagg[node * HD + c4] = make_float4(
        (a0 + b0) + (c0 + d0), (a1 + b1) + (c1 + d1),
        (a2 + b2) + (c2 + d2), (a3 + b3) + (c3 + d3));
}

// ---------------- readout --------------------------------------------------------
__global__ void pool_k(const float* __restrict__ h,
                       const int* __restrict__ batch,
                       float* __restrict__ pooled, float* __restrict__ cnt) {
    int nidx = blockIdx.x * 8 + (threadIdx.x >> 5);
    int lane = threadIdx.x & 31;
    if (nidx >= NN) return;
    int g = batch[nidx];
    float4 v = *(const float4*)&h[nidx * HD + lane * 4];
    float* p = &pooled[g * HD + lane * 4];
    atomicAdd(p + 0, v.x);
    atomicAdd(p + 1, v.y);
    atomicAdd(p + 2, v.z);
    atomicAdd(p + 3, v.w);
    if (lane == 0) atomicAdd(&cnt[g], 1.0f);
}

__global__ void readout_k(const float* __restrict__ pooled,
                          const float* __restrict__ cnt,
                          const float* __restrict__ w1, const float* __restrict__ b1,
                          const float* __restrict__ w2, const float* __restrict__ b2,
                          const float* __restrict__ w3, const float* __restrict__ b3,
                          float* __restrict__ out) {
    __shared__ float p[HD];
    __shared__ float o1s[HD];
    __shared__ float o2s[64];
    int g = blockIdx.x, c = threadIdx.x;
    float cc = fmaxf(cnt[g], 1.0f);
    p[c] = pooled[g * HD + c] / cc;
    __syncthreads();
    float acc = b1[c];
    for (int k = 0; k < HD; k++) acc += p[k] * w1[k * HD + c];
    o1s[c] = fmaxf(acc, 0.0f);
    __syncthreads();
    if (c < 64) {
        float a = b2[c];
        for (int k = 0; k < HD; k++) a += o1s[k] * w2[k * 64 + c];
        o2s[c] = fmaxf(a, 0.0f);
    }
    __syncthreads();
    if (c == 0) {
        float a = b3[0];
        for (int k = 0; k < 64; k++) a += o2s[k] * w3[k];
        out[g] = a;
    }
}

// ---------------- launch ----------------------------------------------------------
extern "C" void kernel_launch(void* const* d_in, const int* in_sizes, int n_in,
                              void* d_out, int out_size) {
    const float* x       = (const float*)d_in[0];
    const int*   ei      = (const int*)d_in[1];
    const float* pos     = (const float*)d_in[3];
    const int*   batch   = (const int*)d_in[4];
    const float* enc_w   = (const float*)d_in[5];
    const float* enc_b   = (const float*)d_in[6];
    const float* msg_w1  = (const float*)d_in[9];
    const float* msg_b1  = (const float*)d_in[10];
    const float* msg_w2  = (const float*)d_in[11];
    const float* msg_b2  = (const float*)d_in[12];
    const float* upd_w1  = (const float*)d_in[13];
    const float* upd_b1  = (const float*)d_in[14];
    const float* upd_w2  = (const float*)d_in[15];
    const float* upd_b2  = (const float*)d_in[16];
    const float* ln_g    = (const float*)d_in[17];
    const float* ln_b    = (const float*)d_in[18];
    const float* mlp_w1  = (const float*)d_in[19];
    const float* mlp_b1  = (const float*)d_in[20];
    const float* mlp_w2  = (const float*)d_in[21];
    const float* mlp_b2  = (const float*)d_in[22];
    const float* mlp_w3  = (const float*)d_in[23];
    const float* mlp_b3  = (const float*)d_in[24];
    float*       out     = (float*)d_out;

    float *h, *P1, *P2, *Yagg, *T, *degf, *W2U, *cvec, *pooled, *cnt;
    int *rowptr, *cursor, *bsum;
    int2 *epack;
    unsigned *wi;
    cudaGetSymbolAddress((void**)&h, d_h);
    cudaGetSymbolAddress((void**)&P1, d_P1);
    cudaGetSymbolAddress((void**)&P2, d_P2);
    cudaGetSymbolAddress((void**)&Yagg, d_Yagg);
    cudaGetSymbolAddress((void**)&T, d_T);
    cudaGetSymbolAddress((void**)&degf, d_degf);
    cudaGetSymbolAddress((void**)&W2U, d_W2U);
    cudaGetSymbolAddress((void**)&cvec, d_cvec);
    cudaGetSymbolAddress((void**)&pooled, d_pooled);
    cudaGetSymbolAddress((void**)&cnt, d_cnt);
    cudaGetSymbolAddress((void**)&rowptr, d_rowptr);
    cudaGetSymbolAddress((void**)&cursor, d_cursor);
    cudaGetSymbolAddress((void**)&bsum, d_bsum);
    cudaGetSymbolAddress((void**)&epack, d_epack);
    cudaGetSymbolAddress((void**)&wi, d_wi);

    cudaFuncSetAttribute(p12_tc,  cudaFuncAttributeMaxDynamicSharedMemorySize, BTILE);
    cudaFuncSetAttribute(upd2_tc, cudaFuncAttributeMaxDynamicSharedMemorySize, BTILE);
    cudaFuncSetAttribute(upd3_tc, cudaFuncAttributeMaxDynamicSharedMemorySize, BTILE);

    // ---- prep; launch #4 = layer-0 p12 so ncu captures it ----
    encoder_k<<<(NN + 15) / 16, 128>>>(x, enc_w, enc_b, h);               // 1
    split_msg<<<dim3(128, 8), 64>>>(msg_w1, wi);                          // 2
    zero_int<<<(NN + 255) / 256, 256>>>(cursor, NN);                      // 3
    p12_tc<<<2 * G128, 256, BTILE>>>(h, wi, msg_b1, P1, P2);              // 4 (profiled)
    count_k<<<(EE + 255) / 256, 256>>>(ei, cursor);                       // 5
    scan_part<<<NB, 256>>>(cursor, rowptr, bsum);                         // 6
    scan_bsum<<<1, 256>>>(bsum);                                          // 7
    add_off<<<NB, 256>>>(rowptr, bsum, cursor);                           // 8
    degf_k<<<(NN + 255) / 256, 256>>>(rowptr, degf);                      // 9
    scatter_k<<<(EE + 255) / 256, 256>>>(ei, pos, cursor, epack);         // 10
    build_w2u<<<dim3(129, 4), 128>>>(msg_w2, msg_b2, upd_w1, W2U, cvec);  // 11
    split_upd<<<dim3(128, 12), 64>>>(upd_w1, W2U, upd_w2, wi);            // 12
    zero_k<<<(NG * HD + 255) / 256, 256>>>(pooled, NG * HD);              // 13
    zero_k<<<1, 64>>>(cnt, NG);                                           // 14

    for (int l = 0; l < NLAY; l++) {
        const float* w1l = msg_w1 + l * 257 * HD;
        if (l > 0) {
            p12_tc<<<2 * G128, 256, BTILE>>>(h, wi + (2 * l) * 16384,
                                             msg_b1 + l * HD, P1, P2);
        }
        aggregate_k<<<NN / 8, 256>>>(rowptr, epack, P1, P2,
                                     w1l + 256 * HD, Yagg);
        upd2_tc<<<G128, 256, BTILE>>>(h, Yagg,
                                      wi + (8 + l) * 16384, wi + (12 + l) * 16384,
                                      upd_b1 + l * HD, degf, cvec + l * HD, T);
        upd3_tc<<<G128, 256, BTILE>>>(T, wi + (16 + l) * 16384,
                                      upd_b2 + l * HD, ln_g + l * HD, ln_b + l * HD,
                                      (l > 0) ? 1 : 0, h);
    }

    pool_k<<<(NN + 7) / 8, 256>>>(h, batch, pooled, cnt);
    readout_k<<<NG, 128>>>(pooled, cnt, mlp_w1, mlp_b1, mlp_w2, mlp_b2,
                           mlp_w3, mlp_b3, out);
}